// round 11
// baseline (speedup 1.0000x reference)
#include <cuda_runtime.h>
#include <cuda_bf16.h>
#include <cstdint>

#define Bb 8
#define Cc 256
#define Nn 4096
#define Dd 16
#define BN 64
#define NTILES (Nn / BN)

typedef unsigned long long ull;

// ---------------- scratch ----------------
__device__ __nv_bfloat16 g_Qb[(size_t)Bb * Nn * Dd];   // [B,N,16] bf16, (q+bq)*0.25*log2e
__device__ __nv_bfloat16 g_Kb[(size_t)Bb * Dd * Nn];   // [B,16,N] bf16, k+bk
__device__ __nv_bfloat16 g_VT[(size_t)Bb * Nn * Cc];   // [B,N,C] bf16
__device__ float g_OA[(size_t)Bb * Cc * Nn];           // [B,C,N]

// ---------------- helpers ----------------
static __device__ __forceinline__ uint32_t smem_u32(const void* p) {
    uint32_t a;
    asm("{ .reg .u64 t; cvta.to.shared.u64 t, %1; cvt.u32.u64 %0, t; }" : "=r"(a) : "l"(p));
    return a;
}
static __device__ __forceinline__ void ldsm_x4(uint32_t &r0, uint32_t &r1, uint32_t &r2, uint32_t &r3, uint32_t addr) {
    asm volatile("ldmatrix.sync.aligned.m8n8.x4.shared.b16 {%0,%1,%2,%3}, [%4];"
                 : "=r"(r0), "=r"(r1), "=r"(r2), "=r"(r3) : "r"(addr));
}
static __device__ __forceinline__ void ldsm_x4t(uint32_t &r0, uint32_t &r1, uint32_t &r2, uint32_t &r3, uint32_t addr) {
    asm volatile("ldmatrix.sync.aligned.m8n8.x4.trans.shared.b16 {%0,%1,%2,%3}, [%4];"
                 : "=r"(r0), "=r"(r1), "=r"(r2), "=r"(r3) : "r"(addr));
}
static __device__ __forceinline__ void mma16816(float* d, const uint32_t* a, uint32_t b0, uint32_t b1) {
    asm volatile("mma.sync.aligned.m16n8k16.row.col.f32.bf16.bf16.f32 "
                 "{%0,%1,%2,%3}, {%4,%5,%6,%7}, {%8,%9}, {%0,%1,%2,%3};"
                 : "+f"(d[0]), "+f"(d[1]), "+f"(d[2]), "+f"(d[3])
                 : "r"(a[0]), "r"(a[1]), "r"(a[2]), "r"(a[3]), "r"(b0), "r"(b1));
}
static __device__ __forceinline__ void mma_tf32(float* d, const uint32_t* a, uint32_t b0, uint32_t b1) {
    asm volatile("mma.sync.aligned.m16n8k8.row.col.f32.tf32.tf32.f32 "
                 "{%0,%1,%2,%3}, {%4,%5,%6,%7}, {%8,%9}, {%0,%1,%2,%3};"
                 : "+f"(d[0]), "+f"(d[1]), "+f"(d[2]), "+f"(d[3])
                 : "r"(a[0]), "r"(a[1]), "r"(a[2]), "r"(a[3]), "r"(b0), "r"(b1));
}
static __device__ __forceinline__ float ex2(float x) {
    float y; asm("ex2.approx.ftz.f32 %0, %1;" : "=f"(y) : "f"(x)); return y;
}
static __device__ __forceinline__ void sts32(uint32_t addr, uint32_t v) {
    asm volatile("st.shared.b32 [%0], %1;" :: "r"(addr), "r"(v));
}
static __device__ __forceinline__ void cp16(uint32_t dst, const void* src) {
    asm volatile("cp.async.cg.shared.global [%0], [%1], 16;" :: "r"(dst), "l"(src));
}
#define CP_COMMIT asm volatile("cp.async.commit_group;" ::: "memory")
#define CP_WAIT1  asm volatile("cp.async.wait_group 1;" ::: "memory")
#define CP_WAIT0  asm volatile("cp.async.wait_group 0;" ::: "memory")
#define BARG(id)  asm volatile("bar.sync %0, 256;" :: "r"(id) : "memory")

#define QSCALE 0.36067376022224085f   // 0.25 * log2(e)
#define CLIP2  72.134752f             // 50 * log2(e)

// ================= fused projection: V (+Q,K) via tf32 MMA, 3-stage ring =================
#define PJ_WS 0                         // 3 x 18432
#define PJ_XS 55296                     // 3 x 17408
#define PJ_BYTES (55296 + 52224)

__global__ __launch_bounds__(256, 2) void proj_kernel(
    const float* __restrict__ x,
    const float* __restrict__ Wq, const float* __restrict__ bq,
    const float* __restrict__ Wk, const float* __restrict__ bk,
    const float* __restrict__ Wv, const float* __restrict__ bv)
{
    extern __shared__ __align__(16) char sm[];
    uint32_t smU = smem_u32(sm);
    int t = threadIdx.x, wid = t >> 5, lane = t & 31;
    int mg = wid >> 1, ng = wid & 1;
    int n0 = blockIdx.x * 128, ytile = blockIdx.y, b = blockIdx.z;
    bool active = (ytile < 2) || (mg == 0);

    int wm = t >> 1, wq4 = t & 1;
    const float* wsrc;
    bool wvalid = true;
    if (ytile < 2) wsrc = Wv + (ytile * 128 + wm) * Cc;
    else {
        if (wm < 16) wsrc = Wq + wm * Cc;
        else if (wm < 32) wsrc = Wk + (wm - 16) * Cc;
        else { wsrc = Wq; wvalid = false; }
    }
    const float* xb = x + (size_t)b * Cc * Nn + n0;
    int xk = t >> 3, xn = t & 7;

#pragma unroll
    for (int ch = 0; ch < 2; ch++) {
        int k0 = ch * 32;
        if (wvalid) {
#pragma unroll
            for (int u = 0; u < 4; u++) {
                int kq = wq4 + 2 * u;
                cp16(smU + PJ_WS + ch * 18432 + wm * 144 + kq * 16, wsrc + k0 + kq * 4);
            }
        }
#pragma unroll
        for (int u = 0; u < 4; u++) {
            int nq = xn + 8 * u;
            cp16(smU + PJ_XS + ch * 17408 + xk * 544 + nq * 16, xb + (size_t)(k0 + xk) * Nn + nq * 4);
        }
        CP_COMMIT;
    }

    float acc[2][8][4];
#pragma unroll
    for (int i = 0; i < 2; i++)
#pragma unroll
        for (int j = 0; j < 8; j++)
#pragma unroll
            for (int q = 0; q < 4; q++) acc[i][j][q] = 0.f;

    int st = 0, sp = 2;
    for (int ch = 0; ch < 8; ch++) {
        CP_WAIT1;
        __syncthreads();
        if (ch + 2 < 8) {
            int k0 = (ch + 2) * 32;
            if (wvalid) {
#pragma unroll
                for (int u = 0; u < 4; u++) {
                    int kq = wq4 + 2 * u;
                    cp16(smU + PJ_WS + sp * 18432 + wm * 144 + kq * 16, wsrc + k0 + kq * 4);
                }
            }
#pragma unroll
            for (int u = 0; u < 4; u++) {
                int nq = xn + 8 * u;
                cp16(smU + PJ_XS + sp * 17408 + xk * 544 + nq * 16, xb + (size_t)(k0 + xk) * Nn + nq * 4);
            }
        }
        CP_COMMIT;
        if (active) {
            const float* wb = (const float*)(sm + PJ_WS + st * 18432);
            const float* xs = (const float*)(sm + PJ_XS + st * 17408);
#pragma unroll
            for (int k8 = 0; k8 < 4; k8++) {
                uint32_t A[2][4];
#pragma unroll
                for (int mi = 0; mi < 2; mi++) {
                    const float* ap = wb + (mg * 32 + mi * 16 + (lane >> 2)) * 36 + k8 * 8 + (lane & 3);
                    A[mi][0] = __float_as_uint(ap[0]);
                    A[mi][2] = __float_as_uint(ap[4]);
                    A[mi][1] = __float_as_uint(ap[8 * 36]);
                    A[mi][3] = __float_as_uint(ap[8 * 36 + 4]);
                }
                const float* bp = xs + (k8 * 8 + (lane & 3)) * 136 + ng * 64 + (lane >> 2);
#pragma unroll
                for (int nb = 0; nb < 8; nb++) {
                    uint32_t b0 = __float_as_uint(bp[nb * 8]);
                    uint32_t b1 = __float_as_uint(bp[nb * 8 + 4 * 136]);
                    mma_tf32(acc[0][nb], A[0], b0, b1);
                    mma_tf32(acc[1][nb], A[1], b0, b1);
                }
            }
        }
        st = (st == 2) ? 0 : st + 1;
        sp = (sp == 2) ? 0 : sp + 1;
    }
    __syncthreads();

    if (ytile < 2) {
        __nv_bfloat16* Tb = (__nv_bfloat16*)(sm + PJ_XS);
#pragma unroll
        for (int mi = 0; mi < 2; mi++) {
            int m = mg * 32 + mi * 16 + (lane >> 2);
            float bv0 = bv[ytile * 128 + m];
            float bv1 = bv[ytile * 128 + m + 8];
#pragma unroll
            for (int nb = 0; nb < 8; nb++) {
                int n = ng * 64 + nb * 8 + (lane & 3) * 2;
                float* a = acc[mi][nb];
                Tb[(size_t)n * 136 + m]           = __float2bfloat16(a[0] + bv0);
                Tb[(size_t)(n + 1) * 136 + m]     = __float2bfloat16(a[1] + bv0);
                Tb[(size_t)n * 136 + m + 8]       = __float2bfloat16(a[2] + bv1);
                Tb[(size_t)(n + 1) * 136 + m + 8] = __float2bfloat16(a[3] + bv1);
            }
        }
        __syncthreads();
        int n = t >> 1, c = t & 1;
        const uint4* src = (const uint4*)((const char*)Tb + n * 272 + c * 128);
        uint4* dst = (uint4*)((char*)(g_VT + ((size_t)(b * Nn + n0 + n)) * Cc + ytile * 128) + c * 128);
#pragma unroll
        for (int u = 0; u < 8; u++) dst[u] = src[u];
    } else {
        __nv_bfloat16* Qt = (__nv_bfloat16*)(sm + PJ_XS);            // [128][24]
        __nv_bfloat16* Kt = (__nv_bfloat16*)(sm + PJ_XS + 6144);     // [16][136]
        if (mg == 0) {
            {
                int d = lane >> 2;
                float b0 = bq[d], b1 = bq[d + 8];
#pragma unroll
                for (int nb = 0; nb < 8; nb++) {
                    int n = ng * 64 + nb * 8 + (lane & 3) * 2;
                    float* a = acc[0][nb];
                    Qt[(size_t)n * 24 + d]           = __float2bfloat16((a[0] + b0) * QSCALE);
                    Qt[(size_t)(n + 1) * 24 + d]     = __float2bfloat16((a[1] + b0) * QSCALE);
                    Qt[(size_t)n * 24 + d + 8]       = __float2bfloat16((a[2] + b1) * QSCALE);
                    Qt[(size_t)(n + 1) * 24 + d + 8] = __float2bfloat16((a[3] + b1) * QSCALE);
                }
            }
            {
                int d = lane >> 2;
                float b0 = bk[d], b1 = bk[d + 8];
#pragma unroll
                for (int nb = 0; nb < 8; nb++) {
                    int n = ng * 64 + nb * 8 + (lane & 3) * 2;
                    float* a = acc[1][nb];
                    Kt[(size_t)d * 136 + n]           = __float2bfloat16(a[0] + b0);
                    Kt[(size_t)d * 136 + n + 1]       = __float2bfloat16(a[1] + b0);
                    Kt[(size_t)(d + 8) * 136 + n]     = __float2bfloat16(a[2] + b1);
                    Kt[(size_t)(d + 8) * 136 + n + 1] = __float2bfloat16(a[3] + b1);
                }
            }
        }
        __syncthreads();
        {
            int n = t >> 1, c = t & 1;
            const uint4* src = (const uint4*)((const char*)Qt + n * 48 + c * 16);
            uint4* dst = (uint4*)((char*)(g_Qb + ((size_t)(b * Nn + n0 + n)) * Dd) + c * 16);
            dst[0] = src[0];
        }
        {
            int d = t >> 4, c = t & 15;
            const uint4* src = (const uint4*)((const char*)Kt + d * 272 + c * 16);
            uint4* dst = (uint4*)((char*)(g_Kb + ((size_t)(b * Dd + d)) * Nn + n0) + c * 16);
            dst[0] = src[0];
        }
    }
}

// ================= fused attention: TWO independent 256-thread pipelines per CTA =================
// per-group layout (bytes): VS 2x33792 @0 | KS 2x2304 @67584 | QS 3072 @72192 |
//                           PS 9216 @75264 | RS 512 @84480  -> GRP_BYTES 84992
#define GRP_BYTES 84992
#define G_VS 0
#define G_KS 67584
#define G_QS 72192
#define G_PS 75264
#define G_RS 84480
#define AT_BYTES (2 * GRP_BYTES)

__global__ __launch_bounds__(512, 1) void attn_kernel()
{
    extern __shared__ __align__(16) char sm[];
    int t = threadIdx.x, b = blockIdx.y;
    int g = t >> 8;                       // group 0/1
    int tg = t & 255;
    int wid8 = (t >> 5) & 7, lane = t & 31;
    int barid = g + 1;
    int m0 = blockIdx.x * 128 + g * 64;
    uint32_t gb = smem_u32(sm) + (uint32_t)g * GRP_BYTES;

    const char* vb = (const char*)(g_VT + (size_t)b * Nn * Cc);
    const char* kb = (const char*)(g_Kb + (size_t)b * Dd * Nn);
    const char* qb = (const char*)(g_Qb + ((size_t)b * Nn + m0) * Dd);

    // QK role: m16 x j32 ; PV role: m32 x e64
    int mgq = wid8 >> 1, jg = wid8 & 1;
    int mg2 = wid8 >> 2, eg = wid8 & 3;

    int vj = tg >> 2, vc = tg & 3;        // V: 64 rows x 512B (stride 528)
    int kd = tg >> 3, kc = tg & 7;        // K: 16 rows x 128B (stride 144)

    // ---- prologue: V/K(0) + Q ----
    {
        uint32_t dst = gb + G_VS + vj * 528 + vc * 16;
        const char* src = vb + (size_t)vj * 512 + vc * 16;
#pragma unroll
        for (int u = 0; u < 8; u++) cp16(dst + u * 64, src + u * 64);
        if (tg < 128) {
            cp16(gb + G_KS + kd * 144 + kc * 16, kb + (size_t)kd * (Nn * 2) + kc * 16);
            int m = tg >> 1, c = tg & 1;
            cp16(gb + G_QS + m * 48 + c * 16, qb + m * 32 + c * 16);
        }
        CP_COMMIT;
    }

    float acc[2][8][4];
#pragma unroll
    for (int i = 0; i < 2; i++)
#pragma unroll
        for (int j = 0; j < 8; j++)
#pragma unroll
            for (int q = 0; q < 4; q++) acc[i][j][q] = 0.f;

    uint32_t qa[4];
    float rs0 = 0.f, rs1 = 0.f;

    uint32_t ps_st = gb + G_PS + (mgq * 16 + (lane >> 2)) * 144 + (jg * 32 + (lane & 3) * 2) * 2;
    uint32_t ps_ld = gb + G_PS +
        (uint32_t)(mg2 * 32 + (lane & 7) + ((lane >> 3) & 1) * 8) * 144 + (lane >> 4) * 16;

    for (int it = 0; it < NTILES; it++) {
        CP_WAIT0;          // V/K(it) fully resident
        BARG(barid);       // group barrier: P free (prev PV done), stage (it+1)&1 free
        if (it == 0) {
            uint32_t qaddr = gb + G_QS +
                (mgq * 16 + (lane & 7) + ((lane >> 3) & 1) * 8) * 48 + (lane >> 4) * 16;
            ldsm_x4(qa[0], qa[1], qa[2], qa[3], qaddr);
        }
        // prefetch V/K(it+1) into the other stage
        if (it + 1 < NTILES) {
            int n0 = (it + 1) * BN, spx = (it + 1) & 1;
            uint32_t dst = gb + G_VS + spx * 33792 + vj * 528 + vc * 16;
            const char* src = vb + ((size_t)(n0 + vj)) * 512 + vc * 16;
#pragma unroll
            for (int u = 0; u < 8; u++) cp16(dst + u * 64, src + u * 64);
            if (tg < 128) cp16(gb + G_KS + spx * 2304 + kd * 144 + kc * 16,
                               kb + (size_t)kd * (Nn * 2) + n0 * 2 + kc * 16);
        }
        CP_COMMIT;

        // ---- QK(it): warp m16 x j32 -> exp -> P sts ----
        {
            uint32_t ksb = gb + G_KS + (it & 1) * 2304;
#pragma unroll
            for (int nb2 = 0; nb2 < 2; nb2++) {
                float c[2][4];
#pragma unroll
                for (int h = 0; h < 2; h++)
#pragma unroll
                    for (int j = 0; j < 4; j++) c[h][j] = 0.f;
                uint32_t b0, b1, b2, b3;
                uint32_t ka = ksb + (lane & 15) * 144 + (jg * 32 + nb2 * 16 + (lane >> 4) * 8) * 2;
                ldsm_x4t(b0, b1, b2, b3, ka);
                mma16816(c[0], qa, b0, b1);
                mma16816(c[1], qa, b2, b3);
#pragma unroll
                for (int h = 0; h < 2; h++) {
                    float e0 = ex2(fminf(fmaxf(c[h][0], -CLIP2), CLIP2));
                    float e1 = ex2(fminf(fmaxf(c[h][1], -CLIP2), CLIP2));
                    float e2 = ex2(fminf(fmaxf(c[h][2], -CLIP2), CLIP2));
                    float e3 = ex2(fminf(fmaxf(c[h][3], -CLIP2), CLIP2));
                    rs0 += e0 + e1;
                    rs1 += e2 + e3;
                    __nv_bfloat162 lo = __floats2bfloat162_rn(e0, e1);
                    __nv_bfloat162 hi = __floats2bfloat162_rn(e2, e3);
                    sts32(ps_st + nb2 * 32 + h * 16, *(uint32_t*)&lo);
                    sts32(ps_st + nb2 * 32 + h * 16 + 8 * 144, *(uint32_t*)&hi);
                }
            }
        }
        BARG(barid);       // P visible to group

        // ---- PV(it): warp m32 x e64 ----
        {
            uint32_t vsb = gb + G_VS + (it & 1) * 33792;
#pragma unroll
            for (int kg = 0; kg < 4; kg++) {
                uint32_t pA[2][4];
#pragma unroll
                for (int mi = 0; mi < 2; mi++)
                    ldsm_x4(pA[mi][0], pA[mi][1], pA[mi][2], pA[mi][3],
                            ps_ld + mi * (16 * 144) + kg * 32);
#pragma unroll
                for (int eb2 = 0; eb2 < 4; eb2++) {
                    uint32_t b0, b1, b2, b3;
                    uint32_t va = vsb + (kg * 16 + (lane & 15)) * 528 +
                                  (eg * 64 + eb2 * 16 + (lane >> 4) * 8) * 2;
                    ldsm_x4t(b0, b1, b2, b3, va);
                    mma16816(acc[0][eb2 * 2],     pA[0], b0, b1);
                    mma16816(acc[0][eb2 * 2 + 1], pA[0], b2, b3);
                    mma16816(acc[1][eb2 * 2],     pA[1], b0, b1);
                    mma16816(acc[1][eb2 * 2 + 1], pA[1], b2, b3);
                }
            }
        }
    }

    // ---- rowsums ----
    rs0 += __shfl_xor_sync(0xffffffffu, rs0, 1);
    rs0 += __shfl_xor_sync(0xffffffffu, rs0, 2);
    rs1 += __shfl_xor_sync(0xffffffffu, rs1, 1);
    rs1 += __shfl_xor_sync(0xffffffffu, rs1, 2);
    float* rs_s = (float*)(sm + (size_t)g * GRP_BYTES + G_RS);
    if ((lane & 3) == 0) {
        rs_s[jg * 64 + mgq * 16 + (lane >> 2)]     = rs0;
        rs_s[jg * 64 + mgq * 16 + (lane >> 2) + 8] = rs1;
    }
    BARG(barid);           // rs visible; V region free for staging

    // ---- epilogue: normalize -> smem [e128 x 68] -> coalesced stores, 2 e-halves ----
    float* Tf = (float*)(sm + (size_t)g * GRP_BYTES + G_VS);
    float* ob = g_OA + (size_t)b * Cc * Nn + m0;
    int r = lane >> 2, q = lane & 3;
#pragma unroll
    for (int h = 0; h < 2; h++) {
        if ((eg >> 1) == h) {
            int ebase = (eg & 1) * 64;
#pragma unroll
            for (int mi = 0; mi < 2; mi++) {
                int ml = mg2 * 32 + mi * 16 + r;
                float inv0 = 1.f / (rs_s[ml]     + rs_s[64 + ml]);
                float inv1 = 1.f / (rs_s[ml + 8] + rs_s[64 + ml + 8]);
#pragma unroll
                for (int nb = 0; nb < 8; nb++) {
                    int e = ebase + nb * 8 + 2 * q;
                    float* a = acc[mi][nb];
                    Tf[(size_t)e * 68 + ml]           = a[0] * inv0;
                    Tf[(size_t)(e + 1) * 68 + ml]     = a[1] * inv0;
                    Tf[(size_t)e * 68 + ml + 8]       = a[2] * inv1;
                    Tf[(size_t)(e + 1) * 68 + ml + 8] = a[3] * inv1;
                }
            }
        }
        BARG(barid);
#pragma unroll
        for (int rr = 0; rr < 16; rr++) {
            int e = wid8 * 16 + rr;
            const float* srcr = Tf + (size_t)e * 68;
            float* dstr = ob + (size_t)(h * 128 + e) * Nn;
            dstr[lane]      = srcr[lane];
            dstr[32 + lane] = srcr[32 + lane];
        }
        BARG(barid);
    }
}

// ================= output projection via tf32 MMA, 3-stage ring + residual =================
__global__ __launch_bounds__(256, 2) void outproj_kernel(
    const float* __restrict__ x,
    const float* __restrict__ Wo, const float* __restrict__ bo,
    const float* __restrict__ gamma, float* __restrict__ out)
{
    extern __shared__ __align__(16) char sm[];
    uint32_t smU = smem_u32(sm);
    int t = threadIdx.x, wid = t >> 5, lane = t & 31;
    int mg = wid >> 1, ng = wid & 1;
    int n0 = blockIdx.x * 128, ytile = blockIdx.y, b = blockIdx.z;

    int wm = t >> 1, wq4 = t & 1;
    const float* wsrc = Wo + (ytile * 128 + wm) * Cc;
    const float* xb = g_OA + (size_t)b * Cc * Nn + n0;
    int xk = t >> 3, xn = t & 7;

#pragma unroll
    for (int ch = 0; ch < 2; ch++) {
        int k0 = ch * 32;
#pragma unroll
        for (int u = 0; u < 4; u++) {
            int kq = wq4 + 2 * u;
            cp16(smU + PJ_WS + ch * 18432 + wm * 144 + kq * 16, wsrc + k0 + kq * 4);
        }
#pragma unroll
        for (int u = 0; u < 4; u++) {
            int nq = xn + 8 * u;
            cp16(smU + PJ_XS + ch * 17408 + xk * 544 + nq * 16, xb + (size_t)(k0 + xk) * Nn + nq * 4);
        }
        CP_COMMIT;
    }

    float acc[2][8][4];
#pragma unroll
    for (int i = 0; i < 2; i++)
#pragma unroll
        for (int j = 0; j < 8; j++)
#pragma unroll
            for (int q = 0; q < 4; q++) acc[i][j][q] = 0.f;

    int st = 0, sp = 2;
    for (int ch = 0; ch < 8; ch++) {
        CP_WAIT1;
        __syncthreads();
        if (ch + 2 < 8) {
            int k0 = (ch + 2) * 32;
#pragma unroll
            for (int u = 0; u < 4; u++) {
                int kq = wq4 + 2 * u;
                cp16(smU + PJ_WS + sp * 18432 + wm * 144 + kq * 16, wsrc + k0 + kq * 4);
            }
#pragma unroll
            for (int u = 0; u < 4; u++) {
                int nq = xn + 8 * u;
                cp16(smU + PJ_XS + sp * 17408 + xk * 544 + nq * 16, xb + (size_t)(k0 + xk) * Nn + nq * 4);
            }
        }
        CP_COMMIT;
        {
            const float* wb = (const float*)(sm + PJ_WS + st * 18432);
            const float* xs = (const float*)(sm + PJ_XS + st * 17408);
#pragma unroll
            for (int k8 = 0; k8 < 4; k8++) {
                uint32_t A[2][4];
#pragma unroll
                for (int mi = 0; mi < 2; mi++) {
                    const float* ap = wb + (mg * 32 + mi * 16 + (lane >> 2)) * 36 + k8 * 8 + (lane & 3);
                    A[mi][0] = __float_as_uint(ap[0]);
                    A[mi][2] = __float_as_uint(ap[4]);
                    A[mi][1] = __float_as_uint(ap[8 * 36]);
                    A[mi][3] = __float_as_uint(ap[8 * 36 + 4]);
                }
                const float* bp = xs + (k8 * 8 + (lane & 3)) * 136 + ng * 64 + (lane >> 2);
#pragma unroll
                for (int nb = 0; nb < 8; nb++) {
                    uint32_t b0 = __float_as_uint(bp[nb * 8]);
                    uint32_t b1 = __float_as_uint(bp[nb * 8 + 4 * 136]);
                    mma_tf32(acc[0][nb], A[0], b0, b1);
                    mma_tf32(acc[1][nb], A[1], b0, b1);
                }
            }
        }
        st = (st == 2) ? 0 : st + 1;
        sp = (sp == 2) ? 0 : sp + 1;
    }
    __syncthreads();

    float* Tf = (float*)sm;
#pragma unroll
    for (int mi = 0; mi < 2; mi++) {
        int m = mg * 32 + mi * 16 + (lane >> 2);
#pragma unroll
        for (int nb = 0; nb < 8; nb++) {
            int n = ng * 64 + nb * 8 + (lane & 3) * 2;
            float* a = acc[mi][nb];
            *(float2*)(Tf + (size_t)m * 132 + n)       = make_float2(a[0], a[1]);
            *(float2*)(Tf + (size_t)(m + 8) * 132 + n) = make_float2(a[2], a[3]);
        }
    }
    __syncthreads();
    float g = fminf(fmaxf(gamma[0], 0.f), 1.f);
    {
        int m = t >> 1, c = t & 1;
        int mglob = ytile * 128 + m;
        float bb = bo[mglob];
        size_t base = ((size_t)(b * Cc + mglob)) * Nn + n0 + c * 64;
#pragma unroll
        for (int u = 0; u < 16; u++) {
            float4 v = *(const float4*)(Tf + (size_t)m * 132 + c * 64 + u * 4);
            float4 xr = *(const float4*)(x + base + u * 4);
            float4 o;
            o.x = g * (v.x + bb) + xr.x;
            o.y = g * (v.y + bb) + xr.y;
            o.z = g * (v.z + bb) + xr.z;
            o.w = g * (v.w + bb) + xr.w;
            *(float4*)(out + base + u * 4) = o;
        }
    }
}

// ---------------- launcher ----------------
extern "C" void kernel_launch(void* const* d_in, const int* in_sizes, int n_in,
                              void* d_out, int out_size)
{
    const float* x     = (const float*)d_in[0];
    const float* Wq    = (const float*)d_in[1];
    const float* bq    = (const float*)d_in[2];
    const float* Wk    = (const float*)d_in[3];
    const float* bk    = (const float*)d_in[4];
    const float* Wv    = (const float*)d_in[5];
    const float* bv    = (const float*)d_in[6];
    const float* Wo    = (const float*)d_in[7];
    const float* bo    = (const float*)d_in[8];
    const float* gamma = (const float*)d_in[9];
    float* out = (float*)d_out;

    cudaFuncSetAttribute(proj_kernel,    cudaFuncAttributeMaxDynamicSharedMemorySize, PJ_BYTES);
    cudaFuncSetAttribute(outproj_kernel, cudaFuncAttributeMaxDynamicSharedMemorySize, PJ_BYTES);
    cudaFuncSetAttribute(attn_kernel,    cudaFuncAttributeMaxDynamicSharedMemorySize, AT_BYTES);

    proj_kernel   <<<dim3(Nn / 128, 3, Bb), 256, PJ_BYTES>>>(x, Wq, bq, Wk, bk, Wv, bv);
    attn_kernel   <<<dim3(Nn / 128, Bb), 512, AT_BYTES>>>();
    outproj_kernel<<<dim3(Nn / 128, 2, Bb), 256, PJ_BYTES>>>(x, Wo, bo, gamma, out);
}

// round 12
// speedup vs baseline: 1.2669x; 1.2669x over previous
#include <cuda_runtime.h>
#include <cuda_bf16.h>
#include <cstdint>

#define Bb 8
#define Cc 256
#define Nn 4096
#define Dd 16
#define BM 128
#define BN 64
#define NTILES (Nn / BN)

typedef unsigned long long ull;

// ---------------- scratch ----------------
__device__ __nv_bfloat16 g_Qb[(size_t)Bb * Nn * Dd];   // [B,N,16] bf16, (q+bq)*0.25*log2e
__device__ __nv_bfloat16 g_Kb[(size_t)Bb * Dd * Nn];   // [B,16,N] bf16, k+bk
__device__ __nv_bfloat16 g_VT[(size_t)Bb * Nn * Cc];   // [B,N,C] bf16
__device__ float g_OA[(size_t)Bb * Cc * Nn];           // [B,C,N]

// ---------------- helpers ----------------
static __device__ __forceinline__ uint32_t smem_u32(const void* p) {
    uint32_t a;
    asm("{ .reg .u64 t; cvta.to.shared.u64 t, %1; cvt.u32.u64 %0, t; }" : "=r"(a) : "l"(p));
    return a;
}
static __device__ __forceinline__ void ldsm_x4(uint32_t &r0, uint32_t &r1, uint32_t &r2, uint32_t &r3, uint32_t addr) {
    asm volatile("ldmatrix.sync.aligned.m8n8.x4.shared.b16 {%0,%1,%2,%3}, [%4];"
                 : "=r"(r0), "=r"(r1), "=r"(r2), "=r"(r3) : "r"(addr));
}
static __device__ __forceinline__ void ldsm_x4t(uint32_t &r0, uint32_t &r1, uint32_t &r2, uint32_t &r3, uint32_t addr) {
    asm volatile("ldmatrix.sync.aligned.m8n8.x4.trans.shared.b16 {%0,%1,%2,%3}, [%4];"
                 : "=r"(r0), "=r"(r1), "=r"(r2), "=r"(r3) : "r"(addr));
}
static __device__ __forceinline__ void mma16816(float* d, const uint32_t* a, uint32_t b0, uint32_t b1) {
    asm volatile("mma.sync.aligned.m16n8k16.row.col.f32.bf16.bf16.f32 "
                 "{%0,%1,%2,%3}, {%4,%5,%6,%7}, {%8,%9}, {%0,%1,%2,%3};"
                 : "+f"(d[0]), "+f"(d[1]), "+f"(d[2]), "+f"(d[3])
                 : "r"(a[0]), "r"(a[1]), "r"(a[2]), "r"(a[3]), "r"(b0), "r"(b1));
}
static __device__ __forceinline__ void mma_tf32(float* d, const uint32_t* a, uint32_t b0, uint32_t b1) {
    asm volatile("mma.sync.aligned.m16n8k8.row.col.f32.tf32.tf32.f32 "
                 "{%0,%1,%2,%3}, {%4,%5,%6,%7}, {%8,%9}, {%0,%1,%2,%3};"
                 : "+f"(d[0]), "+f"(d[1]), "+f"(d[2]), "+f"(d[3])
                 : "r"(a[0]), "r"(a[1]), "r"(a[2]), "r"(a[3]), "r"(b0), "r"(b1));
}
static __device__ __forceinline__ float ex2(float x) {
    float y; asm("ex2.approx.ftz.f32 %0, %1;" : "=f"(y) : "f"(x)); return y;
}
static __device__ __forceinline__ void sts32(uint32_t addr, uint32_t v) {
    asm volatile("st.shared.b32 [%0], %1;" :: "r"(addr), "r"(v));
}
static __device__ __forceinline__ void cp16(uint32_t dst, const void* src) {
    asm volatile("cp.async.cg.shared.global [%0], [%1], 16;" :: "r"(dst), "l"(src));
}
#define CP_COMMIT asm volatile("cp.async.commit_group;" ::: "memory")
#define CP_WAIT1  asm volatile("cp.async.wait_group 1;" ::: "memory")
#define CP_WAIT2  asm volatile("cp.async.wait_group 2;" ::: "memory")

#define QSCALE 0.36067376022224085f   // 0.25 * log2(e)
#define CLIP2  72.134752f             // 50 * log2(e)

// ================= fused projection: V (+Q,K) via tf32 MMA, 3-stage ring =================
#define PJ_WS 0                         // 3 x 18432
#define PJ_XS 55296                     // 3 x 17408
#define PJ_BYTES (55296 + 52224)

__global__ __launch_bounds__(256, 2) void proj_kernel(
    const float* __restrict__ x,
    const float* __restrict__ Wq, const float* __restrict__ bq,
    const float* __restrict__ Wk, const float* __restrict__ bk,
    const float* __restrict__ Wv, const float* __restrict__ bv)
{
    extern __shared__ __align__(16) char sm[];
    uint32_t smU = smem_u32(sm);
    int t = threadIdx.x, wid = t >> 5, lane = t & 31;
    int mg = wid >> 1, ng = wid & 1;
    int n0 = blockIdx.x * 128, ytile = blockIdx.y, b = blockIdx.z;
    bool active = (ytile < 2) || (mg == 0);

    int wm = t >> 1, wq4 = t & 1;
    const float* wsrc;
    bool wvalid = true;
    if (ytile < 2) wsrc = Wv + (ytile * 128 + wm) * Cc;
    else {
        if (wm < 16) wsrc = Wq + wm * Cc;
        else if (wm < 32) wsrc = Wk + (wm - 16) * Cc;
        else { wsrc = Wq; wvalid = false; }
    }
    const float* xb = x + (size_t)b * Cc * Nn + n0;
    int xk = t >> 3, xn = t & 7;

#pragma unroll
    for (int ch = 0; ch < 2; ch++) {
        int k0 = ch * 32;
        if (wvalid) {
#pragma unroll
            for (int u = 0; u < 4; u++) {
                int kq = wq4 + 2 * u;
                cp16(smU + PJ_WS + ch * 18432 + wm * 144 + kq * 16, wsrc + k0 + kq * 4);
            }
        }
#pragma unroll
        for (int u = 0; u < 4; u++) {
            int nq = xn + 8 * u;
            cp16(smU + PJ_XS + ch * 17408 + xk * 544 + nq * 16, xb + (size_t)(k0 + xk) * Nn + nq * 4);
        }
        CP_COMMIT;
    }

    float acc[2][8][4];
#pragma unroll
    for (int i = 0; i < 2; i++)
#pragma unroll
        for (int j = 0; j < 8; j++)
#pragma unroll
            for (int q = 0; q < 4; q++) acc[i][j][q] = 0.f;

    int st = 0, sp = 2;
    for (int ch = 0; ch < 8; ch++) {
        CP_WAIT1;
        __syncthreads();
        if (ch + 2 < 8) {
            int k0 = (ch + 2) * 32;
            if (wvalid) {
#pragma unroll
                for (int u = 0; u < 4; u++) {
                    int kq = wq4 + 2 * u;
                    cp16(smU + PJ_WS + sp * 18432 + wm * 144 + kq * 16, wsrc + k0 + kq * 4);
                }
            }
#pragma unroll
            for (int u = 0; u < 4; u++) {
                int nq = xn + 8 * u;
                cp16(smU + PJ_XS + sp * 17408 + xk * 544 + nq * 16, xb + (size_t)(k0 + xk) * Nn + nq * 4);
            }
        }
        CP_COMMIT;
        if (active) {
            const float* wb = (const float*)(sm + PJ_WS + st * 18432);
            const float* xs = (const float*)(sm + PJ_XS + st * 17408);
#pragma unroll
            for (int k8 = 0; k8 < 4; k8++) {
                uint32_t A[2][4];
#pragma unroll
                for (int mi = 0; mi < 2; mi++) {
                    const float* ap = wb + (mg * 32 + mi * 16 + (lane >> 2)) * 36 + k8 * 8 + (lane & 3);
                    A[mi][0] = __float_as_uint(ap[0]);
                    A[mi][2] = __float_as_uint(ap[4]);
                    A[mi][1] = __float_as_uint(ap[8 * 36]);
                    A[mi][3] = __float_as_uint(ap[8 * 36 + 4]);
                }
                const float* bp = xs + (k8 * 8 + (lane & 3)) * 136 + ng * 64 + (lane >> 2);
#pragma unroll
                for (int nb = 0; nb < 8; nb++) {
                    uint32_t b0 = __float_as_uint(bp[nb * 8]);
                    uint32_t b1 = __float_as_uint(bp[nb * 8 + 4 * 136]);
                    mma_tf32(acc[0][nb], A[0], b0, b1);
                    mma_tf32(acc[1][nb], A[1], b0, b1);
                }
            }
        }
        st = (st == 2) ? 0 : st + 1;
        sp = (sp == 2) ? 0 : sp + 1;
    }
    __syncthreads();

    if (ytile < 2) {
        __nv_bfloat16* Tb = (__nv_bfloat16*)(sm + PJ_XS);
#pragma unroll
        for (int mi = 0; mi < 2; mi++) {
            int m = mg * 32 + mi * 16 + (lane >> 2);
            float bv0 = bv[ytile * 128 + m];
            float bv1 = bv[ytile * 128 + m + 8];
#pragma unroll
            for (int nb = 0; nb < 8; nb++) {
                int n = ng * 64 + nb * 8 + (lane & 3) * 2;
                float* a = acc[mi][nb];
                Tb[(size_t)n * 136 + m]           = __float2bfloat16(a[0] + bv0);
                Tb[(size_t)(n + 1) * 136 + m]     = __float2bfloat16(a[1] + bv0);
                Tb[(size_t)n * 136 + m + 8]       = __float2bfloat16(a[2] + bv1);
                Tb[(size_t)(n + 1) * 136 + m + 8] = __float2bfloat16(a[3] + bv1);
            }
        }
        __syncthreads();
        int n = t >> 1, c = t & 1;
        const uint4* src = (const uint4*)((const char*)Tb + n * 272 + c * 128);
        uint4* dst = (uint4*)((char*)(g_VT + ((size_t)(b * Nn + n0 + n)) * Cc + ytile * 128) + c * 128);
#pragma unroll
        for (int u = 0; u < 8; u++) dst[u] = src[u];
    } else {
        __nv_bfloat16* Qt = (__nv_bfloat16*)(sm + PJ_XS);            // [128][24]
        __nv_bfloat16* Kt = (__nv_bfloat16*)(sm + PJ_XS + 6144);     // [16][136]
        if (mg == 0) {
            {
                int d = lane >> 2;
                float b0 = bq[d], b1 = bq[d + 8];
#pragma unroll
                for (int nb = 0; nb < 8; nb++) {
                    int n = ng * 64 + nb * 8 + (lane & 3) * 2;
                    float* a = acc[0][nb];
                    Qt[(size_t)n * 24 + d]           = __float2bfloat16((a[0] + b0) * QSCALE);
                    Qt[(size_t)(n + 1) * 24 + d]     = __float2bfloat16((a[1] + b0) * QSCALE);
                    Qt[(size_t)n * 24 + d + 8]       = __float2bfloat16((a[2] + b1) * QSCALE);
                    Qt[(size_t)(n + 1) * 24 + d + 8] = __float2bfloat16((a[3] + b1) * QSCALE);
                }
            }
            {
                int d = lane >> 2;
                float b0 = bk[d], b1 = bk[d + 8];
#pragma unroll
                for (int nb = 0; nb < 8; nb++) {
                    int n = ng * 64 + nb * 8 + (lane & 3) * 2;
                    float* a = acc[1][nb];
                    Kt[(size_t)d * 136 + n]           = __float2bfloat16(a[0] + b0);
                    Kt[(size_t)d * 136 + n + 1]       = __float2bfloat16(a[1] + b0);
                    Kt[(size_t)(d + 8) * 136 + n]     = __float2bfloat16(a[2] + b1);
                    Kt[(size_t)(d + 8) * 136 + n + 1] = __float2bfloat16(a[3] + b1);
                }
            }
        }
        __syncthreads();
        {
            int n = t >> 1, c = t & 1;
            const uint4* src = (const uint4*)((const char*)Qt + n * 48 + c * 16);
            uint4* dst = (uint4*)((char*)(g_Qb + ((size_t)(b * Nn + n0 + n)) * Dd) + c * 16);
            dst[0] = src[0];
        }
        {
            int d = t >> 4, c = t & 15;
            const uint4* src = (const uint4*)((const char*)Kt + d * 272 + c * 16);
            uint4* dst = (uint4*)((char*)(g_Kb + ((size_t)(b * Dd + d)) * Nn + n0) + c * 16);
            dst[0] = src[0];
        }
    }
}

// ================= fused attention: pipelined split-role FA2, 5-stage ring, 1 sync/iter =================
// smem: VS 5x33792 | KS 5x2304 @168960 | QS 6144 @180480 | PS 2x18432 @186624 | RS 1024 @223488
#define AT_VS 0
#define AT_KS 168960
#define AT_QS 180480
#define AT_PS 186624
#define AT_RS 223488
#define AT_BYTES 224512

__global__ __launch_bounds__(512, 1) void attn_kernel()
{
    extern __shared__ __align__(16) char sm[];
    uint32_t smU = smem_u32(sm);
    int t = threadIdx.x, b = blockIdx.y, m0 = blockIdx.x * BM;
    int wid = t >> 5, lane = t & 31;
    int mg = wid >> 1, jg = wid & 1;    // QK role: m16 x j32 (disjoint)
    int mg2 = wid >> 2, eg = wid & 3;   // PV role: m32 x e64

    const char* vb = (const char*)(g_VT + (size_t)b * Nn * Cc);
    const char* kb = (const char*)(g_Kb + (size_t)b * Dd * Nn);
    const char* qb = (const char*)(g_Qb + ((size_t)b * Nn + m0) * Dd);

    int vj = t >> 3, vc = t & 7;
    int kd = t >> 3, kc = t & 7;

    // prologue: stages 0,1,2 (+Q)
#pragma unroll
    for (int st = 0; st < 3; st++) {
        int n0 = st * BN;
        uint32_t dst = smU + AT_VS + st * 33792 + vj * 528 + vc * 16;
        const char* src = vb + ((size_t)(n0 + vj)) * 512 + vc * 16;
#pragma unroll
        for (int u = 0; u < 4; u++) cp16(dst + u * 128, src + u * 128);
        if (t < 128) cp16(smU + AT_KS + st * 2304 + kd * 144 + kc * 16,
                          kb + (size_t)kd * (Nn * 2) + n0 * 2 + kc * 16);
        if (st == 0 && t < 256) {
            int m = t >> 1, c = t & 1;
            cp16(smU + AT_QS + m * 48 + c * 16, qb + m * 32 + c * 16);
        }
        CP_COMMIT;
    }

    float acc[2][8][4];
#pragma unroll
    for (int i = 0; i < 2; i++)
#pragma unroll
        for (int j = 0; j < 8; j++)
#pragma unroll
            for (int q = 0; q < 4; q++) acc[i][j][q] = 0.f;

    uint32_t qa[4];
    float rs0 = 0.f, rs1 = 0.f;

    uint32_t ps_st0 = smU + AT_PS + (mg * 16 + (lane >> 2)) * 144 + (jg * 32 + (lane & 3) * 2) * 2;
    uint32_t ps_ld0 = smU + AT_PS +
        (uint32_t)(mg2 * 32 + (lane & 7) + ((lane >> 3) & 1) * 8) * 144 + (lane >> 4) * 16;

    // ---- peeled: wait stage0 (2 groups may stay in flight), QK(0) -> Pbuf0 ----
    CP_WAIT2;
    __syncthreads();
    {
        uint32_t qaddr = smU + AT_QS +
            (mg * 16 + (lane & 7) + ((lane >> 3) & 1) * 8) * 48 + (lane >> 4) * 16;
        ldsm_x4(qa[0], qa[1], qa[2], qa[3], qaddr);
    }
    {
        uint32_t ksb = smU + AT_KS;      // stage 0
        uint32_t pst = ps_st0;            // buf 0
#pragma unroll
        for (int nb2 = 0; nb2 < 2; nb2++) {
            float c[2][4];
#pragma unroll
            for (int h = 0; h < 2; h++)
#pragma unroll
                for (int j = 0; j < 4; j++) c[h][j] = 0.f;
            uint32_t b0, b1, b2, b3;
            uint32_t ka = ksb + (lane & 15) * 144 + (jg * 32 + nb2 * 16 + (lane >> 4) * 8) * 2;
            ldsm_x4t(b0, b1, b2, b3, ka);
            mma16816(c[0], qa, b0, b1);
            mma16816(c[1], qa, b2, b3);
#pragma unroll
            for (int h = 0; h < 2; h++) {
                float e0 = ex2(fminf(fmaxf(c[h][0], -CLIP2), CLIP2));
                float e1 = ex2(fminf(fmaxf(c[h][1], -CLIP2), CLIP2));
                float e2 = ex2(fminf(fmaxf(c[h][2], -CLIP2), CLIP2));
                float e3 = ex2(fminf(fmaxf(c[h][3], -CLIP2), CLIP2));
                rs0 += e0 + e1;
                rs1 += e2 + e3;
                __nv_bfloat162 lo = __floats2bfloat162_rn(e0, e1);
                __nv_bfloat162 hi = __floats2bfloat162_rn(e2, e3);
                sts32(pst + nb2 * 32 + h * 16, *(uint32_t*)&lo);
                sts32(pst + nb2 * 32 + h * 16 + 8 * 144, *(uint32_t*)&hi);
            }
        }
    }

    // ---- main loop: one sync per iteration, prefetch distance 3 ----
    for (int it = 0; it < NTILES; it++) {
        // prefetch V/K(it+3) into stage (it+3)%5 (last read in iter it-2; safe: sync of it-1 passed)
        if (it + 3 < NTILES) {
            int n0 = (it + 3) * BN;
            int sp = (it + 3) % 5;
            uint32_t dst = smU + AT_VS + sp * 33792 + vj * 528 + vc * 16;
            const char* src = vb + ((size_t)(n0 + vj)) * 512 + vc * 16;
#pragma unroll
            for (int u = 0; u < 4; u++) cp16(dst + u * 128, src + u * 128);
            if (t < 128) cp16(smU + AT_KS + sp * 2304 + kd * 144 + kc * 16,
                              kb + (size_t)kd * (Nn * 2) + n0 * 2 + kc * 16);
        }
        CP_COMMIT;
        CP_WAIT2;          // V(it), K(it+1) resident; (it+2),(it+3) may fly
        __syncthreads();   // P(it) visible; prior-stage readers done

        // ---- QK(it+1) -> Pbuf[(it+1)&1] ----
        if (it + 1 < NTILES) {
            uint32_t ksb = smU + AT_KS + ((it + 1) % 5) * 2304;
            uint32_t pst = ps_st0 + ((it + 1) & 1) * 18432;
#pragma unroll
            for (int nb2 = 0; nb2 < 2; nb2++) {
                float c[2][4];
#pragma unroll
                for (int h = 0; h < 2; h++)
#pragma unroll
                    for (int j = 0; j < 4; j++) c[h][j] = 0.f;
                uint32_t b0, b1, b2, b3;
                uint32_t ka = ksb + (lane & 15) * 144 + (jg * 32 + nb2 * 16 + (lane >> 4) * 8) * 2;
                ldsm_x4t(b0, b1, b2, b3, ka);
                mma16816(c[0], qa, b0, b1);
                mma16816(c[1], qa, b2, b3);
#pragma unroll
                for (int h = 0; h < 2; h++) {
                    float e0 = ex2(fminf(fmaxf(c[h][0], -CLIP2), CLIP2));
                    float e1 = ex2(fminf(fmaxf(c[h][1], -CLIP2), CLIP2));
                    float e2 = ex2(fminf(fmaxf(c[h][2], -CLIP2), CLIP2));
                    float e3 = ex2(fminf(fmaxf(c[h][3], -CLIP2), CLIP2));
                    rs0 += e0 + e1;
                    rs1 += e2 + e3;
                    __nv_bfloat162 lo = __floats2bfloat162_rn(e0, e1);
                    __nv_bfloat162 hi = __floats2bfloat162_rn(e2, e3);
                    sts32(pst + nb2 * 32 + h * 16, *(uint32_t*)&lo);
                    sts32(pst + nb2 * 32 + h * 16 + 8 * 144, *(uint32_t*)&hi);
                }
            }
        }

        // ---- PV(it): Pbuf[it&1], V stage it%5 ----
        {
            uint32_t vsb = smU + AT_VS + (it % 5) * 33792;
            uint32_t pld = ps_ld0 + (it & 1) * 18432;
#pragma unroll
            for (int kg = 0; kg < 4; kg++) {
                uint32_t pA[2][4];
#pragma unroll
                for (int mi = 0; mi < 2; mi++)
                    ldsm_x4(pA[mi][0], pA[mi][1], pA[mi][2], pA[mi][3],
                            pld + mi * (16 * 144) + kg * 32);
#pragma unroll
                for (int eb2 = 0; eb2 < 4; eb2++) {
                    uint32_t b0, b1, b2, b3;
                    uint32_t va = vsb + (kg * 16 + (lane & 15)) * 528 +
                                  (eg * 64 + eb2 * 16 + (lane >> 4) * 8) * 2;
                    ldsm_x4t(b0, b1, b2, b3, va);
                    mma16816(acc[0][eb2 * 2],     pA[0], b0, b1);
                    mma16816(acc[0][eb2 * 2 + 1], pA[0], b2, b3);
                    mma16816(acc[1][eb2 * 2],     pA[1], b0, b1);
                    mma16816(acc[1][eb2 * 2 + 1], pA[1], b2, b3);
                }
            }
        }
    }

    // rowsum reduce + stash
    rs0 += __shfl_xor_sync(0xffffffffu, rs0, 1);
    rs0 += __shfl_xor_sync(0xffffffffu, rs0, 2);
    rs1 += __shfl_xor_sync(0xffffffffu, rs1, 1);
    rs1 += __shfl_xor_sync(0xffffffffu, rs1, 2);
    float* rs_s = (float*)(sm + AT_RS);
    if ((lane & 3) == 0) {
        rs_s[jg * 128 + mg * 16 + (lane >> 2)]     = rs0;
        rs_s[jg * 128 + mg * 16 + (lane >> 2) + 8] = rs1;
    }

    // epilogue: normalize -> smem stage [e128 x 132] -> coalesced stores (2 e-halves)
    float* Tf = (float*)sm;
    float* ob = g_OA + (size_t)b * Cc * Nn + m0;
    int r = lane >> 2, q = lane & 3;
#pragma unroll
    for (int h = 0; h < 2; h++) {
        __syncthreads();
        if ((eg >> 1) == h) {
            int ebase = (eg & 1) * 64;
#pragma unroll
            for (int mi = 0; mi < 2; mi++) {
                int ml = mg2 * 32 + mi * 16 + r;
                float inv0 = 1.f / (rs_s[ml]     + rs_s[128 + ml]);
                float inv1 = 1.f / (rs_s[ml + 8] + rs_s[128 + ml + 8]);
#pragma unroll
                for (int nb = 0; nb < 8; nb++) {
                    int e = ebase + nb * 8 + 2 * q;
                    float* a = acc[mi][nb];
                    Tf[(size_t)e * 132 + ml]           = a[0] * inv0;
                    Tf[(size_t)(e + 1) * 132 + ml]     = a[1] * inv0;
                    Tf[(size_t)e * 132 + ml + 8]       = a[2] * inv1;
                    Tf[(size_t)(e + 1) * 132 + ml + 8] = a[3] * inv1;
                }
            }
        }
        __syncthreads();
#pragma unroll
        for (int rr = 0; rr < 8; rr++) {
            int e = wid * 8 + rr;
            const float* srcr = Tf + (size_t)e * 132;
            float* dstr = ob + (size_t)(h * 128 + e) * Nn;
#pragma unroll
            for (int c = 0; c < 4; c++)
                dstr[c * 32 + lane] = srcr[c * 32 + lane];
        }
    }
}

// ================= output projection via tf32 MMA, 3-stage ring + residual =================
__global__ __launch_bounds__(256, 2) void outproj_kernel(
    const float* __restrict__ x,
    const float* __restrict__ Wo, const float* __restrict__ bo,
    const float* __restrict__ gamma, float* __restrict__ out)
{
    extern __shared__ __align__(16) char sm[];
    uint32_t smU = smem_u32(sm);
    int t = threadIdx.x, wid = t >> 5, lane = t & 31;
    int mg = wid >> 1, ng = wid & 1;
    int n0 = blockIdx.x * 128, ytile = blockIdx.y, b = blockIdx.z;

    int wm = t >> 1, wq4 = t & 1;
    const float* wsrc = Wo + (ytile * 128 + wm) * Cc;
    const float* xb = g_OA + (size_t)b * Cc * Nn + n0;
    int xk = t >> 3, xn = t & 7;

#pragma unroll
    for (int ch = 0; ch < 2; ch++) {
        int k0 = ch * 32;
#pragma unroll
        for (int u = 0; u < 4; u++) {
            int kq = wq4 + 2 * u;
            cp16(smU + PJ_WS + ch * 18432 + wm * 144 + kq * 16, wsrc + k0 + kq * 4);
        }
#pragma unroll
        for (int u = 0; u < 4; u++) {
            int nq = xn + 8 * u;
            cp16(smU + PJ_XS + ch * 17408 + xk * 544 + nq * 16, xb + (size_t)(k0 + xk) * Nn + nq * 4);
        }
        CP_COMMIT;
    }

    float acc[2][8][4];
#pragma unroll
    for (int i = 0; i < 2; i++)
#pragma unroll
        for (int j = 0; j < 8; j++)
#pragma unroll
            for (int q = 0; q < 4; q++) acc[i][j][q] = 0.f;

    int st = 0, sp = 2;
    for (int ch = 0; ch < 8; ch++) {
        CP_WAIT1;
        __syncthreads();
        if (ch + 2 < 8) {
            int k0 = (ch + 2) * 32;
#pragma unroll
            for (int u = 0; u < 4; u++) {
                int kq = wq4 + 2 * u;
                cp16(smU + PJ_WS + sp * 18432 + wm * 144 + kq * 16, wsrc + k0 + kq * 4);
            }
#pragma unroll
            for (int u = 0; u < 4; u++) {
                int nq = xn + 8 * u;
                cp16(smU + PJ_XS + sp * 17408 + xk * 544 + nq * 16, xb + (size_t)(k0 + xk) * Nn + nq * 4);
            }
        }
        CP_COMMIT;
        {
            const float* wb = (const float*)(sm + PJ_WS + st * 18432);
            const float* xs = (const float*)(sm + PJ_XS + st * 17408);
#pragma unroll
            for (int k8 = 0; k8 < 4; k8++) {
                uint32_t A[2][4];
#pragma unroll
                for (int mi = 0; mi < 2; mi++) {
                    const float* ap = wb + (mg * 32 + mi * 16 + (lane >> 2)) * 36 + k8 * 8 + (lane & 3);
                    A[mi][0] = __float_as_uint(ap[0]);
                    A[mi][2] = __float_as_uint(ap[4]);
                    A[mi][1] = __float_as_uint(ap[8 * 36]);
                    A[mi][3] = __float_as_uint(ap[8 * 36 + 4]);
                }
                const float* bp = xs + (k8 * 8 + (lane & 3)) * 136 + ng * 64 + (lane >> 2);
#pragma unroll
                for (int nb = 0; nb < 8; nb++) {
                    uint32_t b0 = __float_as_uint(bp[nb * 8]);
                    uint32_t b1 = __float_as_uint(bp[nb * 8 + 4 * 136]);
                    mma_tf32(acc[0][nb], A[0], b0, b1);
                    mma_tf32(acc[1][nb], A[1], b0, b1);
                }
            }
        }
        st = (st == 2) ? 0 : st + 1;
        sp = (sp == 2) ? 0 : sp + 1;
    }
    __syncthreads();

    float* Tf = (float*)sm;
#pragma unroll
    for (int mi = 0; mi < 2; mi++) {
        int m = mg * 32 + mi * 16 + (lane >> 2);
#pragma unroll
        for (int nb = 0; nb < 8; nb++) {
            int n = ng * 64 + nb * 8 + (lane & 3) * 2;
            float* a = acc[mi][nb];
            *(float2*)(Tf + (size_t)m * 132 + n)       = make_float2(a[0], a[1]);
            *(float2*)(Tf + (size_t)(m + 8) * 132 + n) = make_float2(a[2], a[3]);
        }
    }
    __syncthreads();
    float g = fminf(fmaxf(gamma[0], 0.f), 1.f);
    {
        int m = t >> 1, c = t & 1;
        int mglob = ytile * 128 + m;
        float bb = bo[mglob];
        size_t base = ((size_t)(b * Cc + mglob)) * Nn + n0 + c * 64;
#pragma unroll
        for (int u = 0; u < 16; u++) {
            float4 v = *(const float4*)(Tf + (size_t)m * 132 + c * 64 + u * 4);
            float4 xr = *(const float4*)(x + base + u * 4);
            float4 o;
            o.x = g * (v.x + bb) + xr.x;
            o.y = g * (v.y + bb) + xr.y;
            o.z = g * (v.z + bb) + xr.z;
            o.w = g * (v.w + bb) + xr.w;
            *(float4*)(out + base + u * 4) = o;
        }
    }
}

// ---------------- launcher ----------------
extern "C" void kernel_launch(void* const* d_in, const int* in_sizes, int n_in,
                              void* d_out, int out_size)
{
    const float* x     = (const float*)d_in[0];
    const float* Wq    = (const float*)d_in[1];
    const float* bq    = (const float*)d_in[2];
    const float* Wk    = (const float*)d_in[3];
    const float* bk    = (const float*)d_in[4];
    const float* Wv    = (const float*)d_in[5];
    const float* bv    = (const float*)d_in[6];
    const float* Wo    = (const float*)d_in[7];
    const float* bo    = (const float*)d_in[8];
    const float* gamma = (const float*)d_in[9];
    float* out = (float*)d_out;

    cudaFuncSetAttribute(proj_kernel,    cudaFuncAttributeMaxDynamicSharedMemorySize, PJ_BYTES);
    cudaFuncSetAttribute(outproj_kernel, cudaFuncAttributeMaxDynamicSharedMemorySize, PJ_BYTES);
    cudaFuncSetAttribute(attn_kernel,    cudaFuncAttributeMaxDynamicSharedMemorySize, AT_BYTES);

    proj_kernel   <<<dim3(Nn / 128, 3, Bb), 256, PJ_BYTES>>>(x, Wq, bq, Wk, bk, Wv, bv);
    attn_kernel   <<<dim3(Nn / BM, Bb), 512, AT_BYTES>>>();
    outproj_kernel<<<dim3(Nn / 128, 2, Bb), 256, PJ_BYTES>>>(x, Wo, bo, gamma, out);
}

// round 13
// speedup vs baseline: 1.4400x; 1.1366x over previous
#include <cuda_runtime.h>
#include <cuda_bf16.h>
#include <cstdint>

#define Bb 8
#define Cc 256
#define Nn 4096
#define Dd 16
#define BM 128
#define BN 64
#define NTILES (Nn / BN)

// ---------------- scratch ----------------
__device__ __nv_bfloat16 g_Qb[(size_t)Bb * Nn * Dd];   // [B,N,16] bf16, (q+bq)*0.25*log2e
__device__ __nv_bfloat16 g_Kb[(size_t)Bb * Dd * Nn];   // [B,16,N] bf16, k+bk
__device__ __nv_bfloat16 g_VT[(size_t)Bb * Nn * Cc];   // [B,N,C] bf16
__device__ __nv_bfloat16 g_OAb[(size_t)Bb * Cc * Nn];  // [B,C,N] bf16 attn out
__device__ __nv_bfloat16 g_Xb[(size_t)Bb * Cc * Nn];   // x in bf16
__device__ __nv_bfloat16 g_Wb[139264];                 // [Wq 16x256 | Wk 16x256 | Wv 256x256 | Wo 256x256]
#define WQ_OFF 0
#define WK_OFF 4096
#define WV_OFF 8192
#define WO_OFF 73728

// ---------------- helpers ----------------
static __device__ __forceinline__ uint32_t smem_u32(const void* p) {
    uint32_t a;
    asm("{ .reg .u64 t; cvta.to.shared.u64 t, %1; cvt.u32.u64 %0, t; }" : "=r"(a) : "l"(p));
    return a;
}
static __device__ __forceinline__ void ldsm_x4(uint32_t &r0, uint32_t &r1, uint32_t &r2, uint32_t &r3, uint32_t addr) {
    asm volatile("ldmatrix.sync.aligned.m8n8.x4.shared.b16 {%0,%1,%2,%3}, [%4];"
                 : "=r"(r0), "=r"(r1), "=r"(r2), "=r"(r3) : "r"(addr));
}
static __device__ __forceinline__ void ldsm_x4t(uint32_t &r0, uint32_t &r1, uint32_t &r2, uint32_t &r3, uint32_t addr) {
    asm volatile("ldmatrix.sync.aligned.m8n8.x4.trans.shared.b16 {%0,%1,%2,%3}, [%4];"
                 : "=r"(r0), "=r"(r1), "=r"(r2), "=r"(r3) : "r"(addr));
}
static __device__ __forceinline__ void mma16816(float* d, const uint32_t* a, uint32_t b0, uint32_t b1) {
    asm volatile("mma.sync.aligned.m16n8k16.row.col.f32.bf16.bf16.f32 "
                 "{%0,%1,%2,%3}, {%4,%5,%6,%7}, {%8,%9}, {%0,%1,%2,%3};"
                 : "+f"(d[0]), "+f"(d[1]), "+f"(d[2]), "+f"(d[3])
                 : "r"(a[0]), "r"(a[1]), "r"(a[2]), "r"(a[3]), "r"(b0), "r"(b1));
}
static __device__ __forceinline__ float ex2(float x) {
    float y; asm("ex2.approx.ftz.f32 %0, %1;" : "=f"(y) : "f"(x)); return y;
}
static __device__ __forceinline__ void sts32(uint32_t addr, uint32_t v) {
    asm volatile("st.shared.b32 [%0], %1;" :: "r"(addr), "r"(v));
}
static __device__ __forceinline__ void cp16(uint32_t dst, const void* src) {
    asm volatile("cp.async.cg.shared.global [%0], [%1], 16;" :: "r"(dst), "l"(src));
}
#define CP_COMMIT asm volatile("cp.async.commit_group;" ::: "memory")
#define CP_WAIT1  asm volatile("cp.async.wait_group 1;" ::: "memory")

#define QSCALE 0.36067376022224085f   // 0.25 * log2(e)
#define CLIP2  72.134752f             // 50 * log2(e)

// ================= convert x + weights to bf16 =================
__global__ __launch_bounds__(256) void cvt_kernel(
    const float* __restrict__ x,
    const float* __restrict__ Wq, const float* __restrict__ Wk,
    const float* __restrict__ Wv, const float* __restrict__ Wo)
{
    int i = blockIdx.x, t = threadIdx.x;
    if (i < 2048) {
        // x: 2,097,152 float4 total
        const float4* xs = (const float4*)x;
        uint2* xd = (uint2*)g_Xb;
#pragma unroll
        for (int j = 0; j < 4; j++) {
            int idx = i * 1024 + j * 256 + t;
            float4 v = xs[idx];
            __nv_bfloat162 p0 = __floats2bfloat162_rn(v.x, v.y);
            __nv_bfloat162 p1 = __floats2bfloat162_rn(v.z, v.w);
            uint2 u; u.x = *(uint32_t*)&p0; u.y = *(uint32_t*)&p1;
            xd[idx] = u;
        }
    } else {
        // weights: 34816 float4 total
        int idx4 = (i - 2048) * 256 + t;
        const float* src;
        if (idx4 < 1024)       src = Wq + idx4 * 4;
        else if (idx4 < 2048)  src = Wk + (idx4 - 1024) * 4;
        else if (idx4 < 18432) src = Wv + (idx4 - 2048) * 4;
        else                   src = Wo + (idx4 - 18432) * 4;
        float4 v = *(const float4*)src;
        __nv_bfloat162 p0 = __floats2bfloat162_rn(v.x, v.y);
        __nv_bfloat162 p1 = __floats2bfloat162_rn(v.z, v.w);
        uint2 u; u.x = *(uint32_t*)&p0; u.y = *(uint32_t*)&p1;
        ((uint2*)g_Wb)[idx4] = u;
    }
}

// ================= fused projection: V (+Q,K) via bf16 MMA, 3-stage ring =================
// smem: W 3 x [128][144B]=18432 | X 3 x [64][272B]=17408
#define PJ_WS 0
#define PJ_XS 55296
#define PJ_BYTES (55296 + 52224)
#define NCHUNK 4

__global__ __launch_bounds__(256, 2) void proj_kernel(
    const float* __restrict__ bq, const float* __restrict__ bk,
    const float* __restrict__ bv)
{
    extern __shared__ __align__(16) char sm[];
    uint32_t smU = smem_u32(sm);
    int t = threadIdx.x, wid = t >> 5, lane = t & 31;
    int mg = wid >> 1, ng = wid & 1;
    int n0 = blockIdx.x * 128, ytile = blockIdx.y, b = blockIdx.z;
    bool active = (ytile < 2) || (mg == 0);

    int wm = t >> 1, wq = t & 1;
    const __nv_bfloat16* wsrc;
    bool wvalid = true;
    if (ytile < 2) wsrc = g_Wb + WV_OFF + (ytile * 128 + wm) * Cc;
    else {
        if (wm < 16) wsrc = g_Wb + WQ_OFF + wm * Cc;
        else if (wm < 32) wsrc = g_Wb + WK_OFF + (wm - 16) * Cc;
        else { wsrc = g_Wb; wvalid = false; }
    }
    const __nv_bfloat16* xb = g_Xb + (size_t)b * Cc * Nn + n0;
    int xk = t >> 2, xn = t & 3;

    // prologue: chunks 0,1 (k0 = ch*64)
#pragma unroll
    for (int ch = 0; ch < 2; ch++) {
        int k0 = ch * 64;
        if (wvalid) {
#pragma unroll
            for (int u = 0; u < 4; u++)
                cp16(smU + PJ_WS + ch * 18432 + wm * 144 + (wq + 2 * u) * 16,
                     wsrc + k0 + (wq + 2 * u) * 8);
        }
#pragma unroll
        for (int u = 0; u < 4; u++)
            cp16(smU + PJ_XS + ch * 17408 + xk * 272 + (xn + 4 * u) * 16,
                 xb + (size_t)(k0 + xk) * Nn + (xn + 4 * u) * 8);
        CP_COMMIT;
    }

    float acc[2][8][4];
#pragma unroll
    for (int i = 0; i < 2; i++)
#pragma unroll
        for (int j = 0; j < 8; j++)
#pragma unroll
            for (int q = 0; q < 4; q++) acc[i][j][q] = 0.f;

    int st = 0, sp = 2;
    for (int ch = 0; ch < NCHUNK; ch++) {
        CP_WAIT1;
        __syncthreads();
        if (ch + 2 < NCHUNK) {
            int k0 = (ch + 2) * 64;
            if (wvalid) {
#pragma unroll
                for (int u = 0; u < 4; u++)
                    cp16(smU + PJ_WS + sp * 18432 + wm * 144 + (wq + 2 * u) * 16,
                         wsrc + k0 + (wq + 2 * u) * 8);
            }
#pragma unroll
            for (int u = 0; u < 4; u++)
                cp16(smU + PJ_XS + sp * 17408 + xk * 272 + (xn + 4 * u) * 16,
                     xb + (size_t)(k0 + xk) * Nn + (xn + 4 * u) * 8);
        }
        CP_COMMIT;
        if (active) {
            uint32_t wbU = smU + PJ_WS + st * 18432;
            uint32_t xsU = smU + PJ_XS + st * 17408;
#pragma unroll
            for (int kg = 0; kg < 4; kg++) {
                uint32_t A[2][4];
#pragma unroll
                for (int mi = 0; mi < 2; mi++)
                    ldsm_x4(A[mi][0], A[mi][1], A[mi][2], A[mi][3],
                            wbU + (mg * 32 + mi * 16 + (lane & 15)) * 144 +
                            kg * 32 + (lane >> 4) * 16);
#pragma unroll
                for (int nb2 = 0; nb2 < 4; nb2++) {
                    uint32_t b0, b1, b2, b3;
                    ldsm_x4t(b0, b1, b2, b3,
                             xsU + (kg * 16 + (lane & 15)) * 272 +
                             (ng * 64 + nb2 * 16 + (lane >> 4) * 8) * 2);
                    mma16816(acc[0][nb2 * 2],     A[0], b0, b1);
                    mma16816(acc[0][nb2 * 2 + 1], A[0], b2, b3);
                    mma16816(acc[1][nb2 * 2],     A[1], b0, b1);
                    mma16816(acc[1][nb2 * 2 + 1], A[1], b2, b3);
                }
            }
        }
        st = (st == 2) ? 0 : st + 1;
        sp = (sp == 2) ? 0 : sp + 1;
    }
    __syncthreads();

    if (ytile < 2) {
        __nv_bfloat16* Tb = (__nv_bfloat16*)(sm + PJ_XS);
#pragma unroll
        for (int mi = 0; mi < 2; mi++) {
            int m = mg * 32 + mi * 16 + (lane >> 2);
            float bv0 = bv[ytile * 128 + m];
            float bv1 = bv[ytile * 128 + m + 8];
#pragma unroll
            for (int nb = 0; nb < 8; nb++) {
                int n = ng * 64 + nb * 8 + (lane & 3) * 2;
                float* a = acc[mi][nb];
                Tb[(size_t)n * 136 + m]           = __float2bfloat16(a[0] + bv0);
                Tb[(size_t)(n + 1) * 136 + m]     = __float2bfloat16(a[1] + bv0);
                Tb[(size_t)n * 136 + m + 8]       = __float2bfloat16(a[2] + bv1);
                Tb[(size_t)(n + 1) * 136 + m + 8] = __float2bfloat16(a[3] + bv1);
            }
        }
        __syncthreads();
        int n = t >> 1, c = t & 1;
        const uint4* src = (const uint4*)((const char*)Tb + n * 272 + c * 128);
        uint4* dst = (uint4*)((char*)(g_VT + ((size_t)(b * Nn + n0 + n)) * Cc + ytile * 128) + c * 128);
#pragma unroll
        for (int u = 0; u < 8; u++) dst[u] = src[u];
    } else {
        __nv_bfloat16* Qt = (__nv_bfloat16*)(sm + PJ_XS);            // [128][24]
        __nv_bfloat16* Kt = (__nv_bfloat16*)(sm + PJ_XS + 6144);     // [16][136]
        if (mg == 0) {
            {
                int d = lane >> 2;
                float b0 = bq[d], b1 = bq[d + 8];
#pragma unroll
                for (int nb = 0; nb < 8; nb++) {
                    int n = ng * 64 + nb * 8 + (lane & 3) * 2;
                    float* a = acc[0][nb];
                    Qt[(size_t)n * 24 + d]           = __float2bfloat16((a[0] + b0) * QSCALE);
                    Qt[(size_t)(n + 1) * 24 + d]     = __float2bfloat16((a[1] + b0) * QSCALE);
                    Qt[(size_t)n * 24 + d + 8]       = __float2bfloat16((a[2] + b1) * QSCALE);
                    Qt[(size_t)(n + 1) * 24 + d + 8] = __float2bfloat16((a[3] + b1) * QSCALE);
                }
            }
            {
                int d = lane >> 2;
                float b0 = bk[d], b1 = bk[d + 8];
#pragma unroll
                for (int nb = 0; nb < 8; nb++) {
                    int n = ng * 64 + nb * 8 + (lane & 3) * 2;
                    float* a = acc[1][nb];
                    Kt[(size_t)d * 136 + n]           = __float2bfloat16(a[0] + b0);
                    Kt[(size_t)d * 136 + n + 1]       = __float2bfloat16(a[1] + b0);
                    Kt[(size_t)(d + 8) * 136 + n]     = __float2bfloat16(a[2] + b1);
                    Kt[(size_t)(d + 8) * 136 + n + 1] = __float2bfloat16(a[3] + b1);
                }
            }
        }
        __syncthreads();
        {
            int n = t >> 1, c = t & 1;
            const uint4* src = (const uint4*)((const char*)Qt + n * 48 + c * 16);
            uint4* dst = (uint4*)((char*)(g_Qb + ((size_t)(b * Nn + n0 + n)) * Dd) + c * 16);
            dst[0] = src[0];
        }
        {
            int d = t >> 4, c = t & 15;
            const uint4* src = (const uint4*)((const char*)Kt + d * 272 + c * 16);
            uint4* dst = (uint4*)((char*)(g_Kb + ((size_t)(b * Dd + d)) * Nn + n0) + c * 16);
            dst[0] = src[0];
        }
    }
}

// ================= fused attention: pipelined split-role FA2 (R10 structure) =================
// smem: VS 4x33792 | KS 4x2304 @135168 | QS 6144 @144384 | PS 2x18432 @150528 | RS 1024 @187392
#define AT_VS 0
#define AT_KS 135168
#define AT_QS 144384
#define AT_PS 150528
#define AT_RS 187392
#define AT_BYTES 188416

__global__ __launch_bounds__(512, 1) void attn_kernel()
{
    extern __shared__ __align__(16) char sm[];
    uint32_t smU = smem_u32(sm);
    int t = threadIdx.x, b = blockIdx.y, m0 = blockIdx.x * BM;
    int wid = t >> 5, lane = t & 31;
    int mg = wid >> 1, jg = wid & 1;    // QK role: m16 x j32
    int mg2 = wid >> 2, eg = wid & 3;   // PV role: m32 x e64

    const char* vb = (const char*)(g_VT + (size_t)b * Nn * Cc);
    const char* kb = (const char*)(g_Kb + (size_t)b * Dd * Nn);
    const char* qb = (const char*)(g_Qb + ((size_t)b * Nn + m0) * Dd);

    int vj = t >> 3, vc = t & 7;
    int kd = t >> 3, kc = t & 7;

#pragma unroll
    for (int st = 0; st < 2; st++) {
        int n0 = st * BN;
        uint32_t dst = smU + AT_VS + st * 33792 + vj * 528 + vc * 16;
        const char* src = vb + ((size_t)(n0 + vj)) * 512 + vc * 16;
#pragma unroll
        for (int u = 0; u < 4; u++) cp16(dst + u * 128, src + u * 128);
        if (t < 128) cp16(smU + AT_KS + st * 2304 + kd * 144 + kc * 16,
                          kb + (size_t)kd * (Nn * 2) + n0 * 2 + kc * 16);
        if (st == 0 && t < 256) {
            int m = t >> 1, c = t & 1;
            cp16(smU + AT_QS + m * 48 + c * 16, qb + m * 32 + c * 16);
        }
        CP_COMMIT;
    }

    float acc[2][8][4];
#pragma unroll
    for (int i = 0; i < 2; i++)
#pragma unroll
        for (int j = 0; j < 8; j++)
#pragma unroll
            for (int q = 0; q < 4; q++) acc[i][j][q] = 0.f;

    uint32_t qa[4];
    float rs0 = 0.f, rs1 = 0.f;

    uint32_t ps_st0 = smU + AT_PS + (mg * 16 + (lane >> 2)) * 144 + (jg * 32 + (lane & 3) * 2) * 2;
    uint32_t ps_ld0 = smU + AT_PS +
        (uint32_t)(mg2 * 32 + (lane & 7) + ((lane >> 3) & 1) * 8) * 144 + (lane >> 4) * 16;

    // ---- peeled: QK(0) -> Pbuf0 ----
    CP_WAIT1;
    __syncthreads();
    {
        uint32_t qaddr = smU + AT_QS +
            (mg * 16 + (lane & 7) + ((lane >> 3) & 1) * 8) * 48 + (lane >> 4) * 16;
        ldsm_x4(qa[0], qa[1], qa[2], qa[3], qaddr);
    }
    {
        uint32_t ksb = smU + AT_KS;
        uint32_t pst = ps_st0;
#pragma unroll
        for (int nb2 = 0; nb2 < 2; nb2++) {
            float c[2][4];
#pragma unroll
            for (int h = 0; h < 2; h++)
#pragma unroll
                for (int j = 0; j < 4; j++) c[h][j] = 0.f;
            uint32_t b0, b1, b2, b3;
            uint32_t ka = ksb + (lane & 15) * 144 + (jg * 32 + nb2 * 16 + (lane >> 4) * 8) * 2;
            ldsm_x4t(b0, b1, b2, b3, ka);
            mma16816(c[0], qa, b0, b1);
            mma16816(c[1], qa, b2, b3);
#pragma unroll
            for (int h = 0; h < 2; h++) {
                float e0 = ex2(fminf(fmaxf(c[h][0], -CLIP2), CLIP2));
                float e1 = ex2(fminf(fmaxf(c[h][1], -CLIP2), CLIP2));
                float e2 = ex2(fminf(fmaxf(c[h][2], -CLIP2), CLIP2));
                float e3 = ex2(fminf(fmaxf(c[h][3], -CLIP2), CLIP2));
                rs0 += e0 + e1;
                rs1 += e2 + e3;
                __nv_bfloat162 lo = __floats2bfloat162_rn(e0, e1);
                __nv_bfloat162 hi = __floats2bfloat162_rn(e2, e3);
                sts32(pst + nb2 * 32 + h * 16, *(uint32_t*)&lo);
                sts32(pst + nb2 * 32 + h * 16 + 8 * 144, *(uint32_t*)&hi);
            }
        }
    }

    for (int it = 0; it < NTILES; it++) {
        if (it + 2 < NTILES) {
            int n0 = (it + 2) * BN;
            int sp = (it + 2) & 3;
            uint32_t dst = smU + AT_VS + sp * 33792 + vj * 528 + vc * 16;
            const char* src = vb + ((size_t)(n0 + vj)) * 512 + vc * 16;
#pragma unroll
            for (int u = 0; u < 4; u++) cp16(dst + u * 128, src + u * 128);
            if (t < 128) cp16(smU + AT_KS + sp * 2304 + kd * 144 + kc * 16,
                              kb + (size_t)kd * (Nn * 2) + n0 * 2 + kc * 16);
        }
        CP_COMMIT;
        CP_WAIT1;
        __syncthreads();

        if (it + 1 < NTILES) {
            uint32_t ksb = smU + AT_KS + ((it + 1) & 3) * 2304;
            uint32_t pst = ps_st0 + ((it + 1) & 1) * 18432;
#pragma unroll
            for (int nb2 = 0; nb2 < 2; nb2++) {
                float c[2][4];
#pragma unroll
                for (int h = 0; h < 2; h++)
#pragma unroll
                    for (int j = 0; j < 4; j++) c[h][j] = 0.f;
                uint32_t b0, b1, b2, b3;
                uint32_t ka = ksb + (lane & 15) * 144 + (jg * 32 + nb2 * 16 + (lane >> 4) * 8) * 2;
                ldsm_x4t(b0, b1, b2, b3, ka);
                mma16816(c[0], qa, b0, b1);
                mma16816(c[1], qa, b2, b3);
#pragma unroll
                for (int h = 0; h < 2; h++) {
                    float e0 = ex2(fminf(fmaxf(c[h][0], -CLIP2), CLIP2));
                    float e1 = ex2(fminf(fmaxf(c[h][1], -CLIP2), CLIP2));
                    float e2 = ex2(fminf(fmaxf(c[h][2], -CLIP2), CLIP2));
                    float e3 = ex2(fminf(fmaxf(c[h][3], -CLIP2), CLIP2));
                    rs0 += e0 + e1;
                    rs1 += e2 + e3;
                    __nv_bfloat162 lo = __floats2bfloat162_rn(e0, e1);
                    __nv_bfloat162 hi = __floats2bfloat162_rn(e2, e3);
                    sts32(pst + nb2 * 32 + h * 16, *(uint32_t*)&lo);
                    sts32(pst + nb2 * 32 + h * 16 + 8 * 144, *(uint32_t*)&hi);
                }
            }
        }

        {
            uint32_t vsb = smU + AT_VS + (it & 3) * 33792;
            uint32_t pld = ps_ld0 + (it & 1) * 18432;
#pragma unroll
            for (int kg = 0; kg < 4; kg++) {
                uint32_t pA[2][4];
#pragma unroll
                for (int mi = 0; mi < 2; mi++)
                    ldsm_x4(pA[mi][0], pA[mi][1], pA[mi][2], pA[mi][3],
                            pld + mi * (16 * 144) + kg * 32);
#pragma unroll
                for (int eb2 = 0; eb2 < 4; eb2++) {
                    uint32_t b0, b1, b2, b3;
                    uint32_t va = vsb + (kg * 16 + (lane & 15)) * 528 +
                                  (eg * 64 + eb2 * 16 + (lane >> 4) * 8) * 2;
                    ldsm_x4t(b0, b1, b2, b3, va);
                    mma16816(acc[0][eb2 * 2],     pA[0], b0, b1);
                    mma16816(acc[0][eb2 * 2 + 1], pA[0], b2, b3);
                    mma16816(acc[1][eb2 * 2],     pA[1], b0, b1);
                    mma16816(acc[1][eb2 * 2 + 1], pA[1], b2, b3);
                }
            }
        }
    }

    // rowsum reduce + stash
    rs0 += __shfl_xor_sync(0xffffffffu, rs0, 1);
    rs0 += __shfl_xor_sync(0xffffffffu, rs0, 2);
    rs1 += __shfl_xor_sync(0xffffffffu, rs1, 1);
    rs1 += __shfl_xor_sync(0xffffffffu, rs1, 2);
    float* rs_s = (float*)(sm + AT_RS);
    if ((lane & 3) == 0) {
        rs_s[jg * 128 + mg * 16 + (lane >> 2)]     = rs0;
        rs_s[jg * 128 + mg * 16 + (lane >> 2) + 8] = rs1;
    }

    // epilogue: normalize -> smem [e128 x 132] fp32 -> coalesced bf16 stores (2 halves)
    float* Tf = (float*)sm;
    __nv_bfloat16* ob = g_OAb + (size_t)b * Cc * Nn + m0;
    int r = lane >> 2, q = lane & 3;
#pragma unroll
    for (int h = 0; h < 2; h++) {
        __syncthreads();
        if ((eg >> 1) == h) {
            int ebase = (eg & 1) * 64;
#pragma unroll
            for (int mi = 0; mi < 2; mi++) {
                int ml = mg2 * 32 + mi * 16 + r;
                float inv0 = 1.f / (rs_s[ml]     + rs_s[128 + ml]);
                float inv1 = 1.f / (rs_s[ml + 8] + rs_s[128 + ml + 8]);
#pragma unroll
                for (int nb = 0; nb < 8; nb++) {
                    int e = ebase + nb * 8 + 2 * q;
                    float* a = acc[mi][nb];
                    Tf[(size_t)e * 132 + ml]           = a[0] * inv0;
                    Tf[(size_t)(e + 1) * 132 + ml]     = a[1] * inv0;
                    Tf[(size_t)e * 132 + ml + 8]       = a[2] * inv1;
                    Tf[(size_t)(e + 1) * 132 + ml + 8] = a[3] * inv1;
                }
            }
        }
        __syncthreads();
#pragma unroll
        for (int rr = 0; rr < 8; rr++) {
            int e = wid * 8 + rr;
            const float* srcr = Tf + (size_t)e * 132;
            __nv_bfloat16* dstr = ob + (size_t)(h * 128 + e) * Nn;
#pragma unroll
            for (int c = 0; c < 2; c++) {
                float v0 = srcr[c * 64 + lane];
                float v1 = srcr[c * 64 + 32 + lane];
                dstr[c * 64 + lane]      = __float2bfloat16(v0);
                dstr[c * 64 + 32 + lane] = __float2bfloat16(v1);
            }
        }
    }
}

// ================= output projection via bf16 MMA + residual =================
__global__ __launch_bounds__(256, 2) void outproj_kernel(
    const float* __restrict__ x,
    const float* __restrict__ bo,
    const float* __restrict__ gamma, float* __restrict__ out)
{
    extern __shared__ __align__(16) char sm[];
    uint32_t smU = smem_u32(sm);
    int t = threadIdx.x, wid = t >> 5, lane = t & 31;
    int mg = wid >> 1, ng = wid & 1;
    int n0 = blockIdx.x * 128, ytile = blockIdx.y, b = blockIdx.z;

    int wm = t >> 1, wq = t & 1;
    const __nv_bfloat16* wsrc = g_Wb + WO_OFF + (ytile * 128 + wm) * Cc;
    const __nv_bfloat16* xb = g_OAb + (size_t)b * Cc * Nn + n0;
    int xk = t >> 2, xn = t & 3;

#pragma unroll
    for (int ch = 0; ch < 2; ch++) {
        int k0 = ch * 64;
#pragma unroll
        for (int u = 0; u < 4; u++)
            cp16(smU + PJ_WS + ch * 18432 + wm * 144 + (wq + 2 * u) * 16,
                 wsrc + k0 + (wq + 2 * u) * 8);
#pragma unroll
        for (int u = 0; u < 4; u++)
            cp16(smU + PJ_XS + ch * 17408 + xk * 272 + (xn + 4 * u) * 16,
                 xb + (size_t)(k0 + xk) * Nn + (xn + 4 * u) * 8);
        CP_COMMIT;
    }

    float acc[2][8][4];
#pragma unroll
    for (int i = 0; i < 2; i++)
#pragma unroll
        for (int j = 0; j < 8; j++)
#pragma unroll
            for (int q = 0; q < 4; q++) acc[i][j][q] = 0.f;

    int st = 0, sp = 2;
    for (int ch = 0; ch < NCHUNK; ch++) {
        CP_WAIT1;
        __syncthreads();
        if (ch + 2 < NCHUNK) {
            int k0 = (ch + 2) * 64;
#pragma unroll
            for (int u = 0; u < 4; u++)
                cp16(smU + PJ_WS + sp * 18432 + wm * 144 + (wq + 2 * u) * 16,
                     wsrc + k0 + (wq + 2 * u) * 8);
#pragma unroll
            for (int u = 0; u < 4; u++)
                cp16(smU + PJ_XS + sp * 17408 + xk * 272 + (xn + 4 * u) * 16,
                     xb + (size_t)(k0 + xk) * Nn + (xn + 4 * u) * 8);
        }
        CP_COMMIT;
        {
            uint32_t wbU = smU + PJ_WS + st * 18432;
            uint32_t xsU = smU + PJ_XS + st * 17408;
#pragma unroll
            for (int kg = 0; kg < 4; kg++) {
                uint32_t A[2][4];
#pragma unroll
                for (int mi = 0; mi < 2; mi++)
                    ldsm_x4(A[mi][0], A[mi][1], A[mi][2], A[mi][3],
                            wbU + (mg * 32 + mi * 16 + (lane & 15)) * 144 +
                            kg * 32 + (lane >> 4) * 16);
#pragma unroll
                for (int nb2 = 0; nb2 < 4; nb2++) {
                    uint32_t b0, b1, b2, b3;
                    ldsm_x4t(b0, b1, b2, b3,
                             xsU + (kg * 16 + (lane & 15)) * 272 +
                             (ng * 64 + nb2 * 16 + (lane >> 4) * 8) * 2);
                    mma16816(acc[0][nb2 * 2],     A[0], b0, b1);
                    mma16816(acc[0][nb2 * 2 + 1], A[0], b2, b3);
                    mma16816(acc[1][nb2 * 2],     A[1], b0, b1);
                    mma16816(acc[1][nb2 * 2 + 1], A[1], b2, b3);
                }
            }
        }
        st = (st == 2) ? 0 : st + 1;
        sp = (sp == 2) ? 0 : sp + 1;
    }
    __syncthreads();

    float* Tf = (float*)sm;
#pragma unroll
    for (int mi = 0; mi < 2; mi++) {
        int m = mg * 32 + mi * 16 + (lane >> 2);
#pragma unroll
        for (int nb = 0; nb < 8; nb++) {
            int n = ng * 64 + nb * 8 + (lane & 3) * 2;
            float* a = acc[mi][nb];
            *(float2*)(Tf + (size_t)m * 132 + n)       = make_float2(a[0], a[1]);
            *(float2*)(Tf + (size_t)(m + 8) * 132 + n) = make_float2(a[2], a[3]);
        }
    }
    __syncthreads();
    float g = fminf(fmaxf(gamma[0], 0.f), 1.f);
    {
        int m = t >> 1, c = t & 1;
        int mglob = ytile * 128 + m;
        float bb = bo[mglob];
        size_t base = ((size_t)(b * Cc + mglob)) * Nn + n0 + c * 64;
#pragma unroll
        for (int u = 0; u < 16; u++) {
            float4 v = *(const float4*)(Tf + (size_t)m * 132 + c * 64 + u * 4);
            float4 xr = *(const float4*)(x + base + u * 4);
            float4 o;
            o.x = g * (v.x + bb) + xr.x;
            o.y = g * (v.y + bb) + xr.y;
            o.z = g * (v.z + bb) + xr.z;
            o.w = g * (v.w + bb) + xr.w;
            *(float4*)(out + base + u * 4) = o;
        }
    }
}

// ---------------- launcher ----------------
extern "C" void kernel_launch(void* const* d_in, const int* in_sizes, int n_in,
                              void* d_out, int out_size)
{
    const float* x     = (const float*)d_in[0];
    const float* Wq    = (const float*)d_in[1];
    const float* bq    = (const float*)d_in[2];
    const float* Wk    = (const float*)d_in[3];
    const float* bk    = (const float*)d_in[4];
    const float* Wv    = (const float*)d_in[5];
    const float* bv    = (const float*)d_in[6];
    const float* Wo    = (const float*)d_in[7];
    const float* bo    = (const float*)d_in[8];
    const float* gamma = (const float*)d_in[9];
    float* out = (float*)d_out;

    cudaFuncSetAttribute(proj_kernel,    cudaFuncAttributeMaxDynamicSharedMemorySize, PJ_BYTES);
    cudaFuncSetAttribute(outproj_kernel, cudaFuncAttributeMaxDynamicSharedMemorySize, PJ_BYTES);
    cudaFuncSetAttribute(attn_kernel,    cudaFuncAttributeMaxDynamicSharedMemorySize, AT_BYTES);

    cvt_kernel    <<<2184, 256>>>(x, Wq, Wk, Wv, Wo);
    proj_kernel   <<<dim3(Nn / 128, 3, Bb), 256, PJ_BYTES>>>(bq, bk, bv);
    attn_kernel   <<<dim3(Nn / BM, Bb), 512, AT_BYTES>>>();
    outproj_kernel<<<dim3(Nn / 128, 2, Bb), 256, PJ_BYTES>>>(x, bo, gamma, out);
}

// round 14
// speedup vs baseline: 1.4803x; 1.0280x over previous
#include <cuda_runtime.h>
#include <cuda_bf16.h>
#include <cstdint>

#define Bb 8
#define Cc 256
#define Nn 4096
#define Dd 16
#define BM 128
#define BN 64
#define NTILES (Nn / BN)

// ---------------- scratch ----------------
__device__ __nv_bfloat16 g_Qb[(size_t)Bb * Nn * Dd];   // [B,N,16] bf16, (q+bq)*0.25*log2e
__device__ __nv_bfloat16 g_Kb[(size_t)Bb * Dd * Nn];   // [B,16,N] bf16, k+bk
__device__ __nv_bfloat16 g_VT[(size_t)Bb * Nn * Cc];   // [B,N,C] bf16
__device__ __nv_bfloat16 g_OAb[(size_t)Bb * Cc * Nn];  // [B,C,N] bf16 attn out
__device__ __nv_bfloat16 g_Xb[(size_t)Bb * Cc * Nn];   // x in bf16
__device__ __nv_bfloat16 g_Wb[139264];                 // [Wq | Wk | Wv | Wo]
#define WQ_OFF 0
#define WK_OFF 4096
#define WV_OFF 8192
#define WO_OFF 73728

// ---------------- helpers ----------------
static __device__ __forceinline__ uint32_t smem_u32(const void* p) {
    uint32_t a;
    asm("{ .reg .u64 t; cvta.to.shared.u64 t, %1; cvt.u32.u64 %0, t; }" : "=r"(a) : "l"(p));
    return a;
}
static __device__ __forceinline__ void ldsm_x4(uint32_t &r0, uint32_t &r1, uint32_t &r2, uint32_t &r3, uint32_t addr) {
    asm volatile("ldmatrix.sync.aligned.m8n8.x4.shared.b16 {%0,%1,%2,%3}, [%4];"
                 : "=r"(r0), "=r"(r1), "=r"(r2), "=r"(r3) : "r"(addr));
}
static __device__ __forceinline__ void ldsm_x4t(uint32_t &r0, uint32_t &r1, uint32_t &r2, uint32_t &r3, uint32_t addr) {
    asm volatile("ldmatrix.sync.aligned.m8n8.x4.trans.shared.b16 {%0,%1,%2,%3}, [%4];"
                 : "=r"(r0), "=r"(r1), "=r"(r2), "=r"(r3) : "r"(addr));
}
static __device__ __forceinline__ void mma16816(float* d, const uint32_t* a, uint32_t b0, uint32_t b1) {
    asm volatile("mma.sync.aligned.m16n8k16.row.col.f32.bf16.bf16.f32 "
                 "{%0,%1,%2,%3}, {%4,%5,%6,%7}, {%8,%9}, {%0,%1,%2,%3};"
                 : "+f"(d[0]), "+f"(d[1]), "+f"(d[2]), "+f"(d[3])
                 : "r"(a[0]), "r"(a[1]), "r"(a[2]), "r"(a[3]), "r"(b0), "r"(b1));
}
static __device__ __forceinline__ float ex2(float x) {
    float y; asm("ex2.approx.ftz.f32 %0, %1;" : "=f"(y) : "f"(x)); return y;
}
static __device__ __forceinline__ void sts32(uint32_t addr, uint32_t v) {
    asm volatile("st.shared.b32 [%0], %1;" :: "r"(addr), "r"(v));
}
static __device__ __forceinline__ void cp16(uint32_t dst, const void* src) {
    asm volatile("cp.async.cg.shared.global [%0], [%1], 16;" :: "r"(dst), "l"(src));
}
#define CP_COMMIT asm volatile("cp.async.commit_group;" ::: "memory")
#define CP_WAIT0  asm volatile("cp.async.wait_group 0;" ::: "memory")
#define CP_WAIT1  asm volatile("cp.async.wait_group 1;" ::: "memory")

#define QSCALE 0.36067376022224085f   // 0.25 * log2(e)
#define CLIP2  72.134752f             // 50 * log2(e)

// ================= convert x + weights to bf16 =================
__global__ __launch_bounds__(256) void cvt_kernel(
    const float* __restrict__ x,
    const float* __restrict__ Wq, const float* __restrict__ Wk,
    const float* __restrict__ Wv, const float* __restrict__ Wo)
{
    int i = blockIdx.x, t = threadIdx.x;
    if (i < 2048) {
        const float4* xs = (const float4*)x;
        uint2* xd = (uint2*)g_Xb;
#pragma unroll
        for (int j = 0; j < 4; j++) {
            int idx = i * 1024 + j * 256 + t;
            float4 v = xs[idx];
            __nv_bfloat162 p0 = __floats2bfloat162_rn(v.x, v.y);
            __nv_bfloat162 p1 = __floats2bfloat162_rn(v.z, v.w);
            uint2 u; u.x = *(uint32_t*)&p0; u.y = *(uint32_t*)&p1;
            xd[idx] = u;
        }
    } else {
        int idx4 = (i - 2048) * 256 + t;
        const float* src;
        if (idx4 < 1024)       src = Wq + idx4 * 4;
        else if (idx4 < 2048)  src = Wk + (idx4 - 1024) * 4;
        else if (idx4 < 18432) src = Wv + (idx4 - 2048) * 4;
        else                   src = Wo + (idx4 - 18432) * 4;
        float4 v = *(const float4*)src;
        __nv_bfloat162 p0 = __floats2bfloat162_rn(v.x, v.y);
        __nv_bfloat162 p1 = __floats2bfloat162_rn(v.z, v.w);
        uint2 u; u.x = *(uint32_t*)&p0; u.y = *(uint32_t*)&p1;
        ((uint2*)g_Wb)[idx4] = u;
    }
}

// ================= fused projection: V (+Q,K) via bf16 MMA, 3-stage ring =================
#define PJ_WS 0
#define PJ_XS 55296
#define PJ_BYTES (55296 + 52224)
#define NCHUNK 4

__global__ __launch_bounds__(256, 2) void proj_kernel(
    const float* __restrict__ bq, const float* __restrict__ bk,
    const float* __restrict__ bv)
{
    extern __shared__ __align__(16) char sm[];
    uint32_t smU = smem_u32(sm);
    int t = threadIdx.x, wid = t >> 5, lane = t & 31;
    int mg = wid >> 1, ng = wid & 1;
    int n0 = blockIdx.x * 128, ytile = blockIdx.y, b = blockIdx.z;
    bool active = (ytile < 2) || (mg == 0);

    int wm = t >> 1, wq = t & 1;
    const __nv_bfloat16* wsrc;
    bool wvalid = true;
    if (ytile < 2) wsrc = g_Wb + WV_OFF + (ytile * 128 + wm) * Cc;
    else {
        if (wm < 16) wsrc = g_Wb + WQ_OFF + wm * Cc;
        else if (wm < 32) wsrc = g_Wb + WK_OFF + (wm - 16) * Cc;
        else { wsrc = g_Wb; wvalid = false; }
    }
    const __nv_bfloat16* xb = g_Xb + (size_t)b * Cc * Nn + n0;
    int xk = t >> 2, xn = t & 3;

#pragma unroll
    for (int ch = 0; ch < 2; ch++) {
        int k0 = ch * 64;
        if (wvalid) {
#pragma unroll
            for (int u = 0; u < 4; u++)
                cp16(smU + PJ_WS + ch * 18432 + wm * 144 + (wq + 2 * u) * 16,
                     wsrc + k0 + (wq + 2 * u) * 8);
        }
#pragma unroll
        for (int u = 0; u < 4; u++)
            cp16(smU + PJ_XS + ch * 17408 + xk * 272 + (xn + 4 * u) * 16,
                 xb + (size_t)(k0 + xk) * Nn + (xn + 4 * u) * 8);
        CP_COMMIT;
    }

    float acc[2][8][4];
#pragma unroll
    for (int i = 0; i < 2; i++)
#pragma unroll
        for (int j = 0; j < 8; j++)
#pragma unroll
            for (int q = 0; q < 4; q++) acc[i][j][q] = 0.f;

    int st = 0, sp = 2;
    for (int ch = 0; ch < NCHUNK; ch++) {
        CP_WAIT1;
        __syncthreads();
        if (ch + 2 < NCHUNK) {
            int k0 = (ch + 2) * 64;
            if (wvalid) {
#pragma unroll
                for (int u = 0; u < 4; u++)
                    cp16(smU + PJ_WS + sp * 18432 + wm * 144 + (wq + 2 * u) * 16,
                         wsrc + k0 + (wq + 2 * u) * 8);
            }
#pragma unroll
            for (int u = 0; u < 4; u++)
                cp16(smU + PJ_XS + sp * 17408 + xk * 272 + (xn + 4 * u) * 16,
                     xb + (size_t)(k0 + xk) * Nn + (xn + 4 * u) * 8);
        }
        CP_COMMIT;
        if (active) {
            uint32_t wbU = smU + PJ_WS + st * 18432;
            uint32_t xsU = smU + PJ_XS + st * 17408;
#pragma unroll
            for (int kg = 0; kg < 4; kg++) {
                uint32_t A[2][4];
#pragma unroll
                for (int mi = 0; mi < 2; mi++)
                    ldsm_x4(A[mi][0], A[mi][1], A[mi][2], A[mi][3],
                            wbU + (mg * 32 + mi * 16 + (lane & 15)) * 144 +
                            kg * 32 + (lane >> 4) * 16);
#pragma unroll
                for (int nb2 = 0; nb2 < 4; nb2++) {
                    uint32_t b0, b1, b2, b3;
                    ldsm_x4t(b0, b1, b2, b3,
                             xsU + (kg * 16 + (lane & 15)) * 272 +
                             (ng * 64 + nb2 * 16 + (lane >> 4) * 8) * 2);
                    mma16816(acc[0][nb2 * 2],     A[0], b0, b1);
                    mma16816(acc[0][nb2 * 2 + 1], A[0], b2, b3);
                    mma16816(acc[1][nb2 * 2],     A[1], b0, b1);
                    mma16816(acc[1][nb2 * 2 + 1], A[1], b2, b3);
                }
            }
        }
        st = (st == 2) ? 0 : st + 1;
        sp = (sp == 2) ? 0 : sp + 1;
    }
    __syncthreads();

    if (ytile < 2) {
        __nv_bfloat16* Tb = (__nv_bfloat16*)(sm + PJ_XS);
#pragma unroll
        for (int mi = 0; mi < 2; mi++) {
            int m = mg * 32 + mi * 16 + (lane >> 2);
            float bv0 = bv[ytile * 128 + m];
            float bv1 = bv[ytile * 128 + m + 8];
#pragma unroll
            for (int nb = 0; nb < 8; nb++) {
                int n = ng * 64 + nb * 8 + (lane & 3) * 2;
                float* a = acc[mi][nb];
                Tb[(size_t)n * 136 + m]           = __float2bfloat16(a[0] + bv0);
                Tb[(size_t)(n + 1) * 136 + m]     = __float2bfloat16(a[1] + bv0);
                Tb[(size_t)n * 136 + m + 8]       = __float2bfloat16(a[2] + bv1);
                Tb[(size_t)(n + 1) * 136 + m + 8] = __float2bfloat16(a[3] + bv1);
            }
        }
        __syncthreads();
        int n = t >> 1, c = t & 1;
        const uint4* src = (const uint4*)((const char*)Tb + n * 272 + c * 128);
        uint4* dst = (uint4*)((char*)(g_VT + ((size_t)(b * Nn + n0 + n)) * Cc + ytile * 128) + c * 128);
#pragma unroll
        for (int u = 0; u < 8; u++) dst[u] = src[u];
    } else {
        __nv_bfloat16* Qt = (__nv_bfloat16*)(sm + PJ_XS);            // [128][24]
        __nv_bfloat16* Kt = (__nv_bfloat16*)(sm + PJ_XS + 6144);     // [16][136]
        if (mg == 0) {
            {
                int d = lane >> 2;
                float b0 = bq[d], b1 = bq[d + 8];
#pragma unroll
                for (int nb = 0; nb < 8; nb++) {
                    int n = ng * 64 + nb * 8 + (lane & 3) * 2;
                    float* a = acc[0][nb];
                    Qt[(size_t)n * 24 + d]           = __float2bfloat16((a[0] + b0) * QSCALE);
                    Qt[(size_t)(n + 1) * 24 + d]     = __float2bfloat16((a[1] + b0) * QSCALE);
                    Qt[(size_t)n * 24 + d + 8]       = __float2bfloat16((a[2] + b1) * QSCALE);
                    Qt[(size_t)(n + 1) * 24 + d + 8] = __float2bfloat16((a[3] + b1) * QSCALE);
                }
            }
            {
                int d = lane >> 2;
                float b0 = bk[d], b1 = bk[d + 8];
#pragma unroll
                for (int nb = 0; nb < 8; nb++) {
                    int n = ng * 64 + nb * 8 + (lane & 3) * 2;
                    float* a = acc[1][nb];
                    Kt[(size_t)d * 136 + n]           = __float2bfloat16(a[0] + b0);
                    Kt[(size_t)d * 136 + n + 1]       = __float2bfloat16(a[1] + b0);
                    Kt[(size_t)(d + 8) * 136 + n]     = __float2bfloat16(a[2] + b1);
                    Kt[(size_t)(d + 8) * 136 + n + 1] = __float2bfloat16(a[3] + b1);
                }
            }
        }
        __syncthreads();
        {
            int n = t >> 1, c = t & 1;
            const uint4* src = (const uint4*)((const char*)Qt + n * 48 + c * 16);
            uint4* dst = (uint4*)((char*)(g_Qb + ((size_t)(b * Nn + n0 + n)) * Dd) + c * 16);
            dst[0] = src[0];
        }
        {
            int d = t >> 4, c = t & 15;
            const uint4* src = (const uint4*)((const char*)Kt + d * 272 + c * 16);
            uint4* dst = (uint4*)((char*)(g_Kb + ((size_t)(b * Dd + d)) * Nn + n0) + c * 16);
            dst[0] = src[0];
        }
    }
}

// ================= fused attention: pipelined split-role FA2 =================
#define AT_VS 0
#define AT_KS 135168
#define AT_QS 144384
#define AT_PS 150528
#define AT_RS 187392
#define AT_BYTES 188416

__global__ __launch_bounds__(512, 1) void attn_kernel()
{
    extern __shared__ __align__(16) char sm[];
    uint32_t smU = smem_u32(sm);
    int t = threadIdx.x, b = blockIdx.y, m0 = blockIdx.x * BM;
    int wid = t >> 5, lane = t & 31;
    int mg = wid >> 1, jg = wid & 1;
    int mg2 = wid >> 2, eg = wid & 3;

    const char* vb = (const char*)(g_VT + (size_t)b * Nn * Cc);
    const char* kb = (const char*)(g_Kb + (size_t)b * Dd * Nn);
    const char* qb = (const char*)(g_Qb + ((size_t)b * Nn + m0) * Dd);

    int vj = t >> 3, vc = t & 7;
    int kd = t >> 3, kc = t & 7;

#pragma unroll
    for (int st = 0; st < 2; st++) {
        int n0 = st * BN;
        uint32_t dst = smU + AT_VS + st * 33792 + vj * 528 + vc * 16;
        const char* src = vb + ((size_t)(n0 + vj)) * 512 + vc * 16;
#pragma unroll
        for (int u = 0; u < 4; u++) cp16(dst + u * 128, src + u * 128);
        if (t < 128) cp16(smU + AT_KS + st * 2304 + kd * 144 + kc * 16,
                          kb + (size_t)kd * (Nn * 2) + n0 * 2 + kc * 16);
        if (st == 0 && t < 256) {
            int m = t >> 1, c = t & 1;
            cp16(smU + AT_QS + m * 48 + c * 16, qb + m * 32 + c * 16);
        }
        CP_COMMIT;
    }

    float acc[2][8][4];
#pragma unroll
    for (int i = 0; i < 2; i++)
#pragma unroll
        for (int j = 0; j < 8; j++)
#pragma unroll
            for (int q = 0; q < 4; q++) acc[i][j][q] = 0.f;

    uint32_t qa[4];
    float rs0 = 0.f, rs1 = 0.f;

    uint32_t ps_st0 = smU + AT_PS + (mg * 16 + (lane >> 2)) * 144 + (jg * 32 + (lane & 3) * 2) * 2;
    uint32_t ps_ld0 = smU + AT_PS +
        (uint32_t)(mg2 * 32 + (lane & 7) + ((lane >> 3) & 1) * 8) * 144 + (lane >> 4) * 16;

    CP_WAIT1;
    __syncthreads();
    {
        uint32_t qaddr = smU + AT_QS +
            (mg * 16 + (lane & 7) + ((lane >> 3) & 1) * 8) * 48 + (lane >> 4) * 16;
        ldsm_x4(qa[0], qa[1], qa[2], qa[3], qaddr);
    }
    {
        uint32_t ksb = smU + AT_KS;
        uint32_t pst = ps_st0;
#pragma unroll
        for (int nb2 = 0; nb2 < 2; nb2++) {
            float c[2][4];
#pragma unroll
            for (int h = 0; h < 2; h++)
#pragma unroll
                for (int j = 0; j < 4; j++) c[h][j] = 0.f;
            uint32_t b0, b1, b2, b3;
            uint32_t ka = ksb + (lane & 15) * 144 + (jg * 32 + nb2 * 16 + (lane >> 4) * 8) * 2;
            ldsm_x4t(b0, b1, b2, b3, ka);
            mma16816(c[0], qa, b0, b1);
            mma16816(c[1], qa, b2, b3);
#pragma unroll
            for (int h = 0; h < 2; h++) {
                float e0 = ex2(fminf(fmaxf(c[h][0], -CLIP2), CLIP2));
                float e1 = ex2(fminf(fmaxf(c[h][1], -CLIP2), CLIP2));
                float e2 = ex2(fminf(fmaxf(c[h][2], -CLIP2), CLIP2));
                float e3 = ex2(fminf(fmaxf(c[h][3], -CLIP2), CLIP2));
                rs0 += e0 + e1;
                rs1 += e2 + e3;
                __nv_bfloat162 lo = __floats2bfloat162_rn(e0, e1);
                __nv_bfloat162 hi = __floats2bfloat162_rn(e2, e3);
                sts32(pst + nb2 * 32 + h * 16, *(uint32_t*)&lo);
                sts32(pst + nb2 * 32 + h * 16 + 8 * 144, *(uint32_t*)&hi);
            }
        }
    }

    for (int it = 0; it < NTILES; it++) {
        if (it + 2 < NTILES) {
            int n0 = (it + 2) * BN;
            int sp = (it + 2) & 3;
            uint32_t dst = smU + AT_VS + sp * 33792 + vj * 528 + vc * 16;
            const char* src = vb + ((size_t)(n0 + vj)) * 512 + vc * 16;
#pragma unroll
            for (int u = 0; u < 4; u++) cp16(dst + u * 128, src + u * 128);
            if (t < 128) cp16(smU + AT_KS + sp * 2304 + kd * 144 + kc * 16,
                              kb + (size_t)kd * (Nn * 2) + n0 * 2 + kc * 16);
        }
        CP_COMMIT;
        CP_WAIT1;
        __syncthreads();

        if (it + 1 < NTILES) {
            uint32_t ksb = smU + AT_KS + ((it + 1) & 3) * 2304;
            uint32_t pst = ps_st0 + ((it + 1) & 1) * 18432;
#pragma unroll
            for (int nb2 = 0; nb2 < 2; nb2++) {
                float c[2][4];
#pragma unroll
                for (int h = 0; h < 2; h++)
#pragma unroll
                    for (int j = 0; j < 4; j++) c[h][j] = 0.f;
                uint32_t b0, b1, b2, b3;
                uint32_t ka = ksb + (lane & 15) * 144 + (jg * 32 + nb2 * 16 + (lane >> 4) * 8) * 2;
                ldsm_x4t(b0, b1, b2, b3, ka);
                mma16816(c[0], qa, b0, b1);
                mma16816(c[1], qa, b2, b3);
#pragma unroll
                for (int h = 0; h < 2; h++) {
                    float e0 = ex2(fminf(fmaxf(c[h][0], -CLIP2), CLIP2));
                    float e1 = ex2(fminf(fmaxf(c[h][1], -CLIP2), CLIP2));
                    float e2 = ex2(fminf(fmaxf(c[h][2], -CLIP2), CLIP2));
                    float e3 = ex2(fminf(fmaxf(c[h][3], -CLIP2), CLIP2));
                    rs0 += e0 + e1;
                    rs1 += e2 + e3;
                    __nv_bfloat162 lo = __floats2bfloat162_rn(e0, e1);
                    __nv_bfloat162 hi = __floats2bfloat162_rn(e2, e3);
                    sts32(pst + nb2 * 32 + h * 16, *(uint32_t*)&lo);
                    sts32(pst + nb2 * 32 + h * 16 + 8 * 144, *(uint32_t*)&hi);
                }
            }
        }

        {
            uint32_t vsb = smU + AT_VS + (it & 3) * 33792;
            uint32_t pld = ps_ld0 + (it & 1) * 18432;
#pragma unroll
            for (int kg = 0; kg < 4; kg++) {
                uint32_t pA[2][4];
#pragma unroll
                for (int mi = 0; mi < 2; mi++)
                    ldsm_x4(pA[mi][0], pA[mi][1], pA[mi][2], pA[mi][3],
                            pld + mi * (16 * 144) + kg * 32);
#pragma unroll
                for (int eb2 = 0; eb2 < 4; eb2++) {
                    uint32_t b0, b1, b2, b3;
                    uint32_t va = vsb + (kg * 16 + (lane & 15)) * 528 +
                                  (eg * 64 + eb2 * 16 + (lane >> 4) * 8) * 2;
                    ldsm_x4t(b0, b1, b2, b3, va);
                    mma16816(acc[0][eb2 * 2],     pA[0], b0, b1);
                    mma16816(acc[0][eb2 * 2 + 1], pA[0], b2, b3);
                    mma16816(acc[1][eb2 * 2],     pA[1], b0, b1);
                    mma16816(acc[1][eb2 * 2 + 1], pA[1], b2, b3);
                }
            }
        }
    }

    rs0 += __shfl_xor_sync(0xffffffffu, rs0, 1);
    rs0 += __shfl_xor_sync(0xffffffffu, rs0, 2);
    rs1 += __shfl_xor_sync(0xffffffffu, rs1, 1);
    rs1 += __shfl_xor_sync(0xffffffffu, rs1, 2);
    float* rs_s = (float*)(sm + AT_RS);
    if ((lane & 3) == 0) {
        rs_s[jg * 128 + mg * 16 + (lane >> 2)]     = rs0;
        rs_s[jg * 128 + mg * 16 + (lane >> 2) + 8] = rs1;
    }

    float* Tf = (float*)sm;
    __nv_bfloat16* ob = g_OAb + (size_t)b * Cc * Nn + m0;
    int r = lane >> 2, q = lane & 3;
#pragma unroll
    for (int h = 0; h < 2; h++) {
        __syncthreads();
        if ((eg >> 1) == h) {
            int ebase = (eg & 1) * 64;
#pragma unroll
            for (int mi = 0; mi < 2; mi++) {
                int ml = mg2 * 32 + mi * 16 + r;
                float inv0 = 1.f / (rs_s[ml]     + rs_s[128 + ml]);
                float inv1 = 1.f / (rs_s[ml + 8] + rs_s[128 + ml + 8]);
#pragma unroll
                for (int nb = 0; nb < 8; nb++) {
                    int e = ebase + nb * 8 + 2 * q;
                    float* a = acc[mi][nb];
                    Tf[(size_t)e * 132 + ml]           = a[0] * inv0;
                    Tf[(size_t)(e + 1) * 132 + ml]     = a[1] * inv0;
                    Tf[(size_t)e * 132 + ml + 8]       = a[2] * inv1;
                    Tf[(size_t)(e + 1) * 132 + ml + 8] = a[3] * inv1;
                }
            }
        }
        __syncthreads();
#pragma unroll
        for (int rr = 0; rr < 8; rr++) {
            int e = wid * 8 + rr;
            const float* srcr = Tf + (size_t)e * 132;
            __nv_bfloat16* dstr = ob + (size_t)(h * 128 + e) * Nn;
#pragma unroll
            for (int c = 0; c < 2; c++) {
                dstr[c * 64 + lane]      = __float2bfloat16(srcr[c * 64 + lane]);
                dstr[c * 64 + 32 + lane] = __float2bfloat16(srcr[c * 64 + 32 + lane]);
            }
        }
    }
}

// ================= output projection: m64 tiles, 3 CTAs/SM =================
// smem: W 2 x [64][144B]=9216 | X 2 x [64][272B]=17408
#define OP_WS 0
#define OP_XS 18432
#define OP_BYTES (18432 + 34816)

__global__ __launch_bounds__(256, 3) void outproj_kernel(
    const float* __restrict__ x,
    const float* __restrict__ bo,
    const float* __restrict__ gamma, float* __restrict__ out)
{
    extern __shared__ __align__(16) char sm[];
    uint32_t smU = smem_u32(sm);
    int t = threadIdx.x, wid = t >> 5, lane = t & 31;
    int mg = wid >> 1, ng = wid & 1;      // warp: m16 x n64
    int n0 = blockIdx.x * 128, ytile = blockIdx.y, b = blockIdx.z;

    int wm = t >> 2, wq = t & 3;
    const __nv_bfloat16* wsrc = g_Wb + WO_OFF + (ytile * 64 + wm) * Cc;
    const __nv_bfloat16* xb = g_OAb + (size_t)b * Cc * Nn + n0;
    int xk = t >> 2, xn = t & 3;

    // prologue: chunk 0
#pragma unroll
    for (int u = 0; u < 2; u++)
        cp16(smU + OP_WS + wm * 144 + (wq + 4 * u) * 16, wsrc + (wq + 4 * u) * 8);
#pragma unroll
    for (int u = 0; u < 4; u++)
        cp16(smU + OP_XS + xk * 272 + (xn + 4 * u) * 16, xb + (size_t)xk * Nn + (xn + 4 * u) * 8);
    CP_COMMIT;

    float acc[8][4];
#pragma unroll
    for (int j = 0; j < 8; j++)
#pragma unroll
        for (int q = 0; q < 4; q++) acc[j][q] = 0.f;

    for (int ch = 0; ch < 4; ch++) {
        CP_WAIT0;
        __syncthreads();
        if (ch + 1 < 4) {
            int k0 = (ch + 1) * 64, sp = (ch + 1) & 1;
#pragma unroll
            for (int u = 0; u < 2; u++)
                cp16(smU + OP_WS + sp * 9216 + wm * 144 + (wq + 4 * u) * 16,
                     wsrc + k0 + (wq + 4 * u) * 8);
#pragma unroll
            for (int u = 0; u < 4; u++)
                cp16(smU + OP_XS + sp * 17408 + xk * 272 + (xn + 4 * u) * 16,
                     xb + (size_t)(k0 + xk) * Nn + (xn + 4 * u) * 8);
            CP_COMMIT;
        }
        {
            uint32_t wbU = smU + OP_WS + (ch & 1) * 9216;
            uint32_t xsU = smU + OP_XS + (ch & 1) * 17408;
#pragma unroll
            for (int kg = 0; kg < 4; kg++) {
                uint32_t A[4];
                ldsm_x4(A[0], A[1], A[2], A[3],
                        wbU + (mg * 16 + (lane & 15)) * 144 + kg * 32 + (lane >> 4) * 16);
#pragma unroll
                for (int nb2 = 0; nb2 < 4; nb2++) {
                    uint32_t b0, b1, b2, b3;
                    ldsm_x4t(b0, b1, b2, b3,
                             xsU + (kg * 16 + (lane & 15)) * 272 +
                             (ng * 64 + nb2 * 16 + (lane >> 4) * 8) * 2);
                    mma16816(acc[nb2 * 2],     A, b0, b1);
                    mma16816(acc[nb2 * 2 + 1], A, b2, b3);
                }
            }
        }
    }
    __syncthreads();

    // epilogue: stage fp32 [m64][132] then fused coalesced stores
    float* Tf = (float*)sm;
    {
        int m = mg * 16 + (lane >> 2);
#pragma unroll
        for (int nb = 0; nb < 8; nb++) {
            int n = ng * 64 + nb * 8 + (lane & 3) * 2;
            float* a = acc[nb];
            *(float2*)(Tf + (size_t)m * 132 + n)       = make_float2(a[0], a[1]);
            *(float2*)(Tf + (size_t)(m + 8) * 132 + n) = make_float2(a[2], a[3]);
        }
    }
    __syncthreads();
    float g = fminf(fmaxf(gamma[0], 0.f), 1.f);
    {
        int m = t >> 2, c = t & 3;
        int mglob = ytile * 64 + m;
        float bb = bo[mglob];
        size_t base = ((size_t)(b * Cc + mglob)) * Nn + n0 + c * 32;
#pragma unroll
        for (int u = 0; u < 8; u++) {
            float4 v = *(const float4*)(Tf + (size_t)m * 132 + c * 32 + u * 4);
            float4 xr = *(const float4*)(x + base + u * 4);
            float4 o;
            o.x = g * (v.x + bb) + xr.x;
            o.y = g * (v.y + bb) + xr.y;
            o.z = g * (v.z + bb) + xr.z;
            o.w = g * (v.w + bb) + xr.w;
            *(float4*)(out + base + u * 4) = o;
        }
    }
}

// ---------------- launcher ----------------
extern "C" void kernel_launch(void* const* d_in, const int* in_sizes, int n_in,
                              void* d_out, int out_size)
{
    const float* x     = (const float*)d_in[0];
    const float* Wq    = (const float*)d_in[1];
    const float* bq    = (const float*)d_in[2];
    const float* Wk    = (const float*)d_in[3];
    const float* bk    = (const float*)d_in[4];
    const float* Wv    = (const float*)d_in[5];
    const float* bv    = (const float*)d_in[6];
    const float* Wo    = (const float*)d_in[7];
    const float* bo    = (const float*)d_in[8];
    const float* gamma = (const float*)d_in[9];
    float* out = (float*)d_out;

    cudaFuncSetAttribute(proj_kernel,    cudaFuncAttributeMaxDynamicSharedMemorySize, PJ_BYTES);
    cudaFuncSetAttribute(outproj_kernel, cudaFuncAttributeMaxDynamicSharedMemorySize, OP_BYTES);
    cudaFuncSetAttribute(attn_kernel,    cudaFuncAttributeMaxDynamicSharedMemorySize, AT_BYTES);

    cvt_kernel    <<<2184, 256>>>(x, Wq, Wk, Wv, Wo);
    proj_kernel   <<<dim3(Nn / 128, 3, Bb), 256, PJ_BYTES>>>(bq, bk, bv);
    attn_kernel   <<<dim3(Nn / BM, Bb), 512, AT_BYTES>>>();
    outproj_kernel<<<dim3(Nn / 128, 4, Bb), 256, OP_BYTES>>>(x, bo, gamma, out);
}

// round 15
// speedup vs baseline: 1.5120x; 1.0214x over previous
#include <cuda_runtime.h>
#include <cuda_bf16.h>
#include <cstdint>

#define Bb 8
#define Cc 256
#define Nn 4096
#define Dd 16
#define BM 128
#define BN 64
#define NTILES (Nn / BN)

// ---------------- scratch ----------------
__device__ __nv_bfloat16 g_Qb[(size_t)Bb * Nn * Dd];   // [B,N,16] bf16, (q+bq)*0.25*log2e
__device__ __nv_bfloat16 g_Kb[(size_t)Bb * Dd * Nn];   // [B,16,N] bf16, k+bk
__device__ __nv_bfloat16 g_VT[(size_t)Bb * Nn * Cc];   // [B,N,C] bf16
__device__ __nv_bfloat16 g_OAb[(size_t)Bb * Cc * Nn];  // [B,C,N] bf16 attn out
__device__ __nv_bfloat16 g_Xb[(size_t)Bb * Cc * Nn];   // x in bf16
__device__ __nv_bfloat16 g_Wb[139264];                 // [Wq | Wk | Wv | Wo]
#define WQ_OFF 0
#define WK_OFF 4096
#define WV_OFF 8192
#define WO_OFF 73728

// ---------------- helpers ----------------
static __device__ __forceinline__ uint32_t smem_u32(const void* p) {
    uint32_t a;
    asm("{ .reg .u64 t; cvta.to.shared.u64 t, %1; cvt.u32.u64 %0, t; }" : "=r"(a) : "l"(p));
    return a;
}
static __device__ __forceinline__ void ldsm_x4(uint32_t &r0, uint32_t &r1, uint32_t &r2, uint32_t &r3, uint32_t addr) {
    asm volatile("ldmatrix.sync.aligned.m8n8.x4.shared.b16 {%0,%1,%2,%3}, [%4];"
                 : "=r"(r0), "=r"(r1), "=r"(r2), "=r"(r3) : "r"(addr));
}
static __device__ __forceinline__ void ldsm_x4t(uint32_t &r0, uint32_t &r1, uint32_t &r2, uint32_t &r3, uint32_t addr) {
    asm volatile("ldmatrix.sync.aligned.m8n8.x4.trans.shared.b16 {%0,%1,%2,%3}, [%4];"
                 : "=r"(r0), "=r"(r1), "=r"(r2), "=r"(r3) : "r"(addr));
}
static __device__ __forceinline__ void mma16816(float* d, const uint32_t* a, uint32_t b0, uint32_t b1) {
    asm volatile("mma.sync.aligned.m16n8k16.row.col.f32.bf16.bf16.f32 "
                 "{%0,%1,%2,%3}, {%4,%5,%6,%7}, {%8,%9}, {%0,%1,%2,%3};"
                 : "+f"(d[0]), "+f"(d[1]), "+f"(d[2]), "+f"(d[3])
                 : "r"(a[0]), "r"(a[1]), "r"(a[2]), "r"(a[3]), "r"(b0), "r"(b1));
}
static __device__ __forceinline__ float ex2(float x) {
    float y; asm("ex2.approx.ftz.f32 %0, %1;" : "=f"(y) : "f"(x)); return y;
}
static __device__ __forceinline__ void sts32(uint32_t addr, uint32_t v) {
    asm volatile("st.shared.b32 [%0], %1;" :: "r"(addr), "r"(v));
}
static __device__ __forceinline__ void cp16(uint32_t dst, const void* src) {
    asm volatile("cp.async.cg.shared.global [%0], [%1], 16;" :: "r"(dst), "l"(src));
}
#define CP_COMMIT asm volatile("cp.async.commit_group;" ::: "memory")
#define CP_WAIT0  asm volatile("cp.async.wait_group 0;" ::: "memory")
#define CP_WAIT1  asm volatile("cp.async.wait_group 1;" ::: "memory")

#define QSCALE 0.36067376022224085f   // 0.25 * log2(e)
#define CLIP2  72.134752f             // 50 * log2(e)

// ================= convert x + weights to bf16 =================
__global__ __launch_bounds__(256) void cvt_kernel(
    const float* __restrict__ x,
    const float* __restrict__ Wq, const float* __restrict__ Wk,
    const float* __restrict__ Wv, const float* __restrict__ Wo)
{
    int i = blockIdx.x, t = threadIdx.x;
    if (i < 2048) {
        const float4* xs = (const float4*)x;
        uint2* xd = (uint2*)g_Xb;
#pragma unroll
        for (int j = 0; j < 4; j++) {
            int idx = i * 1024 + j * 256 + t;
            float4 v = xs[idx];
            __nv_bfloat162 p0 = __floats2bfloat162_rn(v.x, v.y);
            __nv_bfloat162 p1 = __floats2bfloat162_rn(v.z, v.w);
            uint2 u; u.x = *(uint32_t*)&p0; u.y = *(uint32_t*)&p1;
            xd[idx] = u;
        }
    } else {
        int idx4 = (i - 2048) * 256 + t;
        const float* src;
        if (idx4 < 1024)       src = Wq + idx4 * 4;
        else if (idx4 < 2048)  src = Wk + (idx4 - 1024) * 4;
        else if (idx4 < 18432) src = Wv + (idx4 - 2048) * 4;
        else                   src = Wo + (idx4 - 18432) * 4;
        float4 v = *(const float4*)src;
        __nv_bfloat162 p0 = __floats2bfloat162_rn(v.x, v.y);
        __nv_bfloat162 p1 = __floats2bfloat162_rn(v.z, v.w);
        uint2 u; u.x = *(uint32_t*)&p0; u.y = *(uint32_t*)&p1;
        ((uint2*)g_Wb)[idx4] = u;
    }
}

// ================= fused projection: V (+Q,K) via bf16 MMA, 3-stage ring =================
#define PJ_WS 0
#define PJ_XS 55296
#define PJ_BYTES (55296 + 52224)
#define NCHUNK 4

__global__ __launch_bounds__(256, 2) void proj_kernel(
    const float* __restrict__ bq, const float* __restrict__ bk,
    const float* __restrict__ bv)
{
    extern __shared__ __align__(16) char sm[];
    uint32_t smU = smem_u32(sm);
    int t = threadIdx.x, wid = t >> 5, lane = t & 31;
    int mg = wid >> 1, ng = wid & 1;
    int n0 = blockIdx.x * 128, ytile = blockIdx.y, b = blockIdx.z;
    bool active = (ytile < 2) || (mg == 0);

    int wm = t >> 1, wq = t & 1;
    const __nv_bfloat16* wsrc;
    bool wvalid = true;
    if (ytile < 2) wsrc = g_Wb + WV_OFF + (ytile * 128 + wm) * Cc;
    else {
        if (wm < 16) wsrc = g_Wb + WQ_OFF + wm * Cc;
        else if (wm < 32) wsrc = g_Wb + WK_OFF + (wm - 16) * Cc;
        else { wsrc = g_Wb; wvalid = false; }
    }
    const __nv_bfloat16* xb = g_Xb + (size_t)b * Cc * Nn + n0;
    int xk = t >> 2, xn = t & 3;

#pragma unroll
    for (int ch = 0; ch < 2; ch++) {
        int k0 = ch * 64;
        if (wvalid) {
#pragma unroll
            for (int u = 0; u < 4; u++)
                cp16(smU + PJ_WS + ch * 18432 + wm * 144 + (wq + 2 * u) * 16,
                     wsrc + k0 + (wq + 2 * u) * 8);
        }
#pragma unroll
        for (int u = 0; u < 4; u++)
            cp16(smU + PJ_XS + ch * 17408 + xk * 272 + (xn + 4 * u) * 16,
                 xb + (size_t)(k0 + xk) * Nn + (xn + 4 * u) * 8);
        CP_COMMIT;
    }

    float acc[2][8][4];
#pragma unroll
    for (int i = 0; i < 2; i++)
#pragma unroll
        for (int j = 0; j < 8; j++)
#pragma unroll
            for (int q = 0; q < 4; q++) acc[i][j][q] = 0.f;

    int st = 0, sp = 2;
    for (int ch = 0; ch < NCHUNK; ch++) {
        CP_WAIT1;
        __syncthreads();
        if (ch + 2 < NCHUNK) {
            int k0 = (ch + 2) * 64;
            if (wvalid) {
#pragma unroll
                for (int u = 0; u < 4; u++)
                    cp16(smU + PJ_WS + sp * 18432 + wm * 144 + (wq + 2 * u) * 16,
                         wsrc + k0 + (wq + 2 * u) * 8);
            }
#pragma unroll
            for (int u = 0; u < 4; u++)
                cp16(smU + PJ_XS + sp * 17408 + xk * 272 + (xn + 4 * u) * 16,
                     xb + (size_t)(k0 + xk) * Nn + (xn + 4 * u) * 8);
        }
        CP_COMMIT;
        if (active) {
            uint32_t wbU = smU + PJ_WS + st * 18432;
            uint32_t xsU = smU + PJ_XS + st * 17408;
#pragma unroll
            for (int kg = 0; kg < 4; kg++) {
                uint32_t A[2][4];
#pragma unroll
                for (int mi = 0; mi < 2; mi++)
                    ldsm_x4(A[mi][0], A[mi][1], A[mi][2], A[mi][3],
                            wbU + (mg * 32 + mi * 16 + (lane & 15)) * 144 +
                            kg * 32 + (lane >> 4) * 16);
#pragma unroll
                for (int nb2 = 0; nb2 < 4; nb2++) {
                    uint32_t b0, b1, b2, b3;
                    ldsm_x4t(b0, b1, b2, b3,
                             xsU + (kg * 16 + (lane & 15)) * 272 +
                             (ng * 64 + nb2 * 16 + (lane >> 4) * 8) * 2);
                    mma16816(acc[0][nb2 * 2],     A[0], b0, b1);
                    mma16816(acc[0][nb2 * 2 + 1], A[0], b2, b3);
                    mma16816(acc[1][nb2 * 2],     A[1], b0, b1);
                    mma16816(acc[1][nb2 * 2 + 1], A[1], b2, b3);
                }
            }
        }
        st = (st == 2) ? 0 : st + 1;
        sp = (sp == 2) ? 0 : sp + 1;
    }
    __syncthreads();

    if (ytile < 2) {
        __nv_bfloat16* Tb = (__nv_bfloat16*)(sm + PJ_XS);
#pragma unroll
        for (int mi = 0; mi < 2; mi++) {
            int m = mg * 32 + mi * 16 + (lane >> 2);
            float bv0 = bv[ytile * 128 + m];
            float bv1 = bv[ytile * 128 + m + 8];
#pragma unroll
            for (int nb = 0; nb < 8; nb++) {
                int n = ng * 64 + nb * 8 + (lane & 3) * 2;
                float* a = acc[mi][nb];
                Tb[(size_t)n * 136 + m]           = __float2bfloat16(a[0] + bv0);
                Tb[(size_t)(n + 1) * 136 + m]     = __float2bfloat16(a[1] + bv0);
                Tb[(size_t)n * 136 + m + 8]       = __float2bfloat16(a[2] + bv1);
                Tb[(size_t)(n + 1) * 136 + m + 8] = __float2bfloat16(a[3] + bv1);
            }
        }
        __syncthreads();
        int n = t >> 1, c = t & 1;
        const uint4* src = (const uint4*)((const char*)Tb + n * 272 + c * 128);
        uint4* dst = (uint4*)((char*)(g_VT + ((size_t)(b * Nn + n0 + n)) * Cc + ytile * 128) + c * 128);
#pragma unroll
        for (int u = 0; u < 8; u++) dst[u] = src[u];
    } else {
        __nv_bfloat16* Qt = (__nv_bfloat16*)(sm + PJ_XS);            // [128][24]
        __nv_bfloat16* Kt = (__nv_bfloat16*)(sm + PJ_XS + 6144);     // [16][136]
        if (mg == 0) {
            {
                int d = lane >> 2;
                float b0 = bq[d], b1 = bq[d + 8];
#pragma unroll
                for (int nb = 0; nb < 8; nb++) {
                    int n = ng * 64 + nb * 8 + (lane & 3) * 2;
                    float* a = acc[0][nb];
                    Qt[(size_t)n * 24 + d]           = __float2bfloat16((a[0] + b0) * QSCALE);
                    Qt[(size_t)(n + 1) * 24 + d]     = __float2bfloat16((a[1] + b0) * QSCALE);
                    Qt[(size_t)n * 24 + d + 8]       = __float2bfloat16((a[2] + b1) * QSCALE);
                    Qt[(size_t)(n + 1) * 24 + d + 8] = __float2bfloat16((a[3] + b1) * QSCALE);
                }
            }
            {
                int d = lane >> 2;
                float b0 = bk[d], b1 = bk[d + 8];
#pragma unroll
                for (int nb = 0; nb < 8; nb++) {
                    int n = ng * 64 + nb * 8 + (lane & 3) * 2;
                    float* a = acc[1][nb];
                    Kt[(size_t)d * 136 + n]           = __float2bfloat16(a[0] + b0);
                    Kt[(size_t)d * 136 + n + 1]       = __float2bfloat16(a[1] + b0);
                    Kt[(size_t)(d + 8) * 136 + n]     = __float2bfloat16(a[2] + b1);
                    Kt[(size_t)(d + 8) * 136 + n + 1] = __float2bfloat16(a[3] + b1);
                }
            }
        }
        __syncthreads();
        {
            int n = t >> 1, c = t & 1;
            const uint4* src = (const uint4*)((const char*)Qt + n * 48 + c * 16);
            uint4* dst = (uint4*)((char*)(g_Qb + ((size_t)(b * Nn + n0 + n)) * Dd) + c * 16);
            dst[0] = src[0];
        }
        {
            int d = t >> 4, c = t & 15;
            const uint4* src = (const uint4*)((const char*)Kt + d * 272 + c * 16);
            uint4* dst = (uint4*)((char*)(g_Kb + ((size_t)(b * Dd + d)) * Nn + n0) + c * 16);
            dst[0] = src[0];
        }
    }
}

// ================= fused attention: pipelined split-role FA2 =================
#define AT_VS 0
#define AT_KS 135168
#define AT_QS 144384
#define AT_PS 150528
#define AT_RS 187392
#define AT_BYTES 188416

__global__ __launch_bounds__(512, 1) void attn_kernel()
{
    extern __shared__ __align__(16) char sm[];
    uint32_t smU = smem_u32(sm);
    int t = threadIdx.x, b = blockIdx.y, m0 = blockIdx.x * BM;
    int wid = t >> 5, lane = t & 31;
    int mg = wid >> 1, jg = wid & 1;
    int mg2 = wid >> 2, eg = wid & 3;

    const char* vb = (const char*)(g_VT + (size_t)b * Nn * Cc);
    const char* kb = (const char*)(g_Kb + (size_t)b * Dd * Nn);
    const char* qb = (const char*)(g_Qb + ((size_t)b * Nn + m0) * Dd);

    int vj = t >> 3, vc = t & 7;
    int kd = t >> 3, kc = t & 7;

#pragma unroll
    for (int st = 0; st < 2; st++) {
        int n0 = st * BN;
        uint32_t dst = smU + AT_VS + st * 33792 + vj * 528 + vc * 16;
        const char* src = vb + ((size_t)(n0 + vj)) * 512 + vc * 16;
#pragma unroll
        for (int u = 0; u < 4; u++) cp16(dst + u * 128, src + u * 128);
        if (t < 128) cp16(smU + AT_KS + st * 2304 + kd * 144 + kc * 16,
                          kb + (size_t)kd * (Nn * 2) + n0 * 2 + kc * 16);
        if (st == 0 && t < 256) {
            int m = t >> 1, c = t & 1;
            cp16(smU + AT_QS + m * 48 + c * 16, qb + m * 32 + c * 16);
        }
        CP_COMMIT;
    }

    float acc[2][8][4];
#pragma unroll
    for (int i = 0; i < 2; i++)
#pragma unroll
        for (int j = 0; j < 8; j++)
#pragma unroll
            for (int q = 0; q < 4; q++) acc[i][j][q] = 0.f;

    uint32_t qa[4];
    float rs0 = 0.f, rs1 = 0.f;

    uint32_t ps_st0 = smU + AT_PS + (mg * 16 + (lane >> 2)) * 144 + (jg * 32 + (lane & 3) * 2) * 2;
    uint32_t ps_ld0 = smU + AT_PS +
        (uint32_t)(mg2 * 32 + (lane & 7) + ((lane >> 3) & 1) * 8) * 144 + (lane >> 4) * 16;

    CP_WAIT1;
    __syncthreads();
    {
        uint32_t qaddr = smU + AT_QS +
            (mg * 16 + (lane & 7) + ((lane >> 3) & 1) * 8) * 48 + (lane >> 4) * 16;
        ldsm_x4(qa[0], qa[1], qa[2], qa[3], qaddr);
    }
    {
        uint32_t ksb = smU + AT_KS;
        uint32_t pst = ps_st0;
#pragma unroll
        for (int nb2 = 0; nb2 < 2; nb2++) {
            float c[2][4];
#pragma unroll
            for (int h = 0; h < 2; h++)
#pragma unroll
                for (int j = 0; j < 4; j++) c[h][j] = 0.f;
            uint32_t b0, b1, b2, b3;
            uint32_t ka = ksb + (lane & 15) * 144 + (jg * 32 + nb2 * 16 + (lane >> 4) * 8) * 2;
            ldsm_x4t(b0, b1, b2, b3, ka);
            mma16816(c[0], qa, b0, b1);
            mma16816(c[1], qa, b2, b3);
#pragma unroll
            for (int h = 0; h < 2; h++) {
                float e0 = ex2(fminf(fmaxf(c[h][0], -CLIP2), CLIP2));
                float e1 = ex2(fminf(fmaxf(c[h][1], -CLIP2), CLIP2));
                float e2 = ex2(fminf(fmaxf(c[h][2], -CLIP2), CLIP2));
                float e3 = ex2(fminf(fmaxf(c[h][3], -CLIP2), CLIP2));
                rs0 += e0 + e1;
                rs1 += e2 + e3;
                __nv_bfloat162 lo = __floats2bfloat162_rn(e0, e1);
                __nv_bfloat162 hi = __floats2bfloat162_rn(e2, e3);
                sts32(pst + nb2 * 32 + h * 16, *(uint32_t*)&lo);
                sts32(pst + nb2 * 32 + h * 16 + 8 * 144, *(uint32_t*)&hi);
            }
        }
    }

    for (int it = 0; it < NTILES; it++) {
        if (it + 2 < NTILES) {
            int n0 = (it + 2) * BN;
            int sp = (it + 2) & 3;
            uint32_t dst = smU + AT_VS + sp * 33792 + vj * 528 + vc * 16;
            const char* src = vb + ((size_t)(n0 + vj)) * 512 + vc * 16;
#pragma unroll
            for (int u = 0; u < 4; u++) cp16(dst + u * 128, src + u * 128);
            if (t < 128) cp16(smU + AT_KS + sp * 2304 + kd * 144 + kc * 16,
                              kb + (size_t)kd * (Nn * 2) + n0 * 2 + kc * 16);
        }
        CP_COMMIT;
        CP_WAIT1;
        __syncthreads();

        if (it + 1 < NTILES) {
            uint32_t ksb = smU + AT_KS + ((it + 1) & 3) * 2304;
            uint32_t pst = ps_st0 + ((it + 1) & 1) * 18432;
#pragma unroll
            for (int nb2 = 0; nb2 < 2; nb2++) {
                float c[2][4];
#pragma unroll
                for (int h = 0; h < 2; h++)
#pragma unroll
                    for (int j = 0; j < 4; j++) c[h][j] = 0.f;
                uint32_t b0, b1, b2, b3;
                uint32_t ka = ksb + (lane & 15) * 144 + (jg * 32 + nb2 * 16 + (lane >> 4) * 8) * 2;
                ldsm_x4t(b0, b1, b2, b3, ka);
                mma16816(c[0], qa, b0, b1);
                mma16816(c[1], qa, b2, b3);
#pragma unroll
                for (int h = 0; h < 2; h++) {
                    float e0 = ex2(fminf(fmaxf(c[h][0], -CLIP2), CLIP2));
                    float e1 = ex2(fminf(fmaxf(c[h][1], -CLIP2), CLIP2));
                    float e2 = ex2(fminf(fmaxf(c[h][2], -CLIP2), CLIP2));
                    float e3 = ex2(fminf(fmaxf(c[h][3], -CLIP2), CLIP2));
                    rs0 += e0 + e1;
                    rs1 += e2 + e3;
                    __nv_bfloat162 lo = __floats2bfloat162_rn(e0, e1);
                    __nv_bfloat162 hi = __floats2bfloat162_rn(e2, e3);
                    sts32(pst + nb2 * 32 + h * 16, *(uint32_t*)&lo);
                    sts32(pst + nb2 * 32 + h * 16 + 8 * 144, *(uint32_t*)&hi);
                }
            }
        }

        {
            uint32_t vsb = smU + AT_VS + (it & 3) * 33792;
            uint32_t pld = ps_ld0 + (it & 1) * 18432;
#pragma unroll
            for (int kg = 0; kg < 4; kg++) {
                uint32_t pA[2][4];
#pragma unroll
                for (int mi = 0; mi < 2; mi++)
                    ldsm_x4(pA[mi][0], pA[mi][1], pA[mi][2], pA[mi][3],
                            pld + mi * (16 * 144) + kg * 32);
#pragma unroll
                for (int eb2 = 0; eb2 < 4; eb2++) {
                    uint32_t b0, b1, b2, b3;
                    uint32_t va = vsb + (kg * 16 + (lane & 15)) * 528 +
                                  (eg * 64 + eb2 * 16 + (lane >> 4) * 8) * 2;
                    ldsm_x4t(b0, b1, b2, b3, va);
                    mma16816(acc[0][eb2 * 2],     pA[0], b0, b1);
                    mma16816(acc[0][eb2 * 2 + 1], pA[0], b2, b3);
                    mma16816(acc[1][eb2 * 2],     pA[1], b0, b1);
                    mma16816(acc[1][eb2 * 2 + 1], pA[1], b2, b3);
                }
            }
        }
    }

    rs0 += __shfl_xor_sync(0xffffffffu, rs0, 1);
    rs0 += __shfl_xor_sync(0xffffffffu, rs0, 2);
    rs1 += __shfl_xor_sync(0xffffffffu, rs1, 1);
    rs1 += __shfl_xor_sync(0xffffffffu, rs1, 2);
    float* rs_s = (float*)(sm + AT_RS);
    if ((lane & 3) == 0) {
        rs_s[jg * 128 + mg * 16 + (lane >> 2)]     = rs0;
        rs_s[jg * 128 + mg * 16 + (lane >> 2) + 8] = rs1;
    }

    float* Tf = (float*)sm;
    __nv_bfloat16* ob = g_OAb + (size_t)b * Cc * Nn + m0;
    int r = lane >> 2, q = lane & 3;
#pragma unroll
    for (int h = 0; h < 2; h++) {
        __syncthreads();
        if ((eg >> 1) == h) {
            int ebase = (eg & 1) * 64;
#pragma unroll
            for (int mi = 0; mi < 2; mi++) {
                int ml = mg2 * 32 + mi * 16 + r;
                float inv0 = 1.f / (rs_s[ml]     + rs_s[128 + ml]);
                float inv1 = 1.f / (rs_s[ml + 8] + rs_s[128 + ml + 8]);
#pragma unroll
                for (int nb = 0; nb < 8; nb++) {
                    int e = ebase + nb * 8 + 2 * q;
                    float* a = acc[mi][nb];
                    Tf[(size_t)e * 132 + ml]           = a[0] * inv0;
                    Tf[(size_t)(e + 1) * 132 + ml]     = a[1] * inv0;
                    Tf[(size_t)e * 132 + ml + 8]       = a[2] * inv1;
                    Tf[(size_t)(e + 1) * 132 + ml + 8] = a[3] * inv1;
                }
            }
        }
        __syncthreads();
#pragma unroll
        for (int rr = 0; rr < 8; rr++) {
            int e = wid * 8 + rr;
            const float* srcr = Tf + (size_t)e * 132;
            __nv_bfloat16* dstr = ob + (size_t)(h * 128 + e) * Nn;
#pragma unroll
            for (int c = 0; c < 2; c++) {
                dstr[c * 64 + lane]      = __float2bfloat16(srcr[c * 64 + lane]);
                dstr[c * 64 + 32 + lane] = __float2bfloat16(srcr[c * 64 + 32 + lane]);
            }
        }
    }
}

// ================= output projection: m64 x n64 tiles, 4 CTAs/SM =================
// smem: W 2 x [64][144B]=9216 | X 2 x [64][144B]=9216
#define OP_WS 0
#define OP_XS 18432
#define OP_BYTES 36864

__global__ __launch_bounds__(256, 4) void outproj_kernel(
    const float* __restrict__ x,
    const float* __restrict__ bo,
    const float* __restrict__ gamma, float* __restrict__ out)
{
    extern __shared__ __align__(16) char sm[];
    uint32_t smU = smem_u32(sm);
    int t = threadIdx.x, wid = t >> 5, lane = t & 31;
    int mg = wid >> 1, ng = wid & 1;      // 8 warps: f16 x n32
    int n0 = blockIdx.x * 64, ytile = blockIdx.y, b = blockIdx.z;

    int wm = t >> 2, wq = t & 3;
    const __nv_bfloat16* wsrc = g_Wb + WO_OFF + (ytile * 64 + wm) * Cc;
    const __nv_bfloat16* xb = g_OAb + (size_t)b * Cc * Nn + n0;
    int xk = t >> 2, xn = t & 3;

    // prologue: chunk 0
#pragma unroll
    for (int u = 0; u < 2; u++)
        cp16(smU + OP_WS + wm * 144 + (wq + 4 * u) * 16, wsrc + (wq + 4 * u) * 8);
#pragma unroll
    for (int u = 0; u < 2; u++)
        cp16(smU + OP_XS + xk * 144 + (xn + 4 * u) * 16, xb + (size_t)xk * Nn + (xn + 4 * u) * 8);
    CP_COMMIT;

    float acc[4][4];
#pragma unroll
    for (int j = 0; j < 4; j++)
#pragma unroll
        for (int q = 0; q < 4; q++) acc[j][q] = 0.f;

    for (int ch = 0; ch < 4; ch++) {
        CP_WAIT0;
        __syncthreads();
        if (ch + 1 < 4) {
            int k0 = (ch + 1) * 64, sp = (ch + 1) & 1;
#pragma unroll
            for (int u = 0; u < 2; u++)
                cp16(smU + OP_WS + sp * 9216 + wm * 144 + (wq + 4 * u) * 16,
                     wsrc + k0 + (wq + 4 * u) * 8);
#pragma unroll
            for (int u = 0; u < 2; u++)
                cp16(smU + OP_XS + sp * 9216 + xk * 144 + (xn + 4 * u) * 16,
                     xb + (size_t)(k0 + xk) * Nn + (xn + 4 * u) * 8);
            CP_COMMIT;
        }
        {
            uint32_t wbU = smU + OP_WS + (ch & 1) * 9216;
            uint32_t xsU = smU + OP_XS + (ch & 1) * 9216;
#pragma unroll
            for (int kg = 0; kg < 4; kg++) {
                uint32_t A[4];
                ldsm_x4(A[0], A[1], A[2], A[3],
                        wbU + (mg * 16 + (lane & 15)) * 144 + kg * 32 + (lane >> 4) * 16);
#pragma unroll
                for (int nb2 = 0; nb2 < 2; nb2++) {
                    uint32_t b0, b1, b2, b3;
                    ldsm_x4t(b0, b1, b2, b3,
                             xsU + (kg * 16 + (lane & 15)) * 144 +
                             (ng * 32 + nb2 * 16 + (lane >> 4) * 8) * 2);
                    mma16816(acc[nb2 * 2],     A, b0, b1);
                    mma16816(acc[nb2 * 2 + 1], A, b2, b3);
                }
            }
        }
    }
    __syncthreads();

    // epilogue: stage fp32 [m64][68] then fused coalesced stores
    float* Tf = (float*)sm;
    {
        int m = mg * 16 + (lane >> 2);
#pragma unroll
        for (int nb = 0; nb < 4; nb++) {
            int n = ng * 32 + nb * 8 + (lane & 3) * 2;
            float* a = acc[nb];
            *(float2*)(Tf + (size_t)m * 68 + n)       = make_float2(a[0], a[1]);
            *(float2*)(Tf + (size_t)(m + 8) * 68 + n) = make_float2(a[2], a[3]);
        }
    }
    __syncthreads();
    float g = fminf(fmaxf(gamma[0], 0.f), 1.f);
    {
        int m = t >> 2, c = t & 3;
        int mglob = ytile * 64 + m;
        float bb = bo[mglob];
        size_t base = ((size_t)(b * Cc + mglob)) * Nn + n0 + c * 16;
#pragma unroll
        for (int u = 0; u < 4; u++) {
            float4 v = *(const float4*)(Tf + (size_t)m * 68 + c * 16 + u * 4);
            float4 xr = *(const float4*)(x + base + u * 4);
            float4 o;
            o.x = g * (v.x + bb) + xr.x;
            o.y = g * (v.y + bb) + xr.y;
            o.z = g * (v.z + bb) + xr.z;
            o.w = g * (v.w + bb) + xr.w;
            *(float4*)(out + base + u * 4) = o;
        }
    }
}

// ---------------- launcher ----------------
extern "C" void kernel_launch(void* const* d_in, const int* in_sizes, int n_in,
                              void* d_out, int out_size)
{
    const float* x     = (const float*)d_in[0];
    const float* Wq    = (const float*)d_in[1];
    const float* bq    = (const float*)d_in[2];
    const float* Wk    = (const float*)d_in[3];
    const float* bk    = (const float*)d_in[4];
    const float* Wv    = (const float*)d_in[5];
    const float* bv    = (const float*)d_in[6];
    const float* Wo    = (const float*)d_in[7];
    const float* bo    = (const float*)d_in[8];
    const float* gamma = (const float*)d_in[9];
    float* out = (float*)d_out;

    cudaFuncSetAttribute(proj_kernel,    cudaFuncAttributeMaxDynamicSharedMemorySize, PJ_BYTES);
    cudaFuncSetAttribute(outproj_kernel, cudaFuncAttributeMaxDynamicSharedMemorySize, OP_BYTES);
    cudaFuncSetAttribute(attn_kernel,    cudaFuncAttributeMaxDynamicSharedMemorySize, AT_BYTES);

    cvt_kernel    <<<2184, 256>>>(x, Wq, Wk, Wv, Wo);
    proj_kernel   <<<dim3(Nn / 128, 3, Bb), 256, PJ_BYTES>>>(bq, bk, bv);
    attn_kernel   <<<dim3(Nn / BM, Bb), 512, AT_BYTES>>>();
    outproj_kernel<<<dim3(Nn / 64, 4, Bb), 256, OP_BYTES>>>(x, bo, gamma, out);
}

// round 16
// speedup vs baseline: 1.5273x; 1.0101x over previous
#include <cuda_runtime.h>
#include <cuda_bf16.h>
#include <cstdint>

#define Bb 8
#define Cc 256
#define Nn 4096
#define Dd 16
#define BM 128
#define BN 64
#define NTILES (Nn / BN)

// ---------------- scratch ----------------
__device__ __nv_bfloat16 g_Qb[(size_t)Bb * Nn * Dd];   // [B,N,16] bf16, (q+bq)*0.25*log2e
__device__ __nv_bfloat16 g_Kb[(size_t)Bb * Dd * Nn];   // [B,16,N] bf16, k+bk
__device__ __nv_bfloat16 g_VT[(size_t)Bb * Nn * Cc];   // [B,N,C] bf16
__device__ __nv_bfloat16 g_OAb[(size_t)Bb * Cc * Nn];  // [B,C,N] bf16 attn out
__device__ __nv_bfloat16 g_Xb[(size_t)Bb * Cc * Nn];   // x in bf16
__device__ __nv_bfloat16 g_Wb[139264];                 // [Wq | Wk | Wv | Wo]
#define WQ_OFF 0
#define WK_OFF 4096
#define WV_OFF 8192
#define WO_OFF 73728

// ---------------- helpers ----------------
static __device__ __forceinline__ uint32_t smem_u32(const void* p) {
    uint32_t a;
    asm("{ .reg .u64 t; cvta.to.shared.u64 t, %1; cvt.u32.u64 %0, t; }" : "=r"(a) : "l"(p));
    return a;
}
static __device__ __forceinline__ void ldsm_x4(uint32_t &r0, uint32_t &r1, uint32_t &r2, uint32_t &r3, uint32_t addr) {
    asm volatile("ldmatrix.sync.aligned.m8n8.x4.shared.b16 {%0,%1,%2,%3}, [%4];"
                 : "=r"(r0), "=r"(r1), "=r"(r2), "=r"(r3) : "r"(addr));
}
static __device__ __forceinline__ void ldsm_x4t(uint32_t &r0, uint32_t &r1, uint32_t &r2, uint32_t &r3, uint32_t addr) {
    asm volatile("ldmatrix.sync.aligned.m8n8.x4.trans.shared.b16 {%0,%1,%2,%3}, [%4];"
                 : "=r"(r0), "=r"(r1), "=r"(r2), "=r"(r3) : "r"(addr));
}
static __device__ __forceinline__ void mma16816(float* d, const uint32_t* a, uint32_t b0, uint32_t b1) {
    asm volatile("mma.sync.aligned.m16n8k16.row.col.f32.bf16.bf16.f32 "
                 "{%0,%1,%2,%3}, {%4,%5,%6,%7}, {%8,%9}, {%0,%1,%2,%3};"
                 : "+f"(d[0]), "+f"(d[1]), "+f"(d[2]), "+f"(d[3])
                 : "r"(a[0]), "r"(a[1]), "r"(a[2]), "r"(a[3]), "r"(b0), "r"(b1));
}
static __device__ __forceinline__ float ex2(float x) {
    float y; asm("ex2.approx.ftz.f32 %0, %1;" : "=f"(y) : "f"(x)); return y;
}
static __device__ __forceinline__ void sts32(uint32_t addr, uint32_t v) {
    asm volatile("st.shared.b32 [%0], %1;" :: "r"(addr), "r"(v));
}
static __device__ __forceinline__ void cp16(uint32_t dst, const void* src) {
    asm volatile("cp.async.cg.shared.global [%0], [%1], 16;" :: "r"(dst), "l"(src));
}
#define CP_COMMIT asm volatile("cp.async.commit_group;" ::: "memory")
#define CP_WAIT0  asm volatile("cp.async.wait_group 0;" ::: "memory")
#define CP_WAIT1  asm volatile("cp.async.wait_group 1;" ::: "memory")

#define QSCALE 0.36067376022224085f   // 0.25 * log2(e)
#define CLIP2  72.134752f             // 50 * log2(e)

// ================= convert x + weights to bf16 =================
__global__ __launch_bounds__(256) void cvt_kernel(
    const float* __restrict__ x,
    const float* __restrict__ Wq, const float* __restrict__ Wk,
    const float* __restrict__ Wv, const float* __restrict__ Wo)
{
    int i = blockIdx.x, t = threadIdx.x;
    if (i < 2048) {
        const float4* xs = (const float4*)x;
        uint2* xd = (uint2*)g_Xb;
#pragma unroll
        for (int j = 0; j < 4; j++) {
            int idx = i * 1024 + j * 256 + t;
            float4 v = xs[idx];
            __nv_bfloat162 p0 = __floats2bfloat162_rn(v.x, v.y);
            __nv_bfloat162 p1 = __floats2bfloat162_rn(v.z, v.w);
            uint2 u; u.x = *(uint32_t*)&p0; u.y = *(uint32_t*)&p1;
            xd[idx] = u;
        }
    } else {
        int idx4 = (i - 2048) * 256 + t;
        const float* src;
        if (idx4 < 1024)       src = Wq + idx4 * 4;
        else if (idx4 < 2048)  src = Wk + (idx4 - 1024) * 4;
        else if (idx4 < 18432) src = Wv + (idx4 - 2048) * 4;
        else                   src = Wo + (idx4 - 18432) * 4;
        float4 v = *(const float4*)src;
        __nv_bfloat162 p0 = __floats2bfloat162_rn(v.x, v.y);
        __nv_bfloat162 p1 = __floats2bfloat162_rn(v.z, v.w);
        uint2 u; u.x = *(uint32_t*)&p0; u.y = *(uint32_t*)&p1;
        ((uint2*)g_Wb)[idx4] = u;
    }
}

// ================= fused projection: V (+Q,K), m64 tiles, 3 CTAs/SM =================
// smem: W 2 x [64][144B]=9216 | X 2 x [64][272B]=17408
#define PJ_WS 0
#define PJ_XS 18432
#define PJ_BYTES (18432 + 34816)

__global__ __launch_bounds__(256, 3) void proj_kernel(
    const float* __restrict__ bq, const float* __restrict__ bk,
    const float* __restrict__ bv)
{
    extern __shared__ __align__(16) char sm[];
    uint32_t smU = smem_u32(sm);
    int t = threadIdx.x, wid = t >> 5, lane = t & 31;
    int mg = wid >> 1, ng = wid & 1;      // warp: m16 x n64
    int n0 = blockIdx.x * 128, ytile = blockIdx.y, b = blockIdx.z;
    bool active = (ytile < 4) || (mg < 2);

    int wm = t >> 2, wq = t & 3;
    const __nv_bfloat16* wsrc;
    bool wvalid = true;
    if (ytile < 4) wsrc = g_Wb + WV_OFF + (ytile * 64 + wm) * Cc;
    else {
        if (wm < 16) wsrc = g_Wb + WQ_OFF + wm * Cc;
        else if (wm < 32) wsrc = g_Wb + WK_OFF + (wm - 16) * Cc;
        else { wsrc = g_Wb; wvalid = false; }
    }
    const __nv_bfloat16* xb = g_Xb + (size_t)b * Cc * Nn + n0;
    int xk = t >> 2, xn = t & 3;

    // prologue: chunk 0
    if (wvalid) {
#pragma unroll
        for (int u = 0; u < 2; u++)
            cp16(smU + PJ_WS + wm * 144 + (wq + 4 * u) * 16, wsrc + (wq + 4 * u) * 8);
    }
#pragma unroll
    for (int u = 0; u < 4; u++)
        cp16(smU + PJ_XS + xk * 272 + (xn + 4 * u) * 16, xb + (size_t)xk * Nn + (xn + 4 * u) * 8);
    CP_COMMIT;

    float acc[8][4];
#pragma unroll
    for (int j = 0; j < 8; j++)
#pragma unroll
        for (int q = 0; q < 4; q++) acc[j][q] = 0.f;

    for (int ch = 0; ch < 4; ch++) {
        CP_WAIT0;
        __syncthreads();
        if (ch + 1 < 4) {
            int k0 = (ch + 1) * 64, sp = (ch + 1) & 1;
            if (wvalid) {
#pragma unroll
                for (int u = 0; u < 2; u++)
                    cp16(smU + PJ_WS + sp * 9216 + wm * 144 + (wq + 4 * u) * 16,
                         wsrc + k0 + (wq + 4 * u) * 8);
            }
#pragma unroll
            for (int u = 0; u < 4; u++)
                cp16(smU + PJ_XS + sp * 17408 + xk * 272 + (xn + 4 * u) * 16,
                     xb + (size_t)(k0 + xk) * Nn + (xn + 4 * u) * 8);
            CP_COMMIT;
        }
        if (active) {
            uint32_t wbU = smU + PJ_WS + (ch & 1) * 9216;
            uint32_t xsU = smU + PJ_XS + (ch & 1) * 17408;
#pragma unroll
            for (int kg = 0; kg < 4; kg++) {
                uint32_t A[4];
                ldsm_x4(A[0], A[1], A[2], A[3],
                        wbU + (mg * 16 + (lane & 15)) * 144 + kg * 32 + (lane >> 4) * 16);
#pragma unroll
                for (int nb2 = 0; nb2 < 4; nb2++) {
                    uint32_t b0, b1, b2, b3;
                    ldsm_x4t(b0, b1, b2, b3,
                             xsU + (kg * 16 + (lane & 15)) * 272 +
                             (ng * 64 + nb2 * 16 + (lane >> 4) * 8) * 2);
                    mma16816(acc[nb2 * 2],     A, b0, b1);
                    mma16816(acc[nb2 * 2 + 1], A, b2, b3);
                }
            }
        }
    }
    __syncthreads();

    if (ytile < 4) {
        // V epilogue: stage bf16 transposed [n128][m pad 72]
        __nv_bfloat16* Tb = (__nv_bfloat16*)sm;
        {
            int m = mg * 16 + (lane >> 2);
            float bv0 = bv[ytile * 64 + m];
            float bv1 = bv[ytile * 64 + m + 8];
#pragma unroll
            for (int nb = 0; nb < 8; nb++) {
                int n = ng * 64 + nb * 8 + (lane & 3) * 2;
                float* a = acc[nb];
                Tb[(size_t)n * 72 + m]           = __float2bfloat16(a[0] + bv0);
                Tb[(size_t)(n + 1) * 72 + m]     = __float2bfloat16(a[1] + bv0);
                Tb[(size_t)n * 72 + m + 8]       = __float2bfloat16(a[2] + bv1);
                Tb[(size_t)(n + 1) * 72 + m + 8] = __float2bfloat16(a[3] + bv1);
            }
        }
        __syncthreads();
        int n = t >> 1, c = t & 1;
        const uint4* src = (const uint4*)((const char*)Tb + n * 144 + c * 64);
        uint4* dst = (uint4*)((char*)(g_VT + ((size_t)(b * Nn + n0 + n)) * Cc + ytile * 64) + c * 64);
#pragma unroll
        for (int u = 0; u < 4; u++) dst[u] = src[u];
    } else {
        // QK epilogue: mg0 warps = Q rows 0-15, mg1 warps = K rows 0-15
        __nv_bfloat16* Qt = (__nv_bfloat16*)sm;              // [128][24] = 6144B
        __nv_bfloat16* Kt = (__nv_bfloat16*)(sm + 8192);     // [16][136] = 4352B
        if (mg == 0) {
            int d = lane >> 2;
            float b0 = bq[d], b1 = bq[d + 8];
#pragma unroll
            for (int nb = 0; nb < 8; nb++) {
                int n = ng * 64 + nb * 8 + (lane & 3) * 2;
                float* a = acc[nb];
                Qt[(size_t)n * 24 + d]           = __float2bfloat16((a[0] + b0) * QSCALE);
                Qt[(size_t)(n + 1) * 24 + d]     = __float2bfloat16((a[1] + b0) * QSCALE);
                Qt[(size_t)n * 24 + d + 8]       = __float2bfloat16((a[2] + b1) * QSCALE);
                Qt[(size_t)(n + 1) * 24 + d + 8] = __float2bfloat16((a[3] + b1) * QSCALE);
            }
        } else if (mg == 1) {
            int d = lane >> 2;
            float b0 = bk[d], b1 = bk[d + 8];
#pragma unroll
            for (int nb = 0; nb < 8; nb++) {
                int n = ng * 64 + nb * 8 + (lane & 3) * 2;
                float* a = acc[nb];
                Kt[(size_t)d * 136 + n]           = __float2bfloat16(a[0] + b0);
                Kt[(size_t)d * 136 + n + 1]       = __float2bfloat16(a[1] + b0);
                Kt[(size_t)(d + 8) * 136 + n]     = __float2bfloat16(a[2] + b1);
                Kt[(size_t)(d + 8) * 136 + n + 1] = __float2bfloat16(a[3] + b1);
            }
        }
        __syncthreads();
        {
            int n = t >> 1, c = t & 1;
            const uint4* src = (const uint4*)((const char*)Qt + n * 48 + c * 16);
            uint4* dst = (uint4*)((char*)(g_Qb + ((size_t)(b * Nn + n0 + n)) * Dd) + c * 16);
            dst[0] = src[0];
        }
        {
            int d = t >> 4, c = t & 15;
            const uint4* src = (const uint4*)((const char*)Kt + d * 272 + c * 16);
            uint4* dst = (uint4*)((char*)(g_Kb + ((size_t)(b * Dd + d)) * Nn + n0) + c * 16);
            dst[0] = src[0];
        }
    }
}

// ================= fused attention: pipelined split-role FA2 =================
#define AT_VS 0
#define AT_KS 135168
#define AT_QS 144384
#define AT_PS 150528
#define AT_RS 187392
#define AT_BYTES 188416

__global__ __launch_bounds__(512, 1) void attn_kernel()
{
    extern __shared__ __align__(16) char sm[];
    uint32_t smU = smem_u32(sm);
    int t = threadIdx.x, b = blockIdx.y, m0 = blockIdx.x * BM;
    int wid = t >> 5, lane = t & 31;
    int mg = wid >> 1, jg = wid & 1;
    int mg2 = wid >> 2, eg = wid & 3;

    const char* vb = (const char*)(g_VT + (size_t)b * Nn * Cc);
    const char* kb = (const char*)(g_Kb + (size_t)b * Dd * Nn);
    const char* qb = (const char*)(g_Qb + ((size_t)b * Nn + m0) * Dd);

    int vj = t >> 3, vc = t & 7;
    int kd = t >> 3, kc = t & 7;

#pragma unroll
    for (int st = 0; st < 2; st++) {
        int n0 = st * BN;
        uint32_t dst = smU + AT_VS + st * 33792 + vj * 528 + vc * 16;
        const char* src = vb + ((size_t)(n0 + vj)) * 512 + vc * 16;
#pragma unroll
        for (int u = 0; u < 4; u++) cp16(dst + u * 128, src + u * 128);
        if (t < 128) cp16(smU + AT_KS + st * 2304 + kd * 144 + kc * 16,
                          kb + (size_t)kd * (Nn * 2) + n0 * 2 + kc * 16);
        if (st == 0 && t < 256) {
            int m = t >> 1, c = t & 1;
            cp16(smU + AT_QS + m * 48 + c * 16, qb + m * 32 + c * 16);
        }
        CP_COMMIT;
    }

    float acc[2][8][4];
#pragma unroll
    for (int i = 0; i < 2; i++)
#pragma unroll
        for (int j = 0; j < 8; j++)
#pragma unroll
            for (int q = 0; q < 4; q++) acc[i][j][q] = 0.f;

    uint32_t qa[4];
    float rs0 = 0.f, rs1 = 0.f;

    uint32_t ps_st0 = smU + AT_PS + (mg * 16 + (lane >> 2)) * 144 + (jg * 32 + (lane & 3) * 2) * 2;
    uint32_t ps_ld0 = smU + AT_PS +
        (uint32_t)(mg2 * 32 + (lane & 7) + ((lane >> 3) & 1) * 8) * 144 + (lane >> 4) * 16;

    CP_WAIT1;
    __syncthreads();
    {
        uint32_t qaddr = smU + AT_QS +
            (mg * 16 + (lane & 7) + ((lane >> 3) & 1) * 8) * 48 + (lane >> 4) * 16;
        ldsm_x4(qa[0], qa[1], qa[2], qa[3], qaddr);
    }
    {
        uint32_t ksb = smU + AT_KS;
        uint32_t pst = ps_st0;
#pragma unroll
        for (int nb2 = 0; nb2 < 2; nb2++) {
            float c[2][4];
#pragma unroll
            for (int h = 0; h < 2; h++)
#pragma unroll
                for (int j = 0; j < 4; j++) c[h][j] = 0.f;
            uint32_t b0, b1, b2, b3;
            uint32_t ka = ksb + (lane & 15) * 144 + (jg * 32 + nb2 * 16 + (lane >> 4) * 8) * 2;
            ldsm_x4t(b0, b1, b2, b3, ka);
            mma16816(c[0], qa, b0, b1);
            mma16816(c[1], qa, b2, b3);
#pragma unroll
            for (int h = 0; h < 2; h++) {
                float e0 = ex2(fminf(fmaxf(c[h][0], -CLIP2), CLIP2));
                float e1 = ex2(fminf(fmaxf(c[h][1], -CLIP2), CLIP2));
                float e2 = ex2(fminf(fmaxf(c[h][2], -CLIP2), CLIP2));
                float e3 = ex2(fminf(fmaxf(c[h][3], -CLIP2), CLIP2));
                rs0 += e0 + e1;
                rs1 += e2 + e3;
                __nv_bfloat162 lo = __floats2bfloat162_rn(e0, e1);
                __nv_bfloat162 hi = __floats2bfloat162_rn(e2, e3);
                sts32(pst + nb2 * 32 + h * 16, *(uint32_t*)&lo);
                sts32(pst + nb2 * 32 + h * 16 + 8 * 144, *(uint32_t*)&hi);
            }
        }
    }

    for (int it = 0; it < NTILES; it++) {
        if (it + 2 < NTILES) {
            int n0 = (it + 2) * BN;
            int sp = (it + 2) & 3;
            uint32_t dst = smU + AT_VS + sp * 33792 + vj * 528 + vc * 16;
            const char* src = vb + ((size_t)(n0 + vj)) * 512 + vc * 16;
#pragma unroll
            for (int u = 0; u < 4; u++) cp16(dst + u * 128, src + u * 128);
            if (t < 128) cp16(smU + AT_KS + sp * 2304 + kd * 144 + kc * 16,
                              kb + (size_t)kd * (Nn * 2) + n0 * 2 + kc * 16);
        }
        CP_COMMIT;
        CP_WAIT1;
        __syncthreads();

        if (it + 1 < NTILES) {
            uint32_t ksb = smU + AT_KS + ((it + 1) & 3) * 2304;
            uint32_t pst = ps_st0 + ((it + 1) & 1) * 18432;
#pragma unroll
            for (int nb2 = 0; nb2 < 2; nb2++) {
                float c[2][4];
#pragma unroll
                for (int h = 0; h < 2; h++)
#pragma unroll
                    for (int j = 0; j < 4; j++) c[h][j] = 0.f;
                uint32_t b0, b1, b2, b3;
                uint32_t ka = ksb + (lane & 15) * 144 + (jg * 32 + nb2 * 16 + (lane >> 4) * 8) * 2;
                ldsm_x4t(b0, b1, b2, b3, ka);
                mma16816(c[0], qa, b0, b1);
                mma16816(c[1], qa, b2, b3);
#pragma unroll
                for (int h = 0; h < 2; h++) {
                    float e0 = ex2(fminf(fmaxf(c[h][0], -CLIP2), CLIP2));
                    float e1 = ex2(fminf(fmaxf(c[h][1], -CLIP2), CLIP2));
                    float e2 = ex2(fminf(fmaxf(c[h][2], -CLIP2), CLIP2));
                    float e3 = ex2(fminf(fmaxf(c[h][3], -CLIP2), CLIP2));
                    rs0 += e0 + e1;
                    rs1 += e2 + e3;
                    __nv_bfloat162 lo = __floats2bfloat162_rn(e0, e1);
                    __nv_bfloat162 hi = __floats2bfloat162_rn(e2, e3);
                    sts32(pst + nb2 * 32 + h * 16, *(uint32_t*)&lo);
                    sts32(pst + nb2 * 32 + h * 16 + 8 * 144, *(uint32_t*)&hi);
                }
            }
        }

        {
            uint32_t vsb = smU + AT_VS + (it & 3) * 33792;
            uint32_t pld = ps_ld0 + (it & 1) * 18432;
#pragma unroll
            for (int kg = 0; kg < 4; kg++) {
                uint32_t pA[2][4];
#pragma unroll
                for (int mi = 0; mi < 2; mi++)
                    ldsm_x4(pA[mi][0], pA[mi][1], pA[mi][2], pA[mi][3],
                            pld + mi * (16 * 144) + kg * 32);
#pragma unroll
                for (int eb2 = 0; eb2 < 4; eb2++) {
                    uint32_t b0, b1, b2, b3;
                    uint32_t va = vsb + (kg * 16 + (lane & 15)) * 528 +
                                  (eg * 64 + eb2 * 16 + (lane >> 4) * 8) * 2;
                    ldsm_x4t(b0, b1, b2, b3, va);
                    mma16816(acc[0][eb2 * 2],     pA[0], b0, b1);
                    mma16816(acc[0][eb2 * 2 + 1], pA[0], b2, b3);
                    mma16816(acc[1][eb2 * 2],     pA[1], b0, b1);
                    mma16816(acc[1][eb2 * 2 + 1], pA[1], b2, b3);
                }
            }
        }
    }

    rs0 += __shfl_xor_sync(0xffffffffu, rs0, 1);
    rs0 += __shfl_xor_sync(0xffffffffu, rs0, 2);
    rs1 += __shfl_xor_sync(0xffffffffu, rs1, 1);
    rs1 += __shfl_xor_sync(0xffffffffu, rs1, 2);
    float* rs_s = (float*)(sm + AT_RS);
    if ((lane & 3) == 0) {
        rs_s[jg * 128 + mg * 16 + (lane >> 2)]     = rs0;
        rs_s[jg * 128 + mg * 16 + (lane >> 2) + 8] = rs1;
    }

    float* Tf = (float*)sm;
    __nv_bfloat16* ob = g_OAb + (size_t)b * Cc * Nn + m0;
    int r = lane >> 2, q = lane & 3;
#pragma unroll
    for (int h = 0; h < 2; h++) {
        __syncthreads();
        if ((eg >> 1) == h) {
            int ebase = (eg & 1) * 64;
#pragma unroll
            for (int mi = 0; mi < 2; mi++) {
                int ml = mg2 * 32 + mi * 16 + r;
                float inv0 = 1.f / (rs_s[ml]     + rs_s[128 + ml]);
                float inv1 = 1.f / (rs_s[ml + 8] + rs_s[128 + ml + 8]);
#pragma unroll
                for (int nb = 0; nb < 8; nb++) {
                    int e = ebase + nb * 8 + 2 * q;
                    float* a = acc[mi][nb];
                    Tf[(size_t)e * 132 + ml]           = a[0] * inv0;
                    Tf[(size_t)(e + 1) * 132 + ml]     = a[1] * inv0;
                    Tf[(size_t)e * 132 + ml + 8]       = a[2] * inv1;
                    Tf[(size_t)(e + 1) * 132 + ml + 8] = a[3] * inv1;
                }
            }
        }
        __syncthreads();
#pragma unroll
        for (int rr = 0; rr < 8; rr++) {
            int e = wid * 8 + rr;
            const float* srcr = Tf + (size_t)e * 132;
            __nv_bfloat16* dstr = ob + (size_t)(h * 128 + e) * Nn;
#pragma unroll
            for (int c = 0; c < 2; c++) {
                dstr[c * 64 + lane]      = __float2bfloat16(srcr[c * 64 + lane]);
                dstr[c * 64 + 32 + lane] = __float2bfloat16(srcr[c * 64 + 32 + lane]);
            }
        }
    }
}

// ================= output projection: m64 x n64 tiles, 4 CTAs/SM =================
#define OP_WS 0
#define OP_XS 18432
#define OP_BYTES 36864

__global__ __launch_bounds__(256, 4) void outproj_kernel(
    const float* __restrict__ x,
    const float* __restrict__ bo,
    const float* __restrict__ gamma, float* __restrict__ out)
{
    extern __shared__ __align__(16) char sm[];
    uint32_t smU = smem_u32(sm);
    int t = threadIdx.x, wid = t >> 5, lane = t & 31;
    int mg = wid >> 1, ng = wid & 1;
    int n0 = blockIdx.x * 64, ytile = blockIdx.y, b = blockIdx.z;

    int wm = t >> 2, wq = t & 3;
    const __nv_bfloat16* wsrc = g_Wb + WO_OFF + (ytile * 64 + wm) * Cc;
    const __nv_bfloat16* xb = g_OAb + (size_t)b * Cc * Nn + n0;
    int xk = t >> 2, xn = t & 3;

#pragma unroll
    for (int u = 0; u < 2; u++)
        cp16(smU + OP_WS + wm * 144 + (wq + 4 * u) * 16, wsrc + (wq + 4 * u) * 8);
#pragma unroll
    for (int u = 0; u < 2; u++)
        cp16(smU + OP_XS + xk * 144 + (xn + 4 * u) * 16, xb + (size_t)xk * Nn + (xn + 4 * u) * 8);
    CP_COMMIT;

    float acc[4][4];
#pragma unroll
    for (int j = 0; j < 4; j++)
#pragma unroll
        for (int q = 0; q < 4; q++) acc[j][q] = 0.f;

    for (int ch = 0; ch < 4; ch++) {
        CP_WAIT0;
        __syncthreads();
        if (ch + 1 < 4) {
            int k0 = (ch + 1) * 64, sp = (ch + 1) & 1;
#pragma unroll
            for (int u = 0; u < 2; u++)
                cp16(smU + OP_WS + sp * 9216 + wm * 144 + (wq + 4 * u) * 16,
                     wsrc + k0 + (wq + 4 * u) * 8);
#pragma unroll
            for (int u = 0; u < 2; u++)
                cp16(smU + OP_XS + sp * 9216 + xk * 144 + (xn + 4 * u) * 16,
                     xb + (size_t)(k0 + xk) * Nn + (xn + 4 * u) * 8);
            CP_COMMIT;
        }
        {
            uint32_t wbU = smU + OP_WS + (ch & 1) * 9216;
            uint32_t xsU = smU + OP_XS + (ch & 1) * 9216;
#pragma unroll
            for (int kg = 0; kg < 4; kg++) {
                uint32_t A[4];
                ldsm_x4(A[0], A[1], A[2], A[3],
                        wbU + (mg * 16 + (lane & 15)) * 144 + kg * 32 + (lane >> 4) * 16);
#pragma unroll
                for (int nb2 = 0; nb2 < 2; nb2++) {
                    uint32_t b0, b1, b2, b3;
                    ldsm_x4t(b0, b1, b2, b3,
                             xsU + (kg * 16 + (lane & 15)) * 144 +
                             (ng * 32 + nb2 * 16 + (lane >> 4) * 8) * 2);
                    mma16816(acc[nb2 * 2],     A, b0, b1);
                    mma16816(acc[nb2 * 2 + 1], A, b2, b3);
                }
            }
        }
    }
    __syncthreads();

    float* Tf = (float*)sm;
    {
        int m = mg * 16 + (lane >> 2);
#pragma unroll
        for (int nb = 0; nb < 4; nb++) {
            int n = ng * 32 + nb * 8 + (lane & 3) * 2;
            float* a = acc[nb];
            *(float2*)(Tf + (size_t)m * 68 + n)       = make_float2(a[0], a[1]);
            *(float2*)(Tf + (size_t)(m + 8) * 68 + n) = make_float2(a[2], a[3]);
        }
    }
    __syncthreads();
    float g = fminf(fmaxf(gamma[0], 0.f), 1.f);
    {
        int m = t >> 2, c = t & 3;
        int mglob = ytile * 64 + m;
        float bb = bo[mglob];
        size_t base = ((size_t)(b * Cc + mglob)) * Nn + n0 + c * 16;
#pragma unroll
        for (int u = 0; u < 4; u++) {
            float4 v = *(const float4*)(Tf + (size_t)m * 68 + c * 16 + u * 4);
            float4 xr = *(const float4*)(x + base + u * 4);
            float4 o;
            o.x = g * (v.x + bb) + xr.x;
            o.y = g * (v.y + bb) + xr.y;
            o.z = g * (v.z + bb) + xr.z;
            o.w = g * (v.w + bb) + xr.w;
            *(float4*)(out + base + u * 4) = o;
        }
    }
}

// ---------------- launcher ----------------
extern "C" void kernel_launch(void* const* d_in, const int* in_sizes, int n_in,
                              void* d_out, int out_size)
{
    const float* x     = (const float*)d_in[0];
    const float* Wq    = (const float*)d_in[1];
    const float* bq    = (const float*)d_in[2];
    const float* Wk    = (const float*)d_in[3];
    const float* bk    = (const float*)d_in[4];
    const float* Wv    = (const float*)d_in[5];
    const float* bv    = (const float*)d_in[6];
    const float* Wo    = (const float*)d_in[7];
    const float* bo    = (const float*)d_in[8];
    const float* gamma = (const float*)d_in[9];
    float* out = (float*)d_out;

    cudaFuncSetAttribute(proj_kernel,    cudaFuncAttributeMaxDynamicSharedMemorySize, PJ_BYTES);
    cudaFuncSetAttribute(outproj_kernel, cudaFuncAttributeMaxDynamicSharedMemorySize, OP_BYTES);
    cudaFuncSetAttribute(attn_kernel,    cudaFuncAttributeMaxDynamicSharedMemorySize, AT_BYTES);

    cvt_kernel    <<<2184, 256>>>(x, Wq, Wk, Wv, Wo);
    proj_kernel   <<<dim3(Nn / 128, 5, Bb), 256, PJ_BYTES>>>(bq, bk, bv);
    attn_kernel   <<<dim3(Nn / BM, Bb), 512, AT_BYTES>>>();
    outproj_kernel<<<dim3(Nn / 64, 4, Bb), 256, OP_BYTES>>>(x, bo, gamma, out);
}

// round 17
// speedup vs baseline: 1.5346x; 1.0048x over previous
#include <cuda_runtime.h>
#include <cuda_bf16.h>
#include <cstdint>

#define Bb 8
#define Cc 256
#define Nn 4096
#define Dd 16
#define BM 128
#define BN 64
#define NTILES (Nn / BN)

// ---------------- scratch ----------------
__device__ __nv_bfloat16 g_Qb[(size_t)Bb * Nn * Dd];   // [B,N,16] bf16, (q+bq)*0.25*log2e
__device__ __nv_bfloat16 g_Kb[(size_t)Bb * Dd * Nn];   // [B,16,N] bf16, k+bk
__device__ __nv_bfloat16 g_VT[(size_t)Bb * Nn * Cc];   // [B,N,C] bf16
__device__ __nv_bfloat16 g_OAb[(size_t)Bb * Cc * Nn];  // [B,C,N] bf16 attn out
__device__ __nv_bfloat16 g_Xb[(size_t)Bb * Cc * Nn];   // x in bf16
__device__ __nv_bfloat16 g_Wb[139264];                 // [Wq | Wk | Wv | Wo]
#define WQ_OFF 0
#define WK_OFF 4096
#define WV_OFF 8192
#define WO_OFF 73728

// ---------------- helpers ----------------
static __device__ __forceinline__ uint32_t smem_u32(const void* p) {
    uint32_t a;
    asm("{ .reg .u64 t; cvta.to.shared.u64 t, %1; cvt.u32.u64 %0, t; }" : "=r"(a) : "l"(p));
    return a;
}
static __device__ __forceinline__ void ldsm_x4(uint32_t &r0, uint32_t &r1, uint32_t &r2, uint32_t &r3, uint32_t addr) {
    asm volatile("ldmatrix.sync.aligned.m8n8.x4.shared.b16 {%0,%1,%2,%3}, [%4];"
                 : "=r"(r0), "=r"(r1), "=r"(r2), "=r"(r3) : "r"(addr));
}
static __device__ __forceinline__ void ldsm_x4t(uint32_t &r0, uint32_t &r1, uint32_t &r2, uint32_t &r3, uint32_t addr) {
    asm volatile("ldmatrix.sync.aligned.m8n8.x4.trans.shared.b16 {%0,%1,%2,%3}, [%4];"
                 : "=r"(r0), "=r"(r1), "=r"(r2), "=r"(r3) : "r"(addr));
}
static __device__ __forceinline__ void mma16816(float* d, const uint32_t* a, uint32_t b0, uint32_t b1) {
    asm volatile("mma.sync.aligned.m16n8k16.row.col.f32.bf16.bf16.f32 "
                 "{%0,%1,%2,%3}, {%4,%5,%6,%7}, {%8,%9}, {%0,%1,%2,%3};"
                 : "+f"(d[0]), "+f"(d[1]), "+f"(d[2]), "+f"(d[3])
                 : "r"(a[0]), "r"(a[1]), "r"(a[2]), "r"(a[3]), "r"(b0), "r"(b1));
}
static __device__ __forceinline__ float ex2(float x) {
    float y; asm("ex2.approx.ftz.f32 %0, %1;" : "=f"(y) : "f"(x)); return y;
}
static __device__ __forceinline__ void sts32(uint32_t addr, uint32_t v) {
    asm volatile("st.shared.b32 [%0], %1;" :: "r"(addr), "r"(v));
}
static __device__ __forceinline__ void cp16(uint32_t dst, const void* src) {
    asm volatile("cp.async.cg.shared.global [%0], [%1], 16;" :: "r"(dst), "l"(src));
}
#define CP_COMMIT asm volatile("cp.async.commit_group;" ::: "memory")
#define CP_WAIT0  asm volatile("cp.async.wait_group 0;" ::: "memory")
#define CP_WAIT1  asm volatile("cp.async.wait_group 1;" ::: "memory")

#define QSCALE 0.36067376022224085f   // 0.25 * log2(e)
#define CLIP2  72.134752f             // 50 * log2(e)

// ================= convert x + weights to bf16 =================
__global__ __launch_bounds__(256) void cvt_kernel(
    const float* __restrict__ x,
    const float* __restrict__ Wq, const float* __restrict__ Wk,
    const float* __restrict__ Wv, const float* __restrict__ Wo)
{
    int i = blockIdx.x, t = threadIdx.x;
    if (i < 2048) {
        const float4* xs = (const float4*)x;
        uint2* xd = (uint2*)g_Xb;
#pragma unroll
        for (int j = 0; j < 4; j++) {
            int idx = i * 1024 + j * 256 + t;
            float4 v = xs[idx];
            __nv_bfloat162 p0 = __floats2bfloat162_rn(v.x, v.y);
            __nv_bfloat162 p1 = __floats2bfloat162_rn(v.z, v.w);
            uint2 u; u.x = *(uint32_t*)&p0; u.y = *(uint32_t*)&p1;
            xd[idx] = u;
        }
    } else {
        int idx4 = (i - 2048) * 256 + t;
        const float* src;
        if (idx4 < 1024)       src = Wq + idx4 * 4;
        else if (idx4 < 2048)  src = Wk + (idx4 - 1024) * 4;
        else if (idx4 < 18432) src = Wv + (idx4 - 2048) * 4;
        else                   src = Wo + (idx4 - 18432) * 4;
        float4 v = *(const float4*)src;
        __nv_bfloat162 p0 = __floats2bfloat162_rn(v.x, v.y);
        __nv_bfloat162 p1 = __floats2bfloat162_rn(v.z, v.w);
        uint2 u; u.x = *(uint32_t*)&p0; u.y = *(uint32_t*)&p1;
        ((uint2*)g_Wb)[idx4] = u;
    }
}

// ================= fused projection: V (+Q,K), m64 tiles, 3 CTAs/SM =================
#define PJ_WS 0
#define PJ_XS 18432
#define PJ_BYTES (18432 + 34816)

__global__ __launch_bounds__(256, 3) void proj_kernel(
    const float* __restrict__ bq, const float* __restrict__ bk,
    const float* __restrict__ bv)
{
    extern __shared__ __align__(16) char sm[];
    uint32_t smU = smem_u32(sm);
    int t = threadIdx.x, wid = t >> 5, lane = t & 31;
    int mg = wid >> 1, ng = wid & 1;
    int n0 = blockIdx.x * 128, ytile = blockIdx.y, b = blockIdx.z;
    bool active = (ytile < 4) || (mg < 2);

    int wm = t >> 2, wq = t & 3;
    const __nv_bfloat16* wsrc;
    bool wvalid = true;
    if (ytile < 4) wsrc = g_Wb + WV_OFF + (ytile * 64 + wm) * Cc;
    else {
        if (wm < 16) wsrc = g_Wb + WQ_OFF + wm * Cc;
        else if (wm < 32) wsrc = g_Wb + WK_OFF + (wm - 16) * Cc;
        else { wsrc = g_Wb; wvalid = false; }
    }
    const __nv_bfloat16* xb = g_Xb + (size_t)b * Cc * Nn + n0;
    int xk = t >> 2, xn = t & 3;

    if (wvalid) {
#pragma unroll
        for (int u = 0; u < 2; u++)
            cp16(smU + PJ_WS + wm * 144 + (wq + 4 * u) * 16, wsrc + (wq + 4 * u) * 8);
    }
#pragma unroll
    for (int u = 0; u < 4; u++)
        cp16(smU + PJ_XS + xk * 272 + (xn + 4 * u) * 16, xb + (size_t)xk * Nn + (xn + 4 * u) * 8);
    CP_COMMIT;

    float acc[8][4];
#pragma unroll
    for (int j = 0; j < 8; j++)
#pragma unroll
        for (int q = 0; q < 4; q++) acc[j][q] = 0.f;

    for (int ch = 0; ch < 4; ch++) {
        CP_WAIT0;
        __syncthreads();
        if (ch + 1 < 4) {
            int k0 = (ch + 1) * 64, sp = (ch + 1) & 1;
            if (wvalid) {
#pragma unroll
                for (int u = 0; u < 2; u++)
                    cp16(smU + PJ_WS + sp * 9216 + wm * 144 + (wq + 4 * u) * 16,
                         wsrc + k0 + (wq + 4 * u) * 8);
            }
#pragma unroll
            for (int u = 0; u < 4; u++)
                cp16(smU + PJ_XS + sp * 17408 + xk * 272 + (xn + 4 * u) * 16,
                     xb + (size_t)(k0 + xk) * Nn + (xn + 4 * u) * 8);
            CP_COMMIT;
        }
        if (active) {
            uint32_t wbU = smU + PJ_WS + (ch & 1) * 9216;
            uint32_t xsU = smU + PJ_XS + (ch & 1) * 17408;
#pragma unroll
            for (int kg = 0; kg < 4; kg++) {
                uint32_t A[4];
                ldsm_x4(A[0], A[1], A[2], A[3],
                        wbU + (mg * 16 + (lane & 15)) * 144 + kg * 32 + (lane >> 4) * 16);
#pragma unroll
                for (int nb2 = 0; nb2 < 4; nb2++) {
                    uint32_t b0, b1, b2, b3;
                    ldsm_x4t(b0, b1, b2, b3,
                             xsU + (kg * 16 + (lane & 15)) * 272 +
                             (ng * 64 + nb2 * 16 + (lane >> 4) * 8) * 2);
                    mma16816(acc[nb2 * 2],     A, b0, b1);
                    mma16816(acc[nb2 * 2 + 1], A, b2, b3);
                }
            }
        }
    }
    __syncthreads();

    if (ytile < 4) {
        __nv_bfloat16* Tb = (__nv_bfloat16*)sm;
        {
            int m = mg * 16 + (lane >> 2);
            float bv0 = bv[ytile * 64 + m];
            float bv1 = bv[ytile * 64 + m + 8];
#pragma unroll
            for (int nb = 0; nb < 8; nb++) {
                int n = ng * 64 + nb * 8 + (lane & 3) * 2;
                float* a = acc[nb];
                Tb[(size_t)n * 72 + m]           = __float2bfloat16(a[0] + bv0);
                Tb[(size_t)(n + 1) * 72 + m]     = __float2bfloat16(a[1] + bv0);
                Tb[(size_t)n * 72 + m + 8]       = __float2bfloat16(a[2] + bv1);
                Tb[(size_t)(n + 1) * 72 + m + 8] = __float2bfloat16(a[3] + bv1);
            }
        }
        __syncthreads();
        int n = t >> 1, c = t & 1;
        const uint4* src = (const uint4*)((const char*)Tb + n * 144 + c * 64);
        uint4* dst = (uint4*)((char*)(g_VT + ((size_t)(b * Nn + n0 + n)) * Cc + ytile * 64) + c * 64);
#pragma unroll
        for (int u = 0; u < 4; u++) dst[u] = src[u];
    } else {
        __nv_bfloat16* Qt = (__nv_bfloat16*)sm;              // [128][24]
        __nv_bfloat16* Kt = (__nv_bfloat16*)(sm + 8192);     // [16][136]
        if (mg == 0) {
            int d = lane >> 2;
            float b0 = bq[d], b1 = bq[d + 8];
#pragma unroll
            for (int nb = 0; nb < 8; nb++) {
                int n = ng * 64 + nb * 8 + (lane & 3) * 2;
                float* a = acc[nb];
                Qt[(size_t)n * 24 + d]           = __float2bfloat16((a[0] + b0) * QSCALE);
                Qt[(size_t)(n + 1) * 24 + d]     = __float2bfloat16((a[1] + b0) * QSCALE);
                Qt[(size_t)n * 24 + d + 8]       = __float2bfloat16((a[2] + b1) * QSCALE);
                Qt[(size_t)(n + 1) * 24 + d + 8] = __float2bfloat16((a[3] + b1) * QSCALE);
            }
        } else if (mg == 1) {
            int d = lane >> 2;
            float b0 = bk[d], b1 = bk[d + 8];
#pragma unroll
            for (int nb = 0; nb < 8; nb++) {
                int n = ng * 64 + nb * 8 + (lane & 3) * 2;
                float* a = acc[nb];
                Kt[(size_t)d * 136 + n]           = __float2bfloat16(a[0] + b0);
                Kt[(size_t)d * 136 + n + 1]       = __float2bfloat16(a[1] + b0);
                Kt[(size_t)(d + 8) * 136 + n]     = __float2bfloat16(a[2] + b1);
                Kt[(size_t)(d + 8) * 136 + n + 1] = __float2bfloat16(a[3] + b1);
            }
        }
        __syncthreads();
        {
            int n = t >> 1, c = t & 1;
            const uint4* src = (const uint4*)((const char*)Qt + n * 48 + c * 16);
            uint4* dst = (uint4*)((char*)(g_Qb + ((size_t)(b * Nn + n0 + n)) * Dd) + c * 16);
            dst[0] = src[0];
        }
        {
            int d = t >> 4, c = t & 15;
            const uint4* src = (const uint4*)((const char*)Kt + d * 272 + c * 16);
            uint4* dst = (uint4*)((char*)(g_Kb + ((size_t)(b * Dd + d)) * Nn + n0) + c * 16);
            dst[0] = src[0];
        }
    }
}

// ================= fused attention: pipelined split-role FA2 =================
#define AT_VS 0
#define AT_KS 135168
#define AT_QS 144384
#define AT_PS 150528
#define AT_RS 187392
#define AT_BYTES 188416

__global__ __launch_bounds__(512, 1) void attn_kernel()
{
    extern __shared__ __align__(16) char sm[];
    uint32_t smU = smem_u32(sm);
    int t = threadIdx.x, b = blockIdx.y, m0 = blockIdx.x * BM;
    int wid = t >> 5, lane = t & 31;
    int mg = wid >> 1, jg = wid & 1;
    int mg2 = wid >> 2, eg = wid & 3;

    const char* vb = (const char*)(g_VT + (size_t)b * Nn * Cc);
    const char* kb = (const char*)(g_Kb + (size_t)b * Dd * Nn);
    const char* qb = (const char*)(g_Qb + ((size_t)b * Nn + m0) * Dd);

    int vj = t >> 3, vc = t & 7;
    int kd = t >> 3, kc = t & 7;

#pragma unroll
    for (int st = 0; st < 2; st++) {
        int n0 = st * BN;
        uint32_t dst = smU + AT_VS + st * 33792 + vj * 528 + vc * 16;
        const char* src = vb + ((size_t)(n0 + vj)) * 512 + vc * 16;
#pragma unroll
        for (int u = 0; u < 4; u++) cp16(dst + u * 128, src + u * 128);
        if (t < 128) cp16(smU + AT_KS + st * 2304 + kd * 144 + kc * 16,
                          kb + (size_t)kd * (Nn * 2) + n0 * 2 + kc * 16);
        if (st == 0 && t < 256) {
            int m = t >> 1, c = t & 1;
            cp16(smU + AT_QS + m * 48 + c * 16, qb + m * 32 + c * 16);
        }
        CP_COMMIT;
    }

    float acc[2][8][4];
#pragma unroll
    for (int i = 0; i < 2; i++)
#pragma unroll
        for (int j = 0; j < 8; j++)
#pragma unroll
            for (int q = 0; q < 4; q++) acc[i][j][q] = 0.f;

    uint32_t qa[4];
    float rs0 = 0.f, rs1 = 0.f;

    uint32_t ps_st0 = smU + AT_PS + (mg * 16 + (lane >> 2)) * 144 + (jg * 32 + (lane & 3) * 2) * 2;
    uint32_t ps_ld0 = smU + AT_PS +
        (uint32_t)(mg2 * 32 + (lane & 7) + ((lane >> 3) & 1) * 8) * 144 + (lane >> 4) * 16;

    CP_WAIT1;
    __syncthreads();
    {
        uint32_t qaddr = smU + AT_QS +
            (mg * 16 + (lane & 7) + ((lane >> 3) & 1) * 8) * 48 + (lane >> 4) * 16;
        ldsm_x4(qa[0], qa[1], qa[2], qa[3], qaddr);
    }
    {
        uint32_t ksb = smU + AT_KS;
        uint32_t pst = ps_st0;
#pragma unroll
        for (int nb2 = 0; nb2 < 2; nb2++) {
            float c[2][4];
#pragma unroll
            for (int h = 0; h < 2; h++)
#pragma unroll
                for (int j = 0; j < 4; j++) c[h][j] = 0.f;
            uint32_t b0, b1, b2, b3;
            uint32_t ka = ksb + (lane & 15) * 144 + (jg * 32 + nb2 * 16 + (lane >> 4) * 8) * 2;
            ldsm_x4t(b0, b1, b2, b3, ka);
            mma16816(c[0], qa, b0, b1);
            mma16816(c[1], qa, b2, b3);
#pragma unroll
            for (int h = 0; h < 2; h++) {
                float e0 = ex2(fminf(fmaxf(c[h][0], -CLIP2), CLIP2));
                float e1 = ex2(fminf(fmaxf(c[h][1], -CLIP2), CLIP2));
                float e2 = ex2(fminf(fmaxf(c[h][2], -CLIP2), CLIP2));
                float e3 = ex2(fminf(fmaxf(c[h][3], -CLIP2), CLIP2));
                rs0 += e0 + e1;
                rs1 += e2 + e3;
                __nv_bfloat162 lo = __floats2bfloat162_rn(e0, e1);
                __nv_bfloat162 hi = __floats2bfloat162_rn(e2, e3);
                sts32(pst + nb2 * 32 + h * 16, *(uint32_t*)&lo);
                sts32(pst + nb2 * 32 + h * 16 + 8 * 144, *(uint32_t*)&hi);
            }
        }
    }

    for (int it = 0; it < NTILES; it++) {
        if (it + 2 < NTILES) {
            int n0 = (it + 2) * BN;
            int sp = (it + 2) & 3;
            uint32_t dst = smU + AT_VS + sp * 33792 + vj * 528 + vc * 16;
            const char* src = vb + ((size_t)(n0 + vj)) * 512 + vc * 16;
#pragma unroll
            for (int u = 0; u < 4; u++) cp16(dst + u * 128, src + u * 128);
            if (t < 128) cp16(smU + AT_KS + sp * 2304 + kd * 144 + kc * 16,
                              kb + (size_t)kd * (Nn * 2) + n0 * 2 + kc * 16);
        }
        CP_COMMIT;
        CP_WAIT1;
        __syncthreads();

        if (it + 1 < NTILES) {
            uint32_t ksb = smU + AT_KS + ((it + 1) & 3) * 2304;
            uint32_t pst = ps_st0 + ((it + 1) & 1) * 18432;
#pragma unroll
            for (int nb2 = 0; nb2 < 2; nb2++) {
                float c[2][4];
#pragma unroll
                for (int h = 0; h < 2; h++)
#pragma unroll
                    for (int j = 0; j < 4; j++) c[h][j] = 0.f;
                uint32_t b0, b1, b2, b3;
                uint32_t ka = ksb + (lane & 15) * 144 + (jg * 32 + nb2 * 16 + (lane >> 4) * 8) * 2;
                ldsm_x4t(b0, b1, b2, b3, ka);
                mma16816(c[0], qa, b0, b1);
                mma16816(c[1], qa, b2, b3);
#pragma unroll
                for (int h = 0; h < 2; h++) {
                    float e0 = ex2(fminf(fmaxf(c[h][0], -CLIP2), CLIP2));
                    float e1 = ex2(fminf(fmaxf(c[h][1], -CLIP2), CLIP2));
                    float e2 = ex2(fminf(fmaxf(c[h][2], -CLIP2), CLIP2));
                    float e3 = ex2(fminf(fmaxf(c[h][3], -CLIP2), CLIP2));
                    rs0 += e0 + e1;
                    rs1 += e2 + e3;
                    __nv_bfloat162 lo = __floats2bfloat162_rn(e0, e1);
                    __nv_bfloat162 hi = __floats2bfloat162_rn(e2, e3);
                    sts32(pst + nb2 * 32 + h * 16, *(uint32_t*)&lo);
                    sts32(pst + nb2 * 32 + h * 16 + 8 * 144, *(uint32_t*)&hi);
                }
            }
        }

        {
            uint32_t vsb = smU + AT_VS + (it & 3) * 33792;
            uint32_t pld = ps_ld0 + (it & 1) * 18432;
#pragma unroll
            for (int kg = 0; kg < 4; kg++) {
                uint32_t pA[2][4];
#pragma unroll
                for (int mi = 0; mi < 2; mi++)
                    ldsm_x4(pA[mi][0], pA[mi][1], pA[mi][2], pA[mi][3],
                            pld + mi * (16 * 144) + kg * 32);
#pragma unroll
                for (int eb2 = 0; eb2 < 4; eb2++) {
                    uint32_t b0, b1, b2, b3;
                    uint32_t va = vsb + (kg * 16 + (lane & 15)) * 528 +
                                  (eg * 64 + eb2 * 16 + (lane >> 4) * 8) * 2;
                    ldsm_x4t(b0, b1, b2, b3, va);
                    mma16816(acc[0][eb2 * 2],     pA[0], b0, b1);
                    mma16816(acc[0][eb2 * 2 + 1], pA[0], b2, b3);
                    mma16816(acc[1][eb2 * 2],     pA[1], b0, b1);
                    mma16816(acc[1][eb2 * 2 + 1], pA[1], b2, b3);
                }
            }
        }
    }

    rs0 += __shfl_xor_sync(0xffffffffu, rs0, 1);
    rs0 += __shfl_xor_sync(0xffffffffu, rs0, 2);
    rs1 += __shfl_xor_sync(0xffffffffu, rs1, 1);
    rs1 += __shfl_xor_sync(0xffffffffu, rs1, 2);
    float* rs_s = (float*)(sm + AT_RS);
    if ((lane & 3) == 0) {
        rs_s[jg * 128 + mg * 16 + (lane >> 2)]     = rs0;
        rs_s[jg * 128 + mg * 16 + (lane >> 2) + 8] = rs1;
    }

    float* Tf = (float*)sm;
    __nv_bfloat16* ob = g_OAb + (size_t)b * Cc * Nn + m0;
    int r = lane >> 2, q = lane & 3;
#pragma unroll
    for (int h = 0; h < 2; h++) {
        __syncthreads();
        if ((eg >> 1) == h) {
            int ebase = (eg & 1) * 64;
#pragma unroll
            for (int mi = 0; mi < 2; mi++) {
                int ml = mg2 * 32 + mi * 16 + r;
                float inv0 = 1.f / (rs_s[ml]     + rs_s[128 + ml]);
                float inv1 = 1.f / (rs_s[ml + 8] + rs_s[128 + ml + 8]);
#pragma unroll
                for (int nb = 0; nb < 8; nb++) {
                    int e = ebase + nb * 8 + 2 * q;
                    float* a = acc[mi][nb];
                    Tf[(size_t)e * 132 + ml]           = a[0] * inv0;
                    Tf[(size_t)(e + 1) * 132 + ml]     = a[1] * inv0;
                    Tf[(size_t)e * 132 + ml + 8]       = a[2] * inv1;
                    Tf[(size_t)(e + 1) * 132 + ml + 8] = a[3] * inv1;
                }
            }
        }
        __syncthreads();
#pragma unroll
        for (int rr = 0; rr < 8; rr++) {
            int e = wid * 8 + rr;
            const float* srcr = Tf + (size_t)e * 132;
            __nv_bfloat16* dstr = ob + (size_t)(h * 128 + e) * Nn;
#pragma unroll
            for (int c = 0; c < 2; c++) {
                dstr[c * 64 + lane]      = __float2bfloat16(srcr[c * 64 + lane]);
                dstr[c * 64 + 32 + lane] = __float2bfloat16(srcr[c * 64 + 32 + lane]);
            }
        }
    }
}

// ================= output projection: m64 x n64, 4 CTAs/SM, 3-stage ring =================
// smem: W 3 x 9216 = 27648 | X 3 x 9216 = 27648   total 55296 (x4 = 221 KB)
#define OP_WS 0
#define OP_XS 27648
#define OP_BYTES 55296

__global__ __launch_bounds__(256, 4) void outproj_kernel(
    const float* __restrict__ x,
    const float* __restrict__ bo,
    const float* __restrict__ gamma, float* __restrict__ out)
{
    extern __shared__ __align__(16) char sm[];
    uint32_t smU = smem_u32(sm);
    int t = threadIdx.x, wid = t >> 5, lane = t & 31;
    int mg = wid >> 1, ng = wid & 1;
    int n0 = blockIdx.x * 64, ytile = blockIdx.y, b = blockIdx.z;

    int wm = t >> 2, wq = t & 3;
    const __nv_bfloat16* wsrc = g_Wb + WO_OFF + (ytile * 64 + wm) * Cc;
    const __nv_bfloat16* xb = g_OAb + (size_t)b * Cc * Nn + n0;
    int xk = t >> 2, xn = t & 3;

    // prologue: chunks 0,1 into stages 0,1
#pragma unroll
    for (int ch = 0; ch < 2; ch++) {
        int k0 = ch * 64;
#pragma unroll
        for (int u = 0; u < 2; u++)
            cp16(smU + OP_WS + ch * 9216 + wm * 144 + (wq + 4 * u) * 16,
                 wsrc + k0 + (wq + 4 * u) * 8);
#pragma unroll
        for (int u = 0; u < 2; u++)
            cp16(smU + OP_XS + ch * 9216 + xk * 144 + (xn + 4 * u) * 16,
                 xb + (size_t)(k0 + xk) * Nn + (xn + 4 * u) * 8);
        CP_COMMIT;
    }

    float acc[4][4];
#pragma unroll
    for (int j = 0; j < 4; j++)
#pragma unroll
        for (int q = 0; q < 4; q++) acc[j][q] = 0.f;

    int st = 0, sp = 2;
    for (int ch = 0; ch < 4; ch++) {
        CP_WAIT1;
        __syncthreads();
        if (ch + 2 < 4) {
            int k0 = (ch + 2) * 64;
#pragma unroll
            for (int u = 0; u < 2; u++)
                cp16(smU + OP_WS + sp * 9216 + wm * 144 + (wq + 4 * u) * 16,
                     wsrc + k0 + (wq + 4 * u) * 8);
#pragma unroll
            for (int u = 0; u < 2; u++)
                cp16(smU + OP_XS + sp * 9216 + xk * 144 + (xn + 4 * u) * 16,
                     xb + (size_t)(k0 + xk) * Nn + (xn + 4 * u) * 8);
        }
        CP_COMMIT;
        {
            uint32_t wbU = smU + OP_WS + st * 9216;
            uint32_t xsU = smU + OP_XS + st * 9216;
#pragma unroll
            for (int kg = 0; kg < 4; kg++) {
                uint32_t A[4];
                ldsm_x4(A[0], A[1], A[2], A[3],
                        wbU + (mg * 16 + (lane & 15)) * 144 + kg * 32 + (lane >> 4) * 16);
#pragma unroll
                for (int nb2 = 0; nb2 < 2; nb2++) {
                    uint32_t b0, b1, b2, b3;
                    ldsm_x4t(b0, b1, b2, b3,
                             xsU + (kg * 16 + (lane & 15)) * 144 +
                             (ng * 32 + nb2 * 16 + (lane >> 4) * 8) * 2);
                    mma16816(acc[nb2 * 2],     A, b0, b1);
                    mma16816(acc[nb2 * 2 + 1], A, b2, b3);
                }
            }
        }
        st = (st == 2) ? 0 : st + 1;
        sp = (sp == 2) ? 0 : sp + 1;
    }
    __syncthreads();

    float* Tf = (float*)sm;
    {
        int m = mg * 16 + (lane >> 2);
#pragma unroll
        for (int nb = 0; nb < 4; nb++) {
            int n = ng * 32 + nb * 8 + (lane & 3) * 2;
            float* a = acc[nb];
            *(float2*)(Tf + (size_t)m * 68 + n)       = make_float2(a[0], a[1]);
            *(float2*)(Tf + (size_t)(m + 8) * 68 + n) = make_float2(a[2], a[3]);
        }
    }
    __syncthreads();
    float g = fminf(fmaxf(gamma[0], 0.f), 1.f);
    {
        int m = t >> 2, c = t & 3;
        int mglob = ytile * 64 + m;
        float bb = bo[mglob];
        size_t base = ((size_t)(b * Cc + mglob)) * Nn + n0 + c * 16;
#pragma unroll
        for (int u = 0; u < 4; u++) {
            float4 v = *(const float4*)(Tf + (size_t)m * 68 + c * 16 + u * 4);
            float4 xr = *(const float4*)(x + base + u * 4);
            float4 o;
            o.x = g * (v.x + bb) + xr.x;
            o.y = g * (v.y + bb) + xr.y;
            o.z = g * (v.z + bb) + xr.z;
            o.w = g * (v.w + bb) + xr.w;
            *(float4*)(out + base + u * 4) = o;
        }
    }
}

// ---------------- launcher ----------------
extern "C" void kernel_launch(void* const* d_in, const int* in_sizes, int n_in,
                              void* d_out, int out_size)
{
    const float* x     = (const float*)d_in[0];
    const float* Wq    = (const float*)d_in[1];
    const float* bq    = (const float*)d_in[2];
    const float* Wk    = (const float*)d_in[3];
    const float* bk    = (const float*)d_in[4];
    const float* Wv    = (const float*)d_in[5];
    const float* bv    = (const float*)d_in[6];
    const float* Wo    = (const float*)d_in[7];
    const float* bo    = (const float*)d_in[8];
    const float* gamma = (const float*)d_in[9];
    float* out = (float*)d_out;

    cudaFuncSetAttribute(proj_kernel,    cudaFuncAttributeMaxDynamicSharedMemorySize, PJ_BYTES);
    cudaFuncSetAttribute(outproj_kernel, cudaFuncAttributeMaxDynamicSharedMemorySize, OP_BYTES);
    cudaFuncSetAttribute(attn_kernel,    cudaFuncAttributeMaxDynamicSharedMemorySize, AT_BYTES);

    cvt_kernel    <<<2184, 256>>>(x, Wq, Wk, Wv, Wo);
    proj_kernel   <<<dim3(Nn / 128, 5, Bb), 256, PJ_BYTES>>>(bq, bk, bv);
    attn_kernel   <<<dim3(Nn / BM, Bb), 512, AT_BYTES>>>();
    outproj_kernel<<<dim3(Nn / 64, 4, Bb), 256, OP_BYTES>>>(x, bo, gamma, out);
}